// round 5
// baseline (speedup 1.0000x reference)
#include <cuda_runtime.h>
#include <cstdint>
#include <cstddef>

#define S_N 100000
#define E_N 30000
#define K_N 1000
#define DD 64
#define FF 128
#define B_N 16384
#define NNZ_S 1600000
#define NNZ_E 480000
#define NNZ_K 32000
#define NNZ_TOT (NNZ_S + NNZ_E + NNZ_K)
#define MOM 0.9f
#define LEAK_F 0.1f

// scan segmentation (1024 elements per block, 256 threads x 4)
#define NB_S 98
#define NB_E 30
#define NB_K 1
#define NB_TOT (NB_S + NB_E + NB_K)

static constexpr size_t al256(size_t x) { return (x + 255) & ~(size_t)255; }

// ---------------- static scratch arena ----------------
static constexpr size_t O_RP_S = 0;
static constexpr size_t O_RP_E = O_RP_S + (size_t)(S_N + 1) * 4;
static constexpr size_t O_RP_K = O_RP_E + (size_t)(E_N + 1) * 4;
static constexpr size_t RP_END = O_RP_K + (size_t)(K_N + 1) * 4;
static constexpr size_t O_LK   = al256(RP_END);                 // lookback状态 NB_TOT x u64
static constexpr size_t LK_END = O_LK + (size_t)NB_TOT * 8;
static constexpr int    ZERO_INTS = (int)(LK_END / 4);          // zero rowptrs + lk in one pass

static constexpr size_t O_CUR_S = al256(LK_END);
static constexpr size_t O_CUR_E = al256(O_CUR_S + (size_t)S_N * 4);
static constexpr size_t O_CUR_K = al256(O_CUR_E + (size_t)E_N * 4);
static constexpr size_t O_PAIRS_S = al256(O_CUR_K + (size_t)K_N * 4);
static constexpr size_t O_PAIRS_E = al256(O_PAIRS_S + (size_t)NNZ_S * 8);
static constexpr size_t O_PAIRS_K = al256(O_PAIRS_E + (size_t)NNZ_E * 8);
static constexpr size_t O_X1_S = al256(O_PAIRS_K + (size_t)NNZ_K * 8);
static constexpr size_t O_X2_S = al256(O_X1_S + (size_t)S_N * DD * 4);
static constexpr size_t O_X1_E = al256(O_X2_S + (size_t)S_N * DD * 4);
static constexpr size_t O_X2_E = al256(O_X1_E + (size_t)E_N * DD * 4);
static constexpr size_t O_X1_K = al256(O_X2_E + (size_t)E_N * DD * 4);
static constexpr size_t O_X2_K = al256(O_X1_K + (size_t)K_N * DD * 4);
static constexpr size_t O_A1   = al256(O_X2_K + (size_t)K_N * DD * 4);
static constexpr size_t O_A2   = al256(O_A1 + (size_t)B_N * FF * 4);
static constexpr size_t O_BT32 = al256(O_A2 + (size_t)B_N * FF * 4);   // 1024 x 128 tf32
static constexpr size_t ARENA_BYTES = al256(O_BT32 + (size_t)1024 * FF * 4);

__device__ __align__(256) unsigned char g_arena[ARENA_BYTES];

// ---------------- zero (rowptrs + lookback states + Bt32 pad) ----------------
#define BT_PAD_WORDS (24 * 128)
__global__ void zero_kernel(int* p, uint32_t* bt_pad) {
    int i = blockIdx.x * blockDim.x + threadIdx.x;
    if (i < ZERO_INTS) p[i] = 0;
    else if (i < ZERO_INTS + BT_PAD_WORDS) bt_pad[i - ZERO_INTS] = 0u;
}

// ---------------- histogram ----------------
__global__ void hist_all_kernel(const int* __restrict__ s_rows, const int* __restrict__ e_rows,
                                const int* __restrict__ k_rows, int* __restrict__ rp_s,
                                int* __restrict__ rp_e, int* __restrict__ rp_k) {
    int i = blockIdx.x * blockDim.x + threadIdx.x;
    if (i < NNZ_S) {
        atomicAdd(&rp_s[__ldg(s_rows + i) + 1], 1);
    } else if (i < NNZ_S + NNZ_E) {
        atomicAdd(&rp_e[__ldg(e_rows + (i - NNZ_S)) + 1], 1);
    } else if (i < NNZ_TOT) {
        atomicAdd(&rp_k[__ldg(k_rows + (i - NNZ_S - NNZ_E)) + 1], 1);
    }
}

// ---------------- single-pass decoupled-lookback scan (129 blocks, all resident) ----------------
__global__ void __launch_bounds__(256) scan_lookback_kernel(
    int* __restrict__ rp_s, int* __restrict__ rp_e, int* __restrict__ rp_k,
    int* __restrict__ cur_s, int* __restrict__ cur_e, int* __restrict__ cur_k,
    unsigned long long* __restrict__ lk) {
    __shared__ int wsum[8];
    __shared__ int s_excl;
    const unsigned FULL = 0xFFFFFFFFu;
    int b = blockIdx.x, t = threadIdx.x, lane = t & 31, wid = t >> 5;
    int *x, *c, n, lb;
    if (b < NB_S)             { x = rp_s; c = cur_s; n = S_N + 1; lb = b; }
    else if (b < NB_S + NB_E) { x = rp_e; c = cur_e; n = E_N + 1; lb = b - NB_S; }
    else                      { x = rp_k; c = cur_k; n = K_N + 1; lb = b - NB_S - NB_E; }
    int base = lb * 1024 + t * 4;
    int v0 = (base     < n) ? x[base]     : 0;
    int v1 = (base + 1 < n) ? x[base + 1] : 0;
    int v2 = (base + 2 < n) ? x[base + 2] : 0;
    int v3 = (base + 3 < n) ? x[base + 3] : 0;
    v1 += v0; v2 += v1; v3 += v2;         // thread-inclusive
    int tin = v3;
    int incl = tin;
    #pragma unroll
    for (int off = 1; off < 32; off <<= 1) {
        int o = __shfl_up_sync(FULL, incl, off);
        if (lane >= off) incl += o;
    }
    if (lane == 31) wsum[wid] = incl;
    __syncthreads();
    if (wid == 0) {
        int ws = (lane < 8) ? wsum[lane] : 0;
        #pragma unroll
        for (int off = 1; off < 8; off <<= 1) {
            int o = __shfl_up_sync(FULL, ws, off);
            if (lane >= off) ws += o;
        }
        if (lane < 8) wsum[lane] = ws;    // inclusive warp prefixes
    }
    __syncthreads();
    int agg = wsum[7];
    int warp_excl = wid ? wsum[wid - 1] : 0;
    int thread_excl = warp_excl + (incl - tin);

    if (wid == 0) {
        volatile unsigned long long* vlk = (volatile unsigned long long*)lk;
        if (lb == 0) {
            if (lane == 0) { vlk[b] = (2ULL << 32) | (unsigned)agg; s_excl = 0; }
        } else {
            if (lane == 0) vlk[b] = (1ULL << 32) | (unsigned)agg;
            int gbase = b - lb;
            int running = 0;
            int j = lb - 1;
            while (true) {
                int idx = j - lane;
                bool valid = idx >= 0;
                unsigned long long w = 0; int st = 0;
                while (true) {
                    if (valid) { w = vlk[gbase + idx]; st = (int)(w >> 32); }
                    if (__all_sync(FULL, !valid || st != 0)) break;
                }
                unsigned pm = __ballot_sync(FULL, valid && st == 2);
                int lane_p = pm ? (__ffs(pm) - 1) : 32;
                int val = (valid && lane <= lane_p) ? (int)(unsigned)w : 0;
                #pragma unroll
                for (int off = 16; off; off >>= 1) val += __shfl_xor_sync(FULL, val, off);
                running += val;
                if (lane_p < 32) break;
                j -= 32;
            }
            if (lane == 0) {
                vlk[b] = (2ULL << 32) | (unsigned)(running + agg);
                s_excl = running;
            }
        }
    }
    __syncthreads();
    int off0 = s_excl + thread_excl;
    if (base < n)     { int val = v0 + off0; x[base]     = val; if (base     < n - 1) c[base]     = val; }
    if (base + 1 < n) { int val = v1 + off0; x[base + 1] = val; if (base + 1 < n - 1) c[base + 1] = val; }
    if (base + 2 < n) { int val = v2 + off0; x[base + 2] = val; if (base + 2 < n - 1) c[base + 2] = val; }
    if (base + 3 < n) { int val = v3 + off0; x[base + 3] = val; if (base + 3 < n - 1) c[base + 3] = val; }
}

// ---------------- scatter ----------------
__global__ void scatter_all_kernel(
    const int* __restrict__ s_rows, const int* __restrict__ s_cols, const float* __restrict__ s_vals,
    const int* __restrict__ e_rows, const int* __restrict__ e_cols, const float* __restrict__ e_vals,
    const int* __restrict__ k_rows, const int* __restrict__ k_cols, const float* __restrict__ k_vals,
    int* __restrict__ cur_s, int* __restrict__ cur_e, int* __restrict__ cur_k,
    int2* __restrict__ pairs_s, int2* __restrict__ pairs_e, int2* __restrict__ pairs_k) {
    int i = blockIdx.x * blockDim.x + threadIdx.x;
    if (i < NNZ_S) {
        int p = atomicAdd(&cur_s[__ldg(s_rows + i)], 1);
        pairs_s[p] = make_int2(__ldg(s_cols + i), __float_as_int(__ldg(s_vals + i)));
    } else if (i < NNZ_S + NNZ_E) {
        int j = i - NNZ_S;
        int p = atomicAdd(&cur_e[__ldg(e_rows + j)], 1);
        pairs_e[p] = make_int2(__ldg(e_cols + j), __float_as_int(__ldg(e_vals + j)));
    } else if (i < NNZ_TOT) {
        int j = i - NNZ_S - NNZ_E;
        int p = atomicAdd(&cur_k[__ldg(k_rows + j)], 1);
        pairs_k[p] = make_int2(__ldg(k_cols + j), __float_as_int(__ldg(k_vals + j)));
    }
}

// ---------------- SpMM core ----------------
__device__ __forceinline__ float4 spmm_row(const int* __restrict__ rowptr,
                                           const int2* __restrict__ pairs,
                                           const float4* __restrict__ xin, int row, int d4) {
    int beg = __ldg(rowptr + row);
    int end = __ldg(rowptr + row + 1);
    float4 s = make_float4(0.f, 0.f, 0.f, 0.f);
    int j = beg;
    for (; j + 3 < end; j += 4) {
        int2 p0 = __ldg(pairs + j);
        int2 p1 = __ldg(pairs + j + 1);
        int2 p2 = __ldg(pairs + j + 2);
        int2 p3 = __ldg(pairs + j + 3);
        float4 v0 = __ldg(xin + ((size_t)p0.x << 4) + d4);
        float4 v1 = __ldg(xin + ((size_t)p1.x << 4) + d4);
        float4 v2 = __ldg(xin + ((size_t)p2.x << 4) + d4);
        float4 v3 = __ldg(xin + ((size_t)p3.x << 4) + d4);
        float w0 = __int_as_float(p0.y), w1 = __int_as_float(p1.y);
        float w2 = __int_as_float(p2.y), w3 = __int_as_float(p3.y);
        s.x = fmaf(w0, v0.x, s.x); s.y = fmaf(w0, v0.y, s.y); s.z = fmaf(w0, v0.z, s.z); s.w = fmaf(w0, v0.w, s.w);
        s.x = fmaf(w1, v1.x, s.x); s.y = fmaf(w1, v1.y, s.y); s.z = fmaf(w1, v1.z, s.z); s.w = fmaf(w1, v1.w, s.w);
        s.x = fmaf(w2, v2.x, s.x); s.y = fmaf(w2, v2.y, s.y); s.z = fmaf(w2, v2.z, s.z); s.w = fmaf(w2, v2.w, s.w);
        s.x = fmaf(w3, v3.x, s.x); s.y = fmaf(w3, v3.y, s.y); s.z = fmaf(w3, v3.z, s.z); s.w = fmaf(w3, v3.w, s.w);
    }
    for (; j < end; j++) {
        int2 p = __ldg(pairs + j);
        float w = __int_as_float(p.y);
        float4 v = __ldg(xin + ((size_t)p.x << 4) + d4);
        s.x = fmaf(w, v.x, s.x); s.y = fmaf(w, v.y, s.y); s.z = fmaf(w, v.z, s.z); s.w = fmaf(w, v.w, s.w);
    }
    return s;
}

#define GB_S 6250
#define GB_E 1875
#define GB_K 63

struct SpmmArgs {
    const int* rp[3];
    const int2* pr[3];
    const float4* xin[3];
    float4* xout[3];
    int nrows[3];
};

__global__ void __launch_bounds__(256) spmm_all_kernel(SpmmArgs a) {
    int b = blockIdx.x;
    int seg, lb;
    if (b < GB_S)             { seg = 0; lb = b; }
    else if (b < GB_S + GB_E) { seg = 1; lb = b - GB_S; }
    else                      { seg = 2; lb = b - GB_S - GB_E; }
    int row = lb * 16 + (threadIdx.x >> 4);
    int d4 = threadIdx.x & 15;
    if (row >= a.nrows[seg]) return;
    const float4* xin = a.xin[seg];
    float4 s = spmm_row(a.rp[seg], a.pr[seg], xin, row, d4);
    size_t o = ((size_t)row << 4) + d4;
    float4 m = xin[o];
    s.x += MOM * m.x; s.y += MOM * m.y; s.z += MOM * m.z; s.w += MOM * m.w;
    a.xout[seg][o] = s;
}

// ---------------- merged dense stage (with fused layer-3 SpMM) ----------------
__device__ __forceinline__ uint32_t f2tf32(float f) {
    uint32_t u;
    asm("cvt.rna.tf32.f32 %0, %1;" : "=r"(u) : "f"(f));
    return u;
}

#define G_STU 2048
#define G_EXE 2048
#define G_KNO 125
#define G_IMP 1024
#define G_DENSE (G_STU + G_EXE + G_KNO + G_IMP)

struct DenseArgs {
    const float *xs0, *xs1, *xs2;
    const float *xe0, *xe1, *xe2;
    const float *xk0, *xk1, *xk2;
    const int *rp_s; const int2 *pr_s;
    const int *rp_e; const int2 *pr_e;
    const int *rp_k; const int2 *pr_k;
    const int *sid, *eid;
    const float *Ws, *bs, *We, *be, *Wk, *bk, *Wd, *bd;
    const float *imp;
    float *A1, *A2, *Okt, *Odisc, *Oimp;
    uint32_t *Bt32;
};

// one block = 8 rows: x3 = spmm(x2)+MOM*x2 computed inline; mean/4 @ W + bias, leaky
__device__ void gemm64_body(const float* x0, const float* x1, const float* x2,
                            const int* rp, const int2* pr,
                            const int* ids, const float* W, const float* bias,
                            float* out, uint32_t* out_tf32, int rows, int r0, bool a_tf32,
                            bool do_disc, const float* Wd, const float* bd, float* odisc) {
    __shared__ float Ws[64 * 128];
    __shared__ float Xs[8][64];
    int tid = threadIdx.x;
    const float4* W4 = (const float4*)W;
    float4* Ws4 = (float4*)Ws;
    #pragma unroll
    for (int i = 0; i < 8; i++) Ws4[tid + i * 256] = W4[tid + i * 256];
    if (tid < 128) {
        int rr = tid >> 4;
        int c4 = tid & 15;
        int r = r0 + rr;
        float4 v = make_float4(0.f, 0.f, 0.f, 0.f);
        if (r < rows) {
            int rid = ids ? __ldg(ids + r) : r;
            size_t o = ((size_t)rid << 4) + c4;
            float4 a0 = __ldg((const float4*)x0 + o);
            float4 a1 = __ldg((const float4*)x1 + o);
            float4 a2 = __ldg((const float4*)x2 + o);
            float4 s3 = spmm_row(rp, pr, (const float4*)x2, rid, c4);   // layer-3 fused
            const float M1 = 1.f + MOM;
            v.x = 0.25f * (a0.x + a1.x + M1 * a2.x + s3.x);
            v.y = 0.25f * (a0.y + a1.y + M1 * a2.y + s3.y);
            v.z = 0.25f * (a0.z + a1.z + M1 * a2.z + s3.z);
            v.w = 0.25f * (a0.w + a1.w + M1 * a2.w + s3.w);
        }
        ((float4*)&Xs[rr][0])[c4] = v;
    }
    __syncthreads();
    int col = tid & 127;
    int rbase = tid >> 7;
    float bv = __ldg(bias + col);
    #pragma unroll
    for (int rr = 0; rr < 4; rr++) {
        int lrow = rr * 2 + rbase;
        int r = r0 + lrow;
        if (r >= rows) continue;
        float a = bv;
        #pragma unroll
        for (int i = 0; i < 64; i++) a = fmaf(Xs[lrow][i], Ws[i * 128 + col], a);
        float rv = (a > 0.f) ? a : LEAK_F * a;
        if (a_tf32) ((uint32_t*)out)[(size_t)r * 128 + col] = f2tf32(rv);
        else        out[(size_t)r * 128 + col] = rv;
        if (out_tf32) out_tf32[(size_t)r * 128 + col] = f2tf32(rv);
    }
    if (do_disc && tid < 32) {
        int lrow = tid >> 2;
        int part = tid & 3;
        float s = 0.f;
        #pragma unroll
        for (int i = 0; i < 16; i++) s += Xs[lrow][part * 16 + i] * __ldg(Wd + part * 16 + i);
        s += __shfl_xor_sync(0xFFFFFFFFu, s, 1);
        s += __shfl_xor_sync(0xFFFFFFFFu, s, 2);
        if (part == 0) odisc[r0 + lrow] = 1.f / (1.f + __expf(-(s + __ldg(bd))));
    }
}

__global__ void __launch_bounds__(256) dense_all_kernel(DenseArgs a) {
    int b = blockIdx.x;
    if (b < G_STU) {
        gemm64_body(a.xs0, a.xs1, a.xs2, a.rp_s, a.pr_s, a.sid, a.Ws, a.bs, a.A1, nullptr,
                    B_N, b * 8, true, false, nullptr, nullptr, nullptr);
    } else if (b < G_STU + G_EXE) {
        gemm64_body(a.xe0, a.xe1, a.xe2, a.rp_e, a.pr_e, a.eid, a.We, a.be, a.A2, nullptr,
                    B_N, (b - G_STU) * 8, true, true, a.Wd, a.bd, a.Odisc);
    } else if (b < G_STU + G_EXE + G_KNO) {
        gemm64_body(a.xk0, a.xk1, a.xk2, a.rp_k, a.pr_k, nullptr, a.Wk, a.bk, a.Okt, a.Bt32,
                    K_N, (b - G_STU - G_EXE) * 8, false, false, nullptr, nullptr, nullptr);
    } else {
        int t = (b - G_STU - G_EXE - G_KNO) * 256 + threadIdx.x;
        int bi = t >> 4, q = t & 15;
        ((float4*)a.Oimp)[((size_t)bi << 4) + q] =
            __ldg((const float4*)a.imp + ((size_t)__ldg(a.eid + bi) << 4) + q);
    }
}

// ---------------- TF32 tensor-core big GEMM (128x128 tile, cp.async 2-stage) ----------------
#define MMA_TF32(d, a, b)                                                     \
    asm volatile(                                                             \
        "mma.sync.aligned.m16n8k8.row.col.f32.tf32.tf32.f32 "                 \
        "{%0,%1,%2,%3}, {%4,%5,%6,%7}, {%8,%9}, {%0,%1,%2,%3};\n"             \
        : "+f"(d[0]), "+f"(d[1]), "+f"(d[2]), "+f"(d[3])                      \
        : "r"(a[0]), "r"(a[1]), "r"(a[2]), "r"(a[3]), "r"(b[0]), "r"(b[1]))

#define SMPAD 36
#define STAGE_W (3 * 128 * SMPAD)
#define GEMM_SMEM_BYTES (2 * STAGE_W * 4)

__device__ __forceinline__ void cp16(uint32_t dst, const void* src) {
    asm volatile("cp.async.cg.shared.global [%0], [%1], 16;" :: "r"(dst), "l"(src));
}

__device__ __forceinline__ void load_stage(uint32_t sbase, const uint32_t* A1, const uint32_t* A2,
                                           const uint32_t* B32, int m0, int n0, int kc, int tid) {
    #pragma unroll
    for (int i = 0; i < 4; i++) {
        int idx = tid + i * 256;
        int row = idx >> 3, q = idx & 7;
        uint32_t off = (uint32_t)(row * SMPAD + q * 4) * 4;
        cp16(sbase + off,                       A1 + (size_t)(m0 + row) * 128 + kc + q * 4);
        cp16(sbase + 128 * SMPAD * 4 + off,     A2 + (size_t)(m0 + row) * 128 + kc + q * 4);
        cp16(sbase + 2 * 128 * SMPAD * 4 + off, B32 + (size_t)(n0 + row) * 128 + kc + q * 4);
    }
    asm volatile("cp.async.commit_group;");
}

__global__ void __launch_bounds__(256, 1) big_gemm_tf32_dual(
    const uint32_t* __restrict__ A1, const uint32_t* __restrict__ A2,
    const uint32_t* __restrict__ B32, float* __restrict__ O1, float* __restrict__ O2) {
    extern __shared__ uint32_t sm[];
    uint32_t sbase = (uint32_t)__cvta_generic_to_shared(sm);

    int tid = threadIdx.x;
    int warp = tid >> 5;
    int lane = tid & 31;
    int g = lane >> 2;
    int tg = lane & 3;
    int wm = warp >> 1;
    int wn = warp & 1;
    int m0 = blockIdx.x * 128;
    int n0 = blockIdx.y * 128;

    float acc1[2][8][4] = {};
    float acc2[2][8][4] = {};

    load_stage(sbase, A1, A2, B32, m0, n0, 0, tid);

    #pragma unroll
    for (int c = 0; c < 4; c++) {
        if (c < 3) {
            load_stage(sbase + ((c + 1) & 1) * STAGE_W * 4, A1, A2, B32, m0, n0, (c + 1) * 32, tid);
            asm volatile("cp.async.wait_group 1;");
        } else {
            asm volatile("cp.async.wait_group 0;");
        }
        __syncthreads();
        const uint32_t* As1 = sm + (c & 1) * STAGE_W;
        const uint32_t* As2 = As1 + 128 * SMPAD;
        const uint32_t* Bs  = As2 + 128 * SMPAD;

        #pragma unroll
        for (int ks = 0; ks < 4; ks++) {
            int k0 = ks * 8;
            uint32_t b[8][2];
            #pragma unroll
            for (int nt = 0; nt < 8; nt++) {
                const uint32_t* bp = &Bs[(wn * 64 + nt * 8 + g) * SMPAD + k0 + tg];
                b[nt][0] = bp[0];
                b[nt][1] = bp[4];
            }
            #pragma unroll
            for (int mt = 0; mt < 2; mt++) {
                uint32_t a[4];
                const uint32_t* ap = &As1[(wm * 32 + mt * 16 + g) * SMPAD + k0 + tg];
                a[0] = ap[0]; a[1] = ap[8 * SMPAD]; a[2] = ap[4]; a[3] = ap[8 * SMPAD + 4];
                #pragma unroll
                for (int nt = 0; nt < 8; nt++) MMA_TF32(acc1[mt][nt], a, b[nt]);
                ap = &As2[(wm * 32 + mt * 16 + g) * SMPAD + k0 + tg];
                a[0] = ap[0]; a[1] = ap[8 * SMPAD]; a[2] = ap[4]; a[3] = ap[8 * SMPAD + 4];
                #pragma unroll
                for (int nt = 0; nt < 8; nt++) MMA_TF32(acc2[mt][nt], a, b[nt]);
            }
        }
        __syncthreads();
    }

    #pragma unroll
    for (int mt = 0; mt < 2; mt++) {
        #pragma unroll
        for (int nt = 0; nt < 8; nt++) {
            int col = n0 + wn * 64 + nt * 8 + tg * 2;
            if (col >= K_N) continue;
            size_t r0 = (size_t)(m0 + wm * 32 + mt * 16 + g);
            size_t r1 = r0 + 8;
            *(float2*)(O1 + r0 * K_N + col) = make_float2(acc1[mt][nt][0], acc1[mt][nt][1]);
            *(float2*)(O1 + r1 * K_N + col) = make_float2(acc1[mt][nt][2], acc1[mt][nt][3]);
            *(float2*)(O2 + r0 * K_N + col) = make_float2(acc2[mt][nt][0], acc2[mt][nt][1]);
            *(float2*)(O2 + r1 * K_N + col) = make_float2(acc2[mt][nt][2], acc2[mt][nt][3]);
        }
    }
}

// ---------------- host orchestration ----------------
extern "C" void kernel_launch(void* const* d_in, const int* in_sizes, int n_in,
                              void* d_out, int out_size) {
    (void)in_sizes; (void)n_in; (void)out_size;
    const int*   student_id  = (const int*)d_in[0];
    const int*   exercise_id = (const int*)d_in[1];
    const float* stu_emb     = (const float*)d_in[3];
    const float* exer_emb    = (const float*)d_in[4];
    const float* know_emb    = (const float*)d_in[5];
    const float* impact_emb  = (const float*)d_in[6];
    const int*   s_rows = (const int*)d_in[7];
    const int*   s_cols = (const int*)d_in[8];
    const float* s_vals = (const float*)d_in[9];
    const int*   e_rows = (const int*)d_in[10];
    const int*   e_cols = (const int*)d_in[11];
    const float* e_vals = (const float*)d_in[12];
    const int*   k_rows = (const int*)d_in[13];
    const int*   k_cols = (const int*)d_in[14];
    const float* k_vals = (const float*)d_in[15];
    const float* W_stu  = (const float*)d_in[16];
    const float* b_stu  = (const float*)d_in[17];
    const float* W_exer = (const float*)d_in[18];
    const float* b_exer = (const float*)d_in[19];
    const float* W_know = (const float*)d_in[20];
    const float* b_know = (const float*)d_in[21];
    const float* W_disc = (const float*)d_in[22];
    const float* b_disc = (const float*)d_in[23];

    unsigned char* A = nullptr;
    cudaGetSymbolAddress((void**)&A, g_arena);

    int*  rp_s  = (int*)(A + O_RP_S);
    int*  rp_e  = (int*)(A + O_RP_E);
    int*  rp_k  = (int*)(A + O_RP_K);
    unsigned long long* lk = (unsigned long long*)(A + O_LK);
    int*  cur_s = (int*)(A + O_CUR_S);
    int*  cur_e = (int*)(A + O_CUR_E);
    int*  cur_k = (int*)(A + O_CUR_K);
    int2* pairs_s = (int2*)(A + O_PAIRS_S);
    int2* pairs_e = (int2*)(A + O_PAIRS_E);
    int2* pairs_k = (int2*)(A + O_PAIRS_K);
    float* x1_s = (float*)(A + O_X1_S);
    float* x2_s = (float*)(A + O_X2_S);
    float* x1_e = (float*)(A + O_X1_E);
    float* x2_e = (float*)(A + O_X2_E);
    float* x1_k = (float*)(A + O_X1_K);
    float* x2_k = (float*)(A + O_X2_K);
    float* A1   = (float*)(A + O_A1);
    float* A2   = (float*)(A + O_A2);
    uint32_t* Bt32 = (uint32_t*)(A + O_BT32);

    // 1) CSR build: zero, hist, lookback-scan, scatter (4 launches)
    zero_kernel<<<(ZERO_INTS + BT_PAD_WORDS + 1023) / 1024, 1024>>>(
        (int*)A, Bt32 + (size_t)K_N * 128);
    hist_all_kernel<<<(NNZ_TOT + 255) / 256, 256>>>(s_rows, e_rows, k_rows, rp_s, rp_e, rp_k);
    scan_lookback_kernel<<<NB_TOT, 256>>>(rp_s, rp_e, rp_k, cur_s, cur_e, cur_k, lk);
    scatter_all_kernel<<<(NNZ_TOT + 255) / 256, 256>>>(
        s_rows, s_cols, s_vals, e_rows, e_cols, e_vals, k_rows, k_cols, k_vals,
        cur_s, cur_e, cur_k, pairs_s, pairs_e, pairs_k);

    // 2) layers 1-2 full (layer 3 fused into dense)
    const float* in_s[3] = {stu_emb, x1_s, x2_s};
    const float* in_e[3] = {exer_emb, x1_e, x2_e};
    const float* in_k[3] = {know_emb, x1_k, x2_k};
    for (int l = 0; l < 2; l++) {
        SpmmArgs sa;
        sa.rp[0] = rp_s;  sa.rp[1] = rp_e;  sa.rp[2] = rp_k;
        sa.pr[0] = pairs_s; sa.pr[1] = pairs_e; sa.pr[2] = pairs_k;
        sa.xin[0] = (const float4*)in_s[l]; sa.xin[1] = (const float4*)in_e[l]; sa.xin[2] = (const float4*)in_k[l];
        sa.xout[0] = (float4*)in_s[l + 1];  sa.xout[1] = (float4*)in_e[l + 1];  sa.xout[2] = (float4*)in_k[l + 1];
        sa.nrows[0] = S_N; sa.nrows[1] = E_N; sa.nrows[2] = K_N;
        spmm_all_kernel<<<GB_S + GB_E + GB_K, 256>>>(sa);
    }

    // 3) output layout
    float* out   = (float*)d_out;
    float* O1    = out;
    float* O2    = O1 + (size_t)B_N * K_N;
    float* Odisc = O2 + (size_t)B_N * K_N;
    float* Okt   = Odisc + B_N;
    float* Oimp  = Okt + (size_t)K_N * FF;

    // 4) merged dense stage (layer-3 SpMM fused)
    DenseArgs da;
    da.xs0 = stu_emb; da.xs1 = x1_s; da.xs2 = x2_s;
    da.xe0 = exer_emb; da.xe1 = x1_e; da.xe2 = x2_e;
    da.xk0 = know_emb; da.xk1 = x1_k; da.xk2 = x2_k;
    da.rp_s = rp_s; da.pr_s = pairs_s;
    da.rp_e = rp_e; da.pr_e = pairs_e;
    da.rp_k = rp_k; da.pr_k = pairs_k;
    da.sid = student_id; da.eid = exercise_id;
    da.Ws = W_stu; da.bs = b_stu; da.We = W_exer; da.be = b_exer;
    da.Wk = W_know; da.bk = b_know; da.Wd = W_disc; da.bd = b_disc;
    da.imp = impact_emb;
    da.A1 = A1; da.A2 = A2; da.Okt = Okt; da.Odisc = Odisc; da.Oimp = Oimp;
    da.Bt32 = Bt32;
    dense_all_kernel<<<G_DENSE, 256>>>(da);

    // 5) TF32 big GEMM pair
    static bool attr_set = false;
    if (!attr_set) {
        cudaFuncSetAttribute(big_gemm_tf32_dual,
                             cudaFuncAttributeMaxDynamicSharedMemorySize, GEMM_SMEM_BYTES);
        attr_set = true;
    }
    dim3 grid(B_N / 128, 1024 / 128);
    big_gemm_tf32_dual<<<grid, 256, GEMM_SMEM_BYTES>>>(
        (const uint32_t*)A1, (const uint32_t*)A2, Bt32, O1, O2);
}

// round 6
// speedup vs baseline: 1.0722x; 1.0722x over previous
#include <cuda_runtime.h>
#include <cstdint>
#include <cstddef>

#define S_N 100000
#define E_N 30000
#define K_N 1000
#define DD 64
#define FF 128
#define B_N 16384
#define NNZ_S 1600000
#define NNZ_E 480000
#define NNZ_K 32000
#define NNZ_TOT (NNZ_S + NNZ_E + NNZ_K)
#define MOM 0.9f
#define LEAK_F 0.1f

#define NB_S 98
#define NB_E 30
#define NB_K 1
#define NB_TOT (NB_S + NB_E + NB_K)

static constexpr size_t al256(size_t x) { return (x + 255) & ~(size_t)255; }

// ---------------- static scratch arena ----------------
static constexpr size_t O_RP_S = 0;
static constexpr size_t O_RP_E = O_RP_S + (size_t)(S_N + 1) * 4;
static constexpr size_t O_RP_K = O_RP_E + (size_t)(E_N + 1) * 4;
static constexpr size_t RP_END = O_RP_K + (size_t)(K_N + 1) * 4;
static constexpr size_t O_LK   = al256(RP_END);
static constexpr size_t LK_END = O_LK + (size_t)NB_TOT * 8;
static constexpr int    ZERO_INTS = (int)(LK_END / 4);

static constexpr size_t O_CUR_S = al256(LK_END);
static constexpr size_t O_CUR_E = al256(O_CUR_S + (size_t)S_N * 4);
static constexpr size_t O_CUR_K = al256(O_CUR_E + (size_t)E_N * 4);
static constexpr size_t O_PAIRS_S = al256(O_CUR_K + (size_t)K_N * 4);
static constexpr size_t O_PAIRS_E = al256(O_PAIRS_S + (size_t)NNZ_S * 8);
static constexpr size_t O_PAIRS_K = al256(O_PAIRS_E + (size_t)NNZ_E * 8);
static constexpr size_t O_X1_S = al256(O_PAIRS_K + (size_t)NNZ_K * 8);
static constexpr size_t O_X2_S = al256(O_X1_S + (size_t)S_N * DD * 4);
static constexpr size_t O_X1_E = al256(O_X2_S + (size_t)S_N * DD * 4);
static constexpr size_t O_X2_E = al256(O_X1_E + (size_t)E_N * DD * 4);
static constexpr size_t O_X1_K = al256(O_X2_E + (size_t)E_N * DD * 4);
static constexpr size_t O_X2_K = al256(O_X1_K + (size_t)K_N * DD * 4);
static constexpr size_t O_X3_K = al256(O_X2_K + (size_t)K_N * DD * 4);
static constexpr size_t O_XG_S = al256(O_X3_K + (size_t)K_N * DD * 4);
static constexpr size_t O_XG_E = al256(O_XG_S + (size_t)B_N * DD * 4);
static constexpr size_t O_A1   = al256(O_XG_E + (size_t)B_N * DD * 4);
static constexpr size_t O_A2   = al256(O_A1 + (size_t)B_N * FF * 4);
static constexpr size_t O_BT32 = al256(O_A2 + (size_t)B_N * FF * 4);
static constexpr size_t ARENA_BYTES = al256(O_BT32 + (size_t)1024 * FF * 4);

__device__ __align__(256) unsigned char g_arena[ARENA_BYTES];

// ---------------- zero (rowptrs + lookback states + Bt32 pad) ----------------
#define BT_PAD_WORDS (24 * 128)
__global__ void zero_kernel(int* p, uint32_t* bt_pad) {
    int i = blockIdx.x * blockDim.x + threadIdx.x;
    if (i < ZERO_INTS) p[i] = 0;
    else if (i < ZERO_INTS + BT_PAD_WORDS) bt_pad[i - ZERO_INTS] = 0u;
}

// ---------------- histogram (x4 vectorized) ----------------
#define Q4_S (NNZ_S / 4)
#define Q4_E (NNZ_E / 4)
#define Q4_K (NNZ_K / 4)
#define Q4_TOT (Q4_S + Q4_E + Q4_K)

__global__ void hist_all_kernel(const int4* __restrict__ s_rows, const int4* __restrict__ e_rows,
                                const int4* __restrict__ k_rows, int* __restrict__ rp_s,
                                int* __restrict__ rp_e, int* __restrict__ rp_k) {
    int i = blockIdx.x * blockDim.x + threadIdx.x;
    int4 r; int* rp;
    if (i < Q4_S)             { r = __ldg(s_rows + i); rp = rp_s; }
    else if (i < Q4_S + Q4_E) { r = __ldg(e_rows + (i - Q4_S)); rp = rp_e; }
    else if (i < Q4_TOT)      { r = __ldg(k_rows + (i - Q4_S - Q4_E)); rp = rp_k; }
    else return;
    atomicAdd(&rp[r.x + 1], 1);
    atomicAdd(&rp[r.y + 1], 1);
    atomicAdd(&rp[r.z + 1], 1);
    atomicAdd(&rp[r.w + 1], 1);
}

// ---------------- single-pass decoupled-lookback scan ----------------
__global__ void __launch_bounds__(256) scan_lookback_kernel(
    int* __restrict__ rp_s, int* __restrict__ rp_e, int* __restrict__ rp_k,
    int* __restrict__ cur_s, int* __restrict__ cur_e, int* __restrict__ cur_k,
    unsigned long long* __restrict__ lk) {
    __shared__ int wsum[8];
    __shared__ int s_excl;
    const unsigned FULL = 0xFFFFFFFFu;
    int b = blockIdx.x, t = threadIdx.x, lane = t & 31, wid = t >> 5;
    int *x, *c, n, lb;
    if (b < NB_S)             { x = rp_s; c = cur_s; n = S_N + 1; lb = b; }
    else if (b < NB_S + NB_E) { x = rp_e; c = cur_e; n = E_N + 1; lb = b - NB_S; }
    else                      { x = rp_k; c = cur_k; n = K_N + 1; lb = b - NB_S - NB_E; }
    int base = lb * 1024 + t * 4;
    int v0 = (base     < n) ? x[base]     : 0;
    int v1 = (base + 1 < n) ? x[base + 1] : 0;
    int v2 = (base + 2 < n) ? x[base + 2] : 0;
    int v3 = (base + 3 < n) ? x[base + 3] : 0;
    v1 += v0; v2 += v1; v3 += v2;
    int tin = v3;
    int incl = tin;
    #pragma unroll
    for (int off = 1; off < 32; off <<= 1) {
        int o = __shfl_up_sync(FULL, incl, off);
        if (lane >= off) incl += o;
    }
    if (lane == 31) wsum[wid] = incl;
    __syncthreads();
    if (wid == 0) {
        int ws = (lane < 8) ? wsum[lane] : 0;
        #pragma unroll
        for (int off = 1; off < 8; off <<= 1) {
            int o = __shfl_up_sync(FULL, ws, off);
            if (lane >= off) ws += o;
        }
        if (lane < 8) wsum[lane] = ws;
    }
    __syncthreads();
    int agg = wsum[7];
    int warp_excl = wid ? wsum[wid - 1] : 0;
    int thread_excl = warp_excl + (incl - tin);

    if (wid == 0) {
        volatile unsigned long long* vlk = (volatile unsigned long long*)lk;
        if (lb == 0) {
            if (lane == 0) { vlk[b] = (2ULL << 32) | (unsigned)agg; s_excl = 0; }
        } else {
            if (lane == 0) vlk[b] = (1ULL << 32) | (unsigned)agg;
            int gbase = b - lb;
            int running = 0;
            int j = lb - 1;
            while (true) {
                int idx = j - lane;
                bool valid = idx >= 0;
                unsigned long long w = 0; int st = 0;
                while (true) {
                    if (valid) { w = vlk[gbase + idx]; st = (int)(w >> 32); }
                    if (__all_sync(FULL, !valid || st != 0)) break;
                }
                unsigned pm = __ballot_sync(FULL, valid && st == 2);
                int lane_p = pm ? (__ffs(pm) - 1) : 32;
                int val = (valid && lane <= lane_p) ? (int)(unsigned)w : 0;
                #pragma unroll
                for (int off = 16; off; off >>= 1) val += __shfl_xor_sync(FULL, val, off);
                running += val;
                if (lane_p < 32) break;
                j -= 32;
            }
            if (lane == 0) {
                vlk[b] = (2ULL << 32) | (unsigned)(running + agg);
                s_excl = running;
            }
        }
    }
    __syncthreads();
    int off0 = s_excl + thread_excl;
    if (base < n)     { int val = v0 + off0; x[base]     = val; if (base     < n - 1) c[base]     = val; }
    if (base + 1 < n) { int val = v1 + off0; x[base + 1] = val; if (base + 1 < n - 1) c[base + 1] = val; }
    if (base + 2 < n) { int val = v2 + off0; x[base + 2] = val; if (base + 2 < n - 1) c[base + 2] = val; }
    if (base + 3 < n) { int val = v3 + off0; x[base + 3] = val; if (base + 3 < n - 1) c[base + 3] = val; }
}

// ---------------- scatter (x4 vectorized) ----------------
__global__ void scatter_all_kernel(
    const int4* __restrict__ s_rows, const int4* __restrict__ s_cols, const float4* __restrict__ s_vals,
    const int4* __restrict__ e_rows, const int4* __restrict__ e_cols, const float4* __restrict__ e_vals,
    const int4* __restrict__ k_rows, const int4* __restrict__ k_cols, const float4* __restrict__ k_vals,
    int* __restrict__ cur_s, int* __restrict__ cur_e, int* __restrict__ cur_k,
    int2* __restrict__ pairs_s, int2* __restrict__ pairs_e, int2* __restrict__ pairs_k) {
    int i = blockIdx.x * blockDim.x + threadIdx.x;
    int4 r, cidx; float4 v; int* cur; int2* pairs;
    if (i < Q4_S) {
        r = __ldg(s_rows + i); cidx = __ldg(s_cols + i); v = __ldg(s_vals + i);
        cur = cur_s; pairs = pairs_s;
    } else if (i < Q4_S + Q4_E) {
        int j = i - Q4_S;
        r = __ldg(e_rows + j); cidx = __ldg(e_cols + j); v = __ldg(e_vals + j);
        cur = cur_e; pairs = pairs_e;
    } else if (i < Q4_TOT) {
        int j = i - Q4_S - Q4_E;
        r = __ldg(k_rows + j); cidx = __ldg(k_cols + j); v = __ldg(k_vals + j);
        cur = cur_k; pairs = pairs_k;
    } else return;
    int p0 = atomicAdd(&cur[r.x], 1);
    int p1 = atomicAdd(&cur[r.y], 1);
    int p2 = atomicAdd(&cur[r.z], 1);
    int p3 = atomicAdd(&cur[r.w], 1);
    pairs[p0] = make_int2(cidx.x, __float_as_int(v.x));
    pairs[p1] = make_int2(cidx.y, __float_as_int(v.y));
    pairs[p2] = make_int2(cidx.z, __float_as_int(v.z));
    pairs[p3] = make_int2(cidx.w, __float_as_int(v.w));
}

// ---------------- SpMM core ----------------
__device__ __forceinline__ float4 spmm_row(const int* __restrict__ rowptr,
                                           const int2* __restrict__ pairs,
                                           const float4* __restrict__ xin, int row, int d4) {
    int beg = __ldg(rowptr + row);
    int end = __ldg(rowptr + row + 1);
    float4 s = make_float4(0.f, 0.f, 0.f, 0.f);
    int j = beg;
    for (; j + 3 < end; j += 4) {
        int2 p0 = __ldg(pairs + j);
        int2 p1 = __ldg(pairs + j + 1);
        int2 p2 = __ldg(pairs + j + 2);
        int2 p3 = __ldg(pairs + j + 3);
        float4 v0 = __ldg(xin + ((size_t)p0.x << 4) + d4);
        float4 v1 = __ldg(xin + ((size_t)p1.x << 4) + d4);
        float4 v2 = __ldg(xin + ((size_t)p2.x << 4) + d4);
        float4 v3 = __ldg(xin + ((size_t)p3.x << 4) + d4);
        float w0 = __int_as_float(p0.y), w1 = __int_as_float(p1.y);
        float w2 = __int_as_float(p2.y), w3 = __int_as_float(p3.y);
        s.x = fmaf(w0, v0.x, s.x); s.y = fmaf(w0, v0.y, s.y); s.z = fmaf(w0, v0.z, s.z); s.w = fmaf(w0, v0.w, s.w);
        s.x = fmaf(w1, v1.x, s.x); s.y = fmaf(w1, v1.y, s.y); s.z = fmaf(w1, v1.z, s.z); s.w = fmaf(w1, v1.w, s.w);
        s.x = fmaf(w2, v2.x, s.x); s.y = fmaf(w2, v2.y, s.y); s.z = fmaf(w2, v2.z, s.z); s.w = fmaf(w2, v2.w, s.w);
        s.x = fmaf(w3, v3.x, s.x); s.y = fmaf(w3, v3.y, s.y); s.z = fmaf(w3, v3.z, s.z); s.w = fmaf(w3, v3.w, s.w);
    }
    for (; j < end; j++) {
        int2 p = __ldg(pairs + j);
        float w = __int_as_float(p.y);
        float4 v = __ldg(xin + ((size_t)p.x << 4) + d4);
        s.x = fmaf(w, v.x, s.x); s.y = fmaf(w, v.y, s.y); s.z = fmaf(w, v.z, s.z); s.w = fmaf(w, v.w, s.w);
    }
    return s;
}

#define GB_S 6250
#define GB_E 1875
#define GB_K 63

struct SpmmArgs {
    const int* rp[3];
    const int2* pr[3];
    const float4* xin[3];
    float4* xout[3];
    int nrows[3];
};

__global__ void __launch_bounds__(256) spmm_all_kernel(SpmmArgs a) {
    int b = blockIdx.x;
    int seg, lb;
    if (b < GB_S)             { seg = 0; lb = b; }
    else if (b < GB_S + GB_E) { seg = 1; lb = b - GB_S; }
    else                      { seg = 2; lb = b - GB_S - GB_E; }
    int row = lb * 16 + (threadIdx.x >> 4);
    int d4 = threadIdx.x & 15;
    if (row >= a.nrows[seg]) return;
    const float4* xin = a.xin[seg];
    float4 s = spmm_row(a.rp[seg], a.pr[seg], xin, row, d4);
    size_t o = ((size_t)row << 4) + d4;
    float4 m = xin[o];
    s.x += MOM * m.x; s.y += MOM * m.y; s.z += MOM * m.z; s.w += MOM * m.w;
    a.xout[seg][o] = s;
}

// ---------------- layer 3: batch-restricted stu/exer + full know ----------------
#define GL_S 1024
#define GL_E 1024
#define GL_K 63

struct Spmm3Args {
    const int* rp_s; const int2* pr_s; const float4* x2_s; float4* xg_s; const int* sid;
    const int* rp_e; const int2* pr_e; const float4* x2_e; float4* xg_e; const int* eid;
    const int* rp_k; const int2* pr_k; const float4* x2_k; float4* x3_k;
};

__global__ void __launch_bounds__(256) spmm_l3_kernel(Spmm3Args a) {
    int b = blockIdx.x;
    int d4 = threadIdx.x & 15;
    int lr = (threadIdx.x >> 4);
    if (b < GL_S) {
        int r = b * 16 + lr;
        int row = __ldg(a.sid + r);
        float4 s = spmm_row(a.rp_s, a.pr_s, a.x2_s, row, d4);
        float4 m = a.x2_s[((size_t)row << 4) + d4];
        s.x += MOM * m.x; s.y += MOM * m.y; s.z += MOM * m.z; s.w += MOM * m.w;
        a.xg_s[((size_t)r << 4) + d4] = s;
    } else if (b < GL_S + GL_E) {
        int r = (b - GL_S) * 16 + lr;
        int row = __ldg(a.eid + r);
        float4 s = spmm_row(a.rp_e, a.pr_e, a.x2_e, row, d4);
        float4 m = a.x2_e[((size_t)row << 4) + d4];
        s.x += MOM * m.x; s.y += MOM * m.y; s.z += MOM * m.z; s.w += MOM * m.w;
        a.xg_e[((size_t)r << 4) + d4] = s;
    } else {
        int row = (b - GL_S - GL_E) * 16 + lr;
        if (row >= K_N) return;
        float4 s = spmm_row(a.rp_k, a.pr_k, a.x2_k, row, d4);
        float4 m = a.x2_k[((size_t)row << 4) + d4];
        s.x += MOM * m.x; s.y += MOM * m.y; s.z += MOM * m.z; s.w += MOM * m.w;
        a.x3_k[((size_t)row << 4) + d4] = s;
    }
}

// ---------------- merged dense stage ----------------
__device__ __forceinline__ uint32_t f2tf32(float f) {
    uint32_t u;
    asm("cvt.rna.tf32.f32 %0, %1;" : "=r"(u) : "f"(f));
    return u;
}

#define G_STU 2048
#define G_EXE 2048
#define G_KNO 125
#define G_IMP 1024
#define G_DENSE (G_STU + G_EXE + G_KNO + G_IMP)

struct DenseArgs {
    const float *xs0, *xs1, *xs2, *xs3;
    const float *xe0, *xe1, *xe2, *xe3;
    const float *xk0, *xk1, *xk2, *xk3;
    const int *sid, *eid;
    const float *Ws, *bs, *We, *be, *Wk, *bk, *Wd, *bd;
    const float *imp;
    float *A1, *A2, *Okt, *Odisc, *Oimp;
    uint32_t *Bt32;
};

__device__ void gemm64_body(const float* x0, const float* x1, const float* x2, const float* x3,
                            bool x3_direct, const int* ids, const float* W, const float* bias,
                            float* out, uint32_t* out_tf32, int rows, int r0, bool a_tf32,
                            bool do_disc, const float* Wd, const float* bd, float* odisc) {
    __shared__ float Ws[64 * 128];
    __shared__ float Xs[8][64];
    int tid = threadIdx.x;
    const float4* W4 = (const float4*)W;
    float4* Ws4 = (float4*)Ws;
    #pragma unroll
    for (int i = 0; i < 8; i++) Ws4[tid + i * 256] = W4[tid + i * 256];
    if (tid < 128) {
        int rr = tid >> 4;
        int c4 = tid & 15;
        int r = r0 + rr;
        float4 v = make_float4(0.f, 0.f, 0.f, 0.f);
        if (r < rows) {
            int rid = ids ? __ldg(ids + r) : r;
            size_t o = ((size_t)rid << 4) + c4;
            size_t o3 = x3_direct ? (((size_t)r << 4) + c4) : o;
            float4 a0 = __ldg((const float4*)x0 + o);
            float4 a1 = __ldg((const float4*)x1 + o);
            float4 a2 = __ldg((const float4*)x2 + o);
            float4 a3 = __ldg((const float4*)x3 + o3);
            v.x = 0.25f * (a0.x + a1.x + a2.x + a3.x);
            v.y = 0.25f * (a0.y + a1.y + a2.y + a3.y);
            v.z = 0.25f * (a0.z + a1.z + a2.z + a3.z);
            v.w = 0.25f * (a0.w + a1.w + a2.w + a3.w);
        }
        ((float4*)&Xs[rr][0])[c4] = v;
    }
    __syncthreads();
    int col = tid & 127;
    int rbase = tid >> 7;
    float bv = __ldg(bias + col);
    #pragma unroll
    for (int rr = 0; rr < 4; rr++) {
        int lrow = rr * 2 + rbase;
        int r = r0 + lrow;
        if (r >= rows) continue;
        float a = bv;
        #pragma unroll
        for (int i = 0; i < 64; i++) a = fmaf(Xs[lrow][i], Ws[i * 128 + col], a);
        float rv = (a > 0.f) ? a : LEAK_F * a;
        if (a_tf32) ((uint32_t*)out)[(size_t)r * 128 + col] = f2tf32(rv);
        else        out[(size_t)r * 128 + col] = rv;
        if (out_tf32) out_tf32[(size_t)r * 128 + col] = f2tf32(rv);
    }
    if (do_disc && tid < 32) {
        int lrow = tid >> 2;
        int part = tid & 3;
        float s = 0.f;
        #pragma unroll
        for (int i = 0; i < 16; i++) s += Xs[lrow][part * 16 + i] * __ldg(Wd + part * 16 + i);
        s += __shfl_xor_sync(0xFFFFFFFFu, s, 1);
        s += __shfl_xor_sync(0xFFFFFFFFu, s, 2);
        if (part == 0) odisc[r0 + lrow] = 1.f / (1.f + __expf(-(s + __ldg(bd))));
    }
}

__global__ void __launch_bounds__(256) dense_all_kernel(DenseArgs a) {
    int b = blockIdx.x;
    if (b < G_STU) {
        gemm64_body(a.xs0, a.xs1, a.xs2, a.xs3, true, a.sid, a.Ws, a.bs, a.A1, nullptr,
                    B_N, b * 8, true, false, nullptr, nullptr, nullptr);
    } else if (b < G_STU + G_EXE) {
        gemm64_body(a.xe0, a.xe1, a.xe2, a.xe3, true, a.eid, a.We, a.be, a.A2, nullptr,
                    B_N, (b - G_STU) * 8, true, true, a.Wd, a.bd, a.Odisc);
    } else if (b < G_STU + G_EXE + G_KNO) {
        gemm64_body(a.xk0, a.xk1, a.xk2, a.xk3, false, nullptr, a.Wk, a.bk, a.Okt, a.Bt32,
                    K_N, (b - G_STU - G_EXE) * 8, false, false, nullptr, nullptr, nullptr);
    } else {
        int t = (b - G_STU - G_EXE - G_KNO) * 256 + threadIdx.x;
        int bi = t >> 4, q = t & 15;
        ((float4*)a.Oimp)[((size_t)bi << 4) + q] =
            __ldg((const float4*)a.imp + ((size_t)__ldg(a.eid + bi) << 4) + q);
    }
}

// ---------------- TF32 tensor-core big GEMM ----------------
#define MMA_TF32(d, a, b)                                                     \
    asm volatile(                                                             \
        "mma.sync.aligned.m16n8k8.row.col.f32.tf32.tf32.f32 "                 \
        "{%0,%1,%2,%3}, {%4,%5,%6,%7}, {%8,%9}, {%0,%1,%2,%3};\n"             \
        : "+f"(d[0]), "+f"(d[1]), "+f"(d[2]), "+f"(d[3])                      \
        : "r"(a[0]), "r"(a[1]), "r"(a[2]), "r"(a[3]), "r"(b[0]), "r"(b[1]))

#define SMPAD 36
#define STAGE_W (3 * 128 * SMPAD)
#define GEMM_SMEM_BYTES (2 * STAGE_W * 4)

__device__ __forceinline__ void cp16(uint32_t dst, const void* src) {
    asm volatile("cp.async.cg.shared.global [%0], [%1], 16;" :: "r"(dst), "l"(src));
}

__device__ __forceinline__ void load_stage(uint32_t sbase, const uint32_t* A1, const uint32_t* A2,
                                           const uint32_t* B32, int m0, int n0, int kc, int tid) {
    #pragma unroll
    for (int i = 0; i < 4; i++) {
        int idx = tid + i * 256;
        int row = idx >> 3, q = idx & 7;
        uint32_t off = (uint32_t)(row * SMPAD + q * 4) * 4;
        cp16(sbase + off,                       A1 + (size_t)(m0 + row) * 128 + kc + q * 4);
        cp16(sbase + 128 * SMPAD * 4 + off,     A2 + (size_t)(m0 + row) * 128 + kc + q * 4);
        cp16(sbase + 2 * 128 * SMPAD * 4 + off, B32 + (size_t)(n0 + row) * 128 + kc + q * 4);
    }
    asm volatile("cp.async.commit_group;");
}

__global__ void __launch_bounds__(256, 1) big_gemm_tf32_dual(
    const uint32_t* __restrict__ A1, const uint32_t* __restrict__ A2,
    const uint32_t* __restrict__ B32, float* __restrict__ O1, float* __restrict__ O2) {
    extern __shared__ uint32_t sm[];
    uint32_t sbase = (uint32_t)__cvta_generic_to_shared(sm);

    int tid = threadIdx.x;
    int warp = tid >> 5;
    int lane = tid & 31;
    int g = lane >> 2;
    int tg = lane & 3;
    int wm = warp >> 1;
    int wn = warp & 1;
    int m0 = blockIdx.x * 128;
    int n0 = blockIdx.y * 128;

    float acc1[2][8][4] = {};
    float acc2[2][8][4] = {};

    load_stage(sbase, A1, A2, B32, m0, n0, 0, tid);

    #pragma unroll
    for (int c = 0; c < 4; c++) {
        if (c < 3) {
            load_stage(sbase + ((c + 1) & 1) * STAGE_W * 4, A1, A2, B32, m0, n0, (c + 1) * 32, tid);
            asm volatile("cp.async.wait_group 1;");
        } else {
            asm volatile("cp.async.wait_group 0;");
        }
        __syncthreads();
        const uint32_t* As1 = sm + (c & 1) * STAGE_W;
        const uint32_t* As2 = As1 + 128 * SMPAD;
        const uint32_t* Bs  = As2 + 128 * SMPAD;

        #pragma unroll
        for (int ks = 0; ks < 4; ks++) {
            int k0 = ks * 8;
            uint32_t b[8][2];
            #pragma unroll
            for (int nt = 0; nt < 8; nt++) {
                const uint32_t* bp = &Bs[(wn * 64 + nt * 8 + g) * SMPAD + k0 + tg];
                b[nt][0] = bp[0];
                b[nt][1] = bp[4];
            }
            #pragma unroll
            for (int mt = 0; mt < 2; mt++) {
                uint32_t a[4];
                const uint32_t* ap = &As1[(wm * 32 + mt * 16 + g) * SMPAD + k0 + tg];
                a[0] = ap[0]; a[1] = ap[8 * SMPAD]; a[2] = ap[4]; a[3] = ap[8 * SMPAD + 4];
                #pragma unroll
                for (int nt = 0; nt < 8; nt++) MMA_TF32(acc1[mt][nt], a, b[nt]);
                ap = &As2[(wm * 32 + mt * 16 + g) * SMPAD + k0 + tg];
                a[0] = ap[0]; a[1] = ap[8 * SMPAD]; a[2] = ap[4]; a[3] = ap[8 * SMPAD + 4];
                #pragma unroll
                for (int nt = 0; nt < 8; nt++) MMA_TF32(acc2[mt][nt], a, b[nt]);
            }
        }
        __syncthreads();
    }

    #pragma unroll
    for (int mt = 0; mt < 2; mt++) {
        #pragma unroll
        for (int nt = 0; nt < 8; nt++) {
            int col = n0 + wn * 64 + nt * 8 + tg * 2;
            if (col >= K_N) continue;
            size_t r0 = (size_t)(m0 + wm * 32 + mt * 16 + g);
            size_t r1 = r0 + 8;
            *(float2*)(O1 + r0 * K_N + col) = make_float2(acc1[mt][nt][0], acc1[mt][nt][1]);
            *(float2*)(O1 + r1 * K_N + col) = make_float2(acc1[mt][nt][2], acc1[mt][nt][3]);
            *(float2*)(O2 + r0 * K_N + col) = make_float2(acc2[mt][nt][0], acc2[mt][nt][1]);
            *(float2*)(O2 + r1 * K_N + col) = make_float2(acc2[mt][nt][2], acc2[mt][nt][3]);
        }
    }
}

// ---------------- host orchestration ----------------
extern "C" void kernel_launch(void* const* d_in, const int* in_sizes, int n_in,
                              void* d_out, int out_size) {
    (void)in_sizes; (void)n_in; (void)out_size;
    const int*   student_id  = (const int*)d_in[0];
    const int*   exercise_id = (const int*)d_in[1];
    const float* stu_emb     = (const float*)d_in[3];
    const float* exer_emb    = (const float*)d_in[4];
    const float* know_emb    = (const float*)d_in[5];
    const float* impact_emb  = (const float*)d_in[6];
    const int*   s_rows = (const int*)d_in[7];
    const int*   s_cols = (const int*)d_in[8];
    const float* s_vals = (const float*)d_in[9];
    const int*   e_rows = (const int*)d_in[10];
    const int*   e_cols = (const int*)d_in[11];
    const float* e_vals = (const float*)d_in[12];
    const int*   k_rows = (const int*)d_in[13];
    const int*   k_cols = (const int*)d_in[14];
    const float* k_vals = (const float*)d_in[15];
    const float* W_stu  = (const float*)d_in[16];
    const float* b_stu  = (const float*)d_in[17];
    const float* W_exer = (const float*)d_in[18];
    const float* b_exer = (const float*)d_in[19];
    const float* W_know = (const float*)d_in[20];
    const float* b_know = (const float*)d_in[21];
    const float* W_disc = (const float*)d_in[22];
    const float* b_disc = (const float*)d_in[23];

    unsigned char* A = nullptr;
    cudaGetSymbolAddress((void**)&A, g_arena);

    int*  rp_s  = (int*)(A + O_RP_S);
    int*  rp_e  = (int*)(A + O_RP_E);
    int*  rp_k  = (int*)(A + O_RP_K);
    unsigned long long* lk = (unsigned long long*)(A + O_LK);
    int*  cur_s = (int*)(A + O_CUR_S);
    int*  cur_e = (int*)(A + O_CUR_E);
    int*  cur_k = (int*)(A + O_CUR_K);
    int2* pairs_s = (int2*)(A + O_PAIRS_S);
    int2* pairs_e = (int2*)(A + O_PAIRS_E);
    int2* pairs_k = (int2*)(A + O_PAIRS_K);
    float* x1_s = (float*)(A + O_X1_S);
    float* x2_s = (float*)(A + O_X2_S);
    float* x1_e = (float*)(A + O_X1_E);
    float* x2_e = (float*)(A + O_X2_E);
    float* x1_k = (float*)(A + O_X1_K);
    float* x2_k = (float*)(A + O_X2_K);
    float* x3_k = (float*)(A + O_X3_K);
    float* xg_s = (float*)(A + O_XG_S);
    float* xg_e = (float*)(A + O_XG_E);
    float* A1   = (float*)(A + O_A1);
    float* A2   = (float*)(A + O_A2);
    uint32_t* Bt32 = (uint32_t*)(A + O_BT32);

    // 1) CSR build: zero, hist, lookback-scan, scatter
    zero_kernel<<<(ZERO_INTS + BT_PAD_WORDS + 1023) / 1024, 1024>>>(
        (int*)A, Bt32 + (size_t)K_N * 128);
    hist_all_kernel<<<(Q4_TOT + 255) / 256, 256>>>(
        (const int4*)s_rows, (const int4*)e_rows, (const int4*)k_rows, rp_s, rp_e, rp_k);
    scan_lookback_kernel<<<NB_TOT, 256>>>(rp_s, rp_e, rp_k, cur_s, cur_e, cur_k, lk);
    scatter_all_kernel<<<(Q4_TOT + 255) / 256, 256>>>(
        (const int4*)s_rows, (const int4*)s_cols, (const float4*)s_vals,
        (const int4*)e_rows, (const int4*)e_cols, (const float4*)e_vals,
        (const int4*)k_rows, (const int4*)k_cols, (const float4*)k_vals,
        cur_s, cur_e, cur_k, pairs_s, pairs_e, pairs_k);

    // 2) layers 1-2 full; layer 3 batch-restricted + full know
    const float* in_s[3] = {stu_emb, x1_s, x2_s};
    const float* in_e[3] = {exer_emb, x1_e, x2_e};
    const float* in_k[3] = {know_emb, x1_k, x2_k};
    for (int l = 0; l < 2; l++) {
        SpmmArgs sa;
        sa.rp[0] = rp_s;  sa.rp[1] = rp_e;  sa.rp[2] = rp_k;
        sa.pr[0] = pairs_s; sa.pr[1] = pairs_e; sa.pr[2] = pairs_k;
        sa.xin[0] = (const float4*)in_s[l]; sa.xin[1] = (const float4*)in_e[l]; sa.xin[2] = (const float4*)in_k[l];
        sa.xout[0] = (float4*)in_s[l + 1];  sa.xout[1] = (float4*)in_e[l + 1];  sa.xout[2] = (float4*)in_k[l + 1];
        sa.nrows[0] = S_N; sa.nrows[1] = E_N; sa.nrows[2] = K_N;
        spmm_all_kernel<<<GB_S + GB_E + GB_K, 256>>>(sa);
    }
    {
        Spmm3Args a3;
        a3.rp_s = rp_s; a3.pr_s = pairs_s; a3.x2_s = (const float4*)x2_s; a3.xg_s = (float4*)xg_s; a3.sid = student_id;
        a3.rp_e = rp_e; a3.pr_e = pairs_e; a3.x2_e = (const float4*)x2_e; a3.xg_e = (float4*)xg_e; a3.eid = exercise_id;
        a3.rp_k = rp_k; a3.pr_k = pairs_k; a3.x2_k = (const float4*)x2_k; a3.x3_k = (float4*)x3_k;
        spmm_l3_kernel<<<GL_S + GL_E + GL_K, 256>>>(a3);
    }

    // 3) output layout
    float* out   = (float*)d_out;
    float* O1    = out;
    float* O2    = O1 + (size_t)B_N * K_N;
    float* Odisc = O2 + (size_t)B_N * K_N;
    float* Okt   = Odisc + B_N;
    float* Oimp  = Okt + (size_t)K_N * FF;

    // 4) merged dense stage
    DenseArgs da;
    da.xs0 = stu_emb; da.xs1 = x1_s; da.xs2 = x2_s; da.xs3 = xg_s;
    da.xe0 = exer_emb; da.xe1 = x1_e; da.xe2 = x2_e; da.xe3 = xg_e;
    da.xk0 = know_emb; da.xk1 = x1_k; da.xk2 = x2_k; da.xk3 = x3_k;
    da.sid = student_id; da.eid = exercise_id;
    da.Ws = W_stu; da.bs = b_stu; da.We = W_exer; da.be = b_exer;
    da.Wk = W_know; da.bk = b_know; da.Wd = W_disc; da.bd = b_disc;
    da.imp = impact_emb;
    da.A1 = A1; da.A2 = A2; da.Okt = Okt; da.Odisc = Odisc; da.Oimp = Oimp;
    da.Bt32 = Bt32;
    dense_all_kernel<<<G_DENSE, 256>>>(da);

    // 5) TF32 big GEMM pair
    static bool attr_set = false;
    if (!attr_set) {
        cudaFuncSetAttribute(big_gemm_tf32_dual,
                             cudaFuncAttributeMaxDynamicSharedMemorySize, GEMM_SMEM_BYTES);
        attr_set = true;
    }
    dim3 grid(B_N / 128, 1024 / 128);
    big_gemm_tf32_dual<<<grid, 256, GEMM_SMEM_BYTES>>>(
        (const uint32_t*)A1, (const uint32_t*)A2, Bt32, O1, O2);
}

// round 8
// speedup vs baseline: 1.1719x; 1.0931x over previous
#include <cuda_runtime.h>
#include <cstdint>
#include <cstddef>

#define S_N 100000
#define E_N 30000
#define K_N 1000
#define DD 64
#define FF 128
#define B_N 16384
#define NNZ_S 1600000
#define NNZ_E 480000
#define NNZ_K 32000
#define NNZ_TOT (NNZ_S + NNZ_E + NNZ_K)
#define MOM 0.9f
#define LEAK_F 0.1f

#define NB_S 98
#define NB_E 30
#define NB_K 1
#define NB_TOT (NB_S + NB_E + NB_K)

static constexpr size_t al256(size_t x) { return (x + 255) & ~(size_t)255; }

// ---------------- static scratch arena ----------------
static constexpr size_t O_RP_S = 0;
static constexpr size_t O_RP_E = O_RP_S + (size_t)(S_N + 1) * 4;
static constexpr size_t O_RP_K = O_RP_E + (size_t)(E_N + 1) * 4;
static constexpr size_t RP_END = O_RP_K + (size_t)(K_N + 1) * 4;
static constexpr size_t O_LK   = al256(RP_END);
static constexpr size_t LK_END = O_LK + (size_t)NB_TOT * 8;
static constexpr int    ZERO_INTS = (int)(LK_END / 4);

static constexpr size_t O_CUR_S = al256(LK_END);
static constexpr size_t O_CUR_E = al256(O_CUR_S + (size_t)S_N * 4);
static constexpr size_t O_CUR_K = al256(O_CUR_E + (size_t)E_N * 4);
static constexpr size_t O_PAIRS_S = al256(O_CUR_K + (size_t)K_N * 4);
static constexpr size_t O_PAIRS_E = al256(O_PAIRS_S + (size_t)NNZ_S * 8);
static constexpr size_t O_PAIRS_K = al256(O_PAIRS_E + (size_t)NNZ_E * 8);
static constexpr size_t O_X1_S = al256(O_PAIRS_K + (size_t)NNZ_K * 8);
static constexpr size_t O_X2_S = al256(O_X1_S + (size_t)S_N * DD * 4);
static constexpr size_t O_X1_E = al256(O_X2_S + (size_t)S_N * DD * 4);
static constexpr size_t O_X2_E = al256(O_X1_E + (size_t)E_N * DD * 4);
static constexpr size_t O_X1_K = al256(O_X2_E + (size_t)E_N * DD * 4);
static constexpr size_t O_X2_K = al256(O_X1_K + (size_t)K_N * DD * 4);
static constexpr size_t O_X3_K = al256(O_X2_K + (size_t)K_N * DD * 4);
static constexpr size_t O_XG_S = al256(O_X3_K + (size_t)K_N * DD * 4);
static constexpr size_t O_XG_E = al256(O_XG_S + (size_t)B_N * DD * 4);
static constexpr size_t O_A1   = al256(O_XG_E + (size_t)B_N * DD * 4);
static constexpr size_t O_A2   = al256(O_A1 + (size_t)B_N * FF * 4);
static constexpr size_t O_BT32 = al256(O_A2 + (size_t)B_N * FF * 4);
static constexpr size_t ARENA_BYTES = al256(O_BT32 + (size_t)1024 * FF * 4);

__device__ __align__(256) unsigned char g_arena[ARENA_BYTES];

// ---------------- zero (rowptrs + lookback states + Bt32 pad) ----------------
#define BT_PAD_WORDS (24 * 128)
__global__ void zero_kernel(int* p, uint32_t* bt_pad) {
    int i = blockIdx.x * blockDim.x + threadIdx.x;
    if (i < ZERO_INTS) p[i] = 0;
    else if (i < ZERO_INTS + BT_PAD_WORDS) bt_pad[i - ZERO_INTS] = 0u;
}

// ---------------- histogram (x4 vectorized) ----------------
#define Q4_S (NNZ_S / 4)
#define Q4_E (NNZ_E / 4)
#define Q4_K (NNZ_K / 4)
#define Q4_TOT (Q4_S + Q4_E + Q4_K)

__global__ void hist_all_kernel(const int4* __restrict__ s_rows, const int4* __restrict__ e_rows,
                                const int4* __restrict__ k_rows, int* __restrict__ rp_s,
                                int* __restrict__ rp_e, int* __restrict__ rp_k) {
    int i = blockIdx.x * blockDim.x + threadIdx.x;
    int4 r; int* rp;
    if (i < Q4_S)             { r = __ldg(s_rows + i); rp = rp_s; }
    else if (i < Q4_S + Q4_E) { r = __ldg(e_rows + (i - Q4_S)); rp = rp_e; }
    else if (i < Q4_TOT)      { r = __ldg(k_rows + (i - Q4_S - Q4_E)); rp = rp_k; }
    else return;
    atomicAdd(&rp[r.x + 1], 1);
    atomicAdd(&rp[r.y + 1], 1);
    atomicAdd(&rp[r.z + 1], 1);
    atomicAdd(&rp[r.w + 1], 1);
}

// ---------------- single-pass decoupled-lookback scan ----------------
__global__ void __launch_bounds__(256) scan_lookback_kernel(
    int* __restrict__ rp_s, int* __restrict__ rp_e, int* __restrict__ rp_k,
    int* __restrict__ cur_s, int* __restrict__ cur_e, int* __restrict__ cur_k,
    unsigned long long* __restrict__ lk) {
    __shared__ int wsum[8];
    __shared__ int s_excl;
    const unsigned FULL = 0xFFFFFFFFu;
    int b = blockIdx.x, t = threadIdx.x, lane = t & 31, wid = t >> 5;
    int *x, *c, n, lb;
    if (b < NB_S)             { x = rp_s; c = cur_s; n = S_N + 1; lb = b; }
    else if (b < NB_S + NB_E) { x = rp_e; c = cur_e; n = E_N + 1; lb = b - NB_S; }
    else                      { x = rp_k; c = cur_k; n = K_N + 1; lb = b - NB_S - NB_E; }
    int base = lb * 1024 + t * 4;
    int v0 = (base     < n) ? x[base]     : 0;
    int v1 = (base + 1 < n) ? x[base + 1] : 0;
    int v2 = (base + 2 < n) ? x[base + 2] : 0;
    int v3 = (base + 3 < n) ? x[base + 3] : 0;
    v1 += v0; v2 += v1; v3 += v2;
    int tin = v3;
    int incl = tin;
    #pragma unroll
    for (int off = 1; off < 32; off <<= 1) {
        int o = __shfl_up_sync(FULL, incl, off);
        if (lane >= off) incl += o;
    }
    if (lane == 31) wsum[wid] = incl;
    __syncthreads();
    if (wid == 0) {
        int ws = (lane < 8) ? wsum[lane] : 0;
        #pragma unroll
        for (int off = 1; off < 8; off <<= 1) {
            int o = __shfl_up_sync(FULL, ws, off);
            if (lane >= off) ws += o;
        }
        if (lane < 8) wsum[lane] = ws;
    }
    __syncthreads();
    int agg = wsum[7];
    int warp_excl = wid ? wsum[wid - 1] : 0;
    int thread_excl = warp_excl + (incl - tin);

    if (wid == 0) {
        volatile unsigned long long* vlk = (volatile unsigned long long*)lk;
        if (lb == 0) {
            if (lane == 0) { vlk[b] = (2ULL << 32) | (unsigned)agg; s_excl = 0; }
        } else {
            if (lane == 0) vlk[b] = (1ULL << 32) | (unsigned)agg;
            int gbase = b - lb;
            int running = 0;
            int j = lb - 1;
            while (true) {
                int idx = j - lane;
                bool valid = idx >= 0;
                unsigned long long w = 0; int st = 0;
                while (true) {
                    if (valid) { w = vlk[gbase + idx]; st = (int)(w >> 32); }
                    if (__all_sync(FULL, !valid || st != 0)) break;
                }
                unsigned pm = __ballot_sync(FULL, valid && st == 2);
                int lane_p = pm ? (__ffs(pm) - 1) : 32;
                int val = (valid && lane <= lane_p) ? (int)(unsigned)w : 0;
                #pragma unroll
                for (int off = 16; off; off >>= 1) val += __shfl_xor_sync(FULL, val, off);
                running += val;
                if (lane_p < 32) break;
                j -= 32;
            }
            if (lane == 0) {
                vlk[b] = (2ULL << 32) | (unsigned)(running + agg);
                s_excl = running;
            }
        }
    }
    __syncthreads();
    int off0 = s_excl + thread_excl;
    if (base < n)     { int val = v0 + off0; x[base]     = val; if (base     < n - 1) c[base]     = val; }
    if (base + 1 < n) { int val = v1 + off0; x[base + 1] = val; if (base + 1 < n - 1) c[base + 1] = val; }
    if (base + 2 < n) { int val = v2 + off0; x[base + 2] = val; if (base + 2 < n - 1) c[base + 2] = val; }
    if (base + 3 < n) { int val = v3 + off0; x[base + 3] = val; if (base + 3 < n - 1) c[base + 3] = val; }
}

// ---------------- scatter (x4 vectorized) ----------------
__global__ void scatter_all_kernel(
    const int4* __restrict__ s_rows, const int4* __restrict__ s_cols, const float4* __restrict__ s_vals,
    const int4* __restrict__ e_rows, const int4* __restrict__ e_cols, const float4* __restrict__ e_vals,
    const int4* __restrict__ k_rows, const int4* __restrict__ k_cols, const float4* __restrict__ k_vals,
    int* __restrict__ cur_s, int* __restrict__ cur_e, int* __restrict__ cur_k,
    int2* __restrict__ pairs_s, int2* __restrict__ pairs_e, int2* __restrict__ pairs_k) {
    int i = blockIdx.x * blockDim.x + threadIdx.x;
    int4 r, cidx; float4 v; int* cur; int2* pairs;
    if (i < Q4_S) {
        r = __ldg(s_rows + i); cidx = __ldg(s_cols + i); v = __ldg(s_vals + i);
        cur = cur_s; pairs = pairs_s;
    } else if (i < Q4_S + Q4_E) {
        int j = i - Q4_S;
        r = __ldg(e_rows + j); cidx = __ldg(e_cols + j); v = __ldg(e_vals + j);
        cur = cur_e; pairs = pairs_e;
    } else if (i < Q4_TOT) {
        int j = i - Q4_S - Q4_E;
        r = __ldg(k_rows + j); cidx = __ldg(k_cols + j); v = __ldg(k_vals + j);
        cur = cur_k; pairs = pairs_k;
    } else return;
    int p0 = atomicAdd(&cur[r.x], 1);
    int p1 = atomicAdd(&cur[r.y], 1);
    int p2 = atomicAdd(&cur[r.z], 1);
    int p3 = atomicAdd(&cur[r.w], 1);
    pairs[p0] = make_int2(cidx.x, __float_as_int(v.x));
    pairs[p1] = make_int2(cidx.y, __float_as_int(v.y));
    pairs[p2] = make_int2(cidx.z, __float_as_int(v.z));
    pairs[p3] = make_int2(cidx.w, __float_as_int(v.w));
}

// ---------------- SpMM core ----------------
__device__ __forceinline__ float4 spmm_row(const int* __restrict__ rowptr,
                                           const int2* __restrict__ pairs,
                                           const float4* __restrict__ xin, int row, int d4) {
    int beg = __ldg(rowptr + row);
    int end = __ldg(rowptr + row + 1);
    float4 s = make_float4(0.f, 0.f, 0.f, 0.f);
    int j = beg;
    for (; j + 3 < end; j += 4) {
        int2 p0 = __ldg(pairs + j);
        int2 p1 = __ldg(pairs + j + 1);
        int2 p2 = __ldg(pairs + j + 2);
        int2 p3 = __ldg(pairs + j + 3);
        float4 v0 = __ldg(xin + ((size_t)p0.x << 4) + d4);
        float4 v1 = __ldg(xin + ((size_t)p1.x << 4) + d4);
        float4 v2 = __ldg(xin + ((size_t)p2.x << 4) + d4);
        float4 v3 = __ldg(xin + ((size_t)p3.x << 4) + d4);
        float w0 = __int_as_float(p0.y), w1 = __int_as_float(p1.y);
        float w2 = __int_as_float(p2.y), w3 = __int_as_float(p3.y);
        s.x = fmaf(w0, v0.x, s.x); s.y = fmaf(w0, v0.y, s.y); s.z = fmaf(w0, v0.z, s.z); s.w = fmaf(w0, v0.w, s.w);
        s.x = fmaf(w1, v1.x, s.x); s.y = fmaf(w1, v1.y, s.y); s.z = fmaf(w1, v1.z, s.z); s.w = fmaf(w1, v1.w, s.w);
        s.x = fmaf(w2, v2.x, s.x); s.y = fmaf(w2, v2.y, s.y); s.z = fmaf(w2, v2.z, s.z); s.w = fmaf(w2, v2.w, s.w);
        s.x = fmaf(w3, v3.x, s.x); s.y = fmaf(w3, v3.y, s.y); s.z = fmaf(w3, v3.z, s.z); s.w = fmaf(w3, v3.w, s.w);
    }
    for (; j < end; j++) {
        int2 p = __ldg(pairs + j);
        float w = __int_as_float(p.y);
        float4 v = __ldg(xin + ((size_t)p.x << 4) + d4);
        s.x = fmaf(w, v.x, s.x); s.y = fmaf(w, v.y, s.y); s.z = fmaf(w, v.z, s.z); s.w = fmaf(w, v.w, s.w);
    }
    return s;
}

#define GB_S 6250
#define GB_E 1875
#define GB_K 63

struct SpmmArgs {
    const int* rp[3];
    const int2* pr[3];
    const float4* xin[3];
    float4* xout[3];
    int nrows[3];
};

__global__ void __launch_bounds__(256) spmm_all_kernel(SpmmArgs a) {
    int b = blockIdx.x;
    int seg, lb;
    if (b < GB_S)             { seg = 0; lb = b; }
    else if (b < GB_S + GB_E) { seg = 1; lb = b - GB_S; }
    else                      { seg = 2; lb = b - GB_S - GB_E; }
    int row = lb * 16 + (threadIdx.x >> 4);
    int d4 = threadIdx.x & 15;
    if (row >= a.nrows[seg]) return;
    const float4* xin = a.xin[seg];
    float4 s = spmm_row(a.rp[seg], a.pr[seg], xin, row, d4);
    size_t o = ((size_t)row << 4) + d4;
    float4 m = xin[o];
    s.x += MOM * m.x; s.y += MOM * m.y; s.z += MOM * m.z; s.w += MOM * m.w;
    a.xout[seg][o] = s;
}

// ---------------- layer 3: batch-restricted stu/exer + full know ----------------
#define GL_S 1024
#define GL_E 1024
#define GL_K 63

struct Spmm3Args {
    const int* rp_s; const int2* pr_s; const float4* x2_s; float4* xg_s; const int* sid;
    const int* rp_e; const int2* pr_e; const float4* x2_e; float4* xg_e; const int* eid;
    const int* rp_k; const int2* pr_k; const float4* x2_k; float4* x3_k;
};

__global__ void __launch_bounds__(256) spmm_l3_kernel(Spmm3Args a) {
    int b = blockIdx.x;
    int d4 = threadIdx.x & 15;
    int lr = (threadIdx.x >> 4);
    if (b < GL_S) {
        int r = b * 16 + lr;
        int row = __ldg(a.sid + r);
        float4 s = spmm_row(a.rp_s, a.pr_s, a.x2_s, row, d4);
        float4 m = a.x2_s[((size_t)row << 4) + d4];
        s.x += MOM * m.x; s.y += MOM * m.y; s.z += MOM * m.z; s.w += MOM * m.w;
        a.xg_s[((size_t)r << 4) + d4] = s;
    } else if (b < GL_S + GL_E) {
        int r = (b - GL_S) * 16 + lr;
        int row = __ldg(a.eid + r);
        float4 s = spmm_row(a.rp_e, a.pr_e, a.x2_e, row, d4);
        float4 m = a.x2_e[((size_t)row << 4) + d4];
        s.x += MOM * m.x; s.y += MOM * m.y; s.z += MOM * m.z; s.w += MOM * m.w;
        a.xg_e[((size_t)r << 4) + d4] = s;
    } else {
        int row = (b - GL_S - GL_E) * 16 + lr;
        if (row >= K_N) return;
        float4 s = spmm_row(a.rp_k, a.pr_k, a.x2_k, row, d4);
        float4 m = a.x2_k[((size_t)row << 4) + d4];
        s.x += MOM * m.x; s.y += MOM * m.y; s.z += MOM * m.z; s.w += MOM * m.w;
        a.x3_k[((size_t)row << 4) + d4] = s;
    }
}

// ---------------- tf32 helpers / MMA macro ----------------
__device__ __forceinline__ uint32_t f2tf32(float f) {
    uint32_t u;
    asm("cvt.rna.tf32.f32 %0, %1;" : "=r"(u) : "f"(f));
    return u;
}

#define MMA_TF32(d, a, b)                                                     \
    asm volatile(                                                             \
        "mma.sync.aligned.m16n8k8.row.col.f32.tf32.tf32.f32 "                 \
        "{%0,%1,%2,%3}, {%4,%5,%6,%7}, {%8,%9}, {%0,%1,%2,%3};\n"             \
        : "+f"(d[0]), "+f"(d[1]), "+f"(d[2]), "+f"(d[3])                      \
        : "r"(a[0]), "r"(a[1]), "r"(a[2]), "r"(a[3]), "r"(b[0]), "r"(b[1]))

// ---------------- dense stage (tensor cores) for stu/exer batch rows ----------------
// Dynamic smem layout (words): Xs[64*68] | Wt[128*68] | bsm[128] | wd[64]
#define XS_STRIDE 68
#define WT_STRIDE 68
#define DM_XS_W   (64 * XS_STRIDE)
#define DM_WT_W   (128 * WT_STRIDE)
#define DM_SMEM_BYTES ((DM_XS_W + DM_WT_W + 128 + 64) * 4)

struct DenseMmaArgs {
    const float *x0s, *x1s, *x2s, *x3s;   // x3s compact [B_N,64]
    const float *x0e, *x1e, *x2e, *x3e;   // x3e compact
    const int *sid, *eid;
    const float *Ws, *bs, *We, *be, *Wd, *bd;
    uint32_t *A1, *A2;
    float *Odisc;
};

__global__ void __launch_bounds__(256) dense_mma_kernel(DenseMmaArgs a) {
    extern __shared__ uint32_t dsm[];
    uint32_t* Xs = dsm;
    uint32_t* Wt = dsm + DM_XS_W;
    float* bsm = (float*)(dsm + DM_XS_W + DM_WT_W);
    float* wd  = bsm + 128;
    const unsigned FULL = 0xFFFFFFFFu;
    int b = blockIdx.x, tid = threadIdx.x;
    bool is_e = b >= 256;
    int r0 = (is_e ? b - 256 : b) * 64;
    const float* x0 = is_e ? a.x0e : a.x0s;
    const float* x1 = is_e ? a.x1e : a.x1s;
    const float* x2 = is_e ? a.x2e : a.x2s;
    const float* x3 = is_e ? a.x3e : a.x3s;
    const int* ids  = is_e ? a.eid : a.sid;
    const float* W  = is_e ? a.We : a.Ws;
    const float* bias = is_e ? a.be : a.bs;
    uint32_t* out = is_e ? a.A2 : a.A1;

    // W [64k][128n] row-major -> Wt [n][k] tf32
    for (int i = tid; i < 8192; i += 256) {
        int k = i >> 7, n = i & 127;
        Wt[n * WT_STRIDE + k] = f2tf32(__ldg(W + i));
    }
    if (tid < 128) bsm[tid] = __ldg(bias + tid);
    if (is_e && tid < 64) wd[tid] = __ldg(a.Wd + tid);

    // gather X: 64 rows x 16 float4
    for (int i = tid; i < 1024; i += 256) {
        int rr = i >> 4, c4 = i & 15;
        int r = r0 + rr;
        int rid = __ldg(ids + r);
        size_t o  = ((size_t)rid << 4) + c4;
        size_t o3 = ((size_t)r << 4) + c4;
        float4 a0 = __ldg((const float4*)x0 + o);
        float4 a1 = __ldg((const float4*)x1 + o);
        float4 a2 = __ldg((const float4*)x2 + o);
        float4 a3 = __ldg((const float4*)x3 + o3);
        uint4 w;
        w.x = f2tf32(0.25f * (a0.x + a1.x + a2.x + a3.x));
        w.y = f2tf32(0.25f * (a0.y + a1.y + a2.y + a3.y));
        w.z = f2tf32(0.25f * (a0.z + a1.z + a2.z + a3.z));
        w.w = f2tf32(0.25f * (a0.w + a1.w + a2.w + a3.w));
        *(uint4*)&Xs[rr * XS_STRIDE + c4 * 4] = w;
    }
    __syncthreads();

    int warp = tid >> 5, lane = tid & 31, g = lane >> 2, tg = lane & 3;
    int wm = warp >> 1;     // 4 m-groups of 16 rows
    int wn = warp & 1;      // 2 n-halves of 64 cols
    float acc[8][4] = {};
    #pragma unroll
    for (int ks = 0; ks < 8; ks++) {
        int k0 = ks * 8;
        uint32_t A[4];
        const uint32_t* ap = &Xs[(wm * 16 + g) * XS_STRIDE + k0 + tg];
        A[0] = ap[0]; A[1] = ap[8 * XS_STRIDE]; A[2] = ap[4]; A[3] = ap[8 * XS_STRIDE + 4];
        #pragma unroll
        for (int nt = 0; nt < 8; nt++) {
            const uint32_t* bp = &Wt[(wn * 64 + nt * 8 + g) * WT_STRIDE + k0 + tg];
            uint32_t B[2] = {bp[0], bp[4]};
            MMA_TF32(acc[nt], A, B);
        }
    }

    // epilogue: bias + leaky + tf32 store
    #pragma unroll
    for (int nt = 0; nt < 8; nt++) {
        int col = wn * 64 + nt * 8 + tg * 2;
        float b0 = bsm[col], b1 = bsm[col + 1];
        size_t rA = (size_t)(r0 + wm * 16 + g);
        size_t rB = rA + 8;
        float v0 = acc[nt][0] + b0; v0 = (v0 > 0.f) ? v0 : LEAK_F * v0;
        float v1 = acc[nt][1] + b1; v1 = (v1 > 0.f) ? v1 : LEAK_F * v1;
        float v2 = acc[nt][2] + b0; v2 = (v2 > 0.f) ? v2 : LEAK_F * v2;
        float v3 = acc[nt][3] + b1; v3 = (v3 > 0.f) ? v3 : LEAK_F * v3;
        *(uint2*)(out + rA * 128 + col) = make_uint2(f2tf32(v0), f2tf32(v1));
        *(uint2*)(out + rB * 128 + col) = make_uint2(f2tf32(v2), f2tf32(v3));
    }

    // disc (exer blocks): sigmoid(X @ Wd + bd)
    if (is_e) {
        int row = tid >> 2, part = tid & 3;
        float s = 0.f;
        #pragma unroll
        for (int i = 0; i < 16; i++)
            s += __uint_as_float(Xs[row * XS_STRIDE + part * 16 + i]) * wd[part * 16 + i];
        s += __shfl_xor_sync(FULL, s, 1);
        s += __shfl_xor_sync(FULL, s, 2);
        if (part == 0) a.Odisc[r0 + row] = 1.f / (1.f + __expf(-(s + __ldg(a.bd))));
    }
}

// ---------------- dense stage (FFMA) for know + impact gather ----------------
#define G_KNO 125
#define G_IMP 1024
#define G_DENSE (G_KNO + G_IMP)

struct DenseArgs {
    const float *xk0, *xk1, *xk2, *xk3;
    const int *eid;
    const float *Wk, *bk;
    const float *imp;
    float *Okt, *Oimp;
    uint32_t *Bt32;
};

__global__ void __launch_bounds__(256) dense_all_kernel(DenseArgs a) {
    int b = blockIdx.x;
    if (b < G_KNO) {
        __shared__ float Ws[64 * 128];
        __shared__ float Xs[8][64];
        int tid = threadIdx.x;
        int r0 = b * 8;
        const float4* W4 = (const float4*)a.Wk;
        float4* Ws4 = (float4*)Ws;
        #pragma unroll
        for (int i = 0; i < 8; i++) Ws4[tid + i * 256] = W4[tid + i * 256];
        if (tid < 128) {
            int rr = tid >> 4;
            int c4 = tid & 15;
            int r = r0 + rr;
            float4 v = make_float4(0.f, 0.f, 0.f, 0.f);
            if (r < K_N) {
                size_t o = ((size_t)r << 4) + c4;
                float4 a0 = __ldg((const float4*)a.xk0 + o);
                float4 a1 = __ldg((const float4*)a.xk1 + o);
                float4 a2 = __ldg((const float4*)a.xk2 + o);
                float4 a3 = __ldg((const float4*)a.xk3 + o);
                v.x = 0.25f * (a0.x + a1.x + a2.x + a3.x);
                v.y = 0.25f * (a0.y + a1.y + a2.y + a3.y);
                v.z = 0.25f * (a0.z + a1.z + a2.z + a3.z);
                v.w = 0.25f * (a0.w + a1.w + a2.w + a3.w);
            }
            ((float4*)&Xs[rr][0])[c4] = v;
        }
        __syncthreads();
        int col = tid & 127;
        int rbase = tid >> 7;
        float bv = __ldg(a.bk + col);
        #pragma unroll
        for (int rr = 0; rr < 4; rr++) {
            int lrow = rr * 2 + rbase;
            int r = r0 + lrow;
            if (r >= K_N) continue;
            float acc = bv;
            #pragma unroll
            for (int i = 0; i < 64; i++) acc = fmaf(Xs[lrow][i], Ws[i * 128 + col], acc);
            float rv = (acc > 0.f) ? acc : LEAK_F * acc;
            a.Okt[(size_t)r * 128 + col] = rv;
            a.Bt32[(size_t)r * 128 + col] = f2tf32(rv);
        }
    } else {
        int t = (b - G_KNO) * 256 + threadIdx.x;
        int bi = t >> 4, q = t & 15;
        ((float4*)a.Oimp)[((size_t)bi << 4) + q] =
            __ldg((const float4*)a.imp + ((size_t)__ldg(a.eid + bi) << 4) + q);
    }
}

// ---------------- TF32 tensor-core big GEMM (128x128 tile, cp.async 2-stage) ----------------
#define SMPAD 36
#define STAGE_W (3 * 128 * SMPAD)
#define GEMM_SMEM_BYTES (2 * STAGE_W * 4)

__device__ __forceinline__ void cp16(uint32_t dst, const void* src) {
    asm volatile("cp.async.cg.shared.global [%0], [%1], 16;" :: "r"(dst), "l"(src));
}

__device__ __forceinline__ void load_stage(uint32_t sbase, const uint32_t* A1, const uint32_t* A2,
                                           const uint32_t* B32, int m0, int n0, int kc, int tid) {
    #pragma unroll
    for (int i = 0; i < 4; i++) {
        int idx = tid + i * 256;
        int row = idx >> 3, q = idx & 7;
        uint32_t off = (uint32_t)(row * SMPAD + q * 4) * 4;
        cp16(sbase + off,                       A1 + (size_t)(m0 + row) * 128 + kc + q * 4);
        cp16(sbase + 128 * SMPAD * 4 + off,     A2 + (size_t)(m0 + row) * 128 + kc + q * 4);
        cp16(sbase + 2 * 128 * SMPAD * 4 + off, B32 + (size_t)(n0 + row) * 128 + kc + q * 4);
    }
    asm volatile("cp.async.commit_group;");
}

__global__ void __launch_bounds__(256, 1) big_gemm_tf32_dual(
    const uint32_t* __restrict__ A1, const uint32_t* __restrict__ A2,
    const uint32_t* __restrict__ B32, float* __restrict__ O1, float* __restrict__ O2) {
    extern __shared__ uint32_t sm[];
    uint32_t sbase = (uint32_t)__cvta_generic_to_shared(sm);

    int tid = threadIdx.x;
    int warp = tid >> 5;
    int lane = tid & 31;
    int g = lane >> 2;
    int tg = lane & 3;
    int wm = warp >> 1;
    int wn = warp & 1;
    int m0 = blockIdx.x * 128;
    int n0 = blockIdx.y * 128;

    float acc1[2][8][4] = {};
    float acc2[2][8][4] = {};

    load_stage(sbase, A1, A2, B32, m0, n0, 0, tid);

    #pragma unroll
    for (int c = 0; c < 4; c++) {
        if (c < 3) {
            load_stage(sbase + ((c + 1) & 1) * STAGE_W * 4, A1, A2, B32, m0, n0, (c + 1) * 32, tid);
            asm volatile("cp.async.wait_group 1;");
        } else {
            asm volatile("cp.async.wait_group 0;");
        }
        __syncthreads();
        const uint32_t* As1 = sm + (c & 1) * STAGE_W;
        const uint32_t* As2 = As1 + 128 * SMPAD;
        const uint32_t* Bs  = As2 + 128 * SMPAD;

        #pragma unroll
        for (int ks = 0; ks < 4; ks++) {
            int k0 = ks * 8;
            uint32_t b[8][2];
            #pragma unroll
            for (int nt = 0; nt < 8; nt++) {
                const uint32_t* bp = &Bs[(wn * 64 + nt * 8 + g) * SMPAD + k0 + tg];
                b[nt][0] = bp[0];
                b[nt][1] = bp[4];
            }
            #pragma unroll
            for (int mt = 0; mt < 2; mt++) {
                uint32_t a[4];
                const uint32_t* ap = &As1[(wm * 32 + mt * 16 + g) * SMPAD + k0 + tg];
                a[0] = ap[0]; a[1] = ap[8 * SMPAD]; a[2] = ap[4]; a[3] = ap[8 * SMPAD + 4];
                #pragma unroll
                for (int nt = 0; nt < 8; nt++) MMA_TF32(acc1[mt][nt], a, b[nt]);
                ap = &As2[(wm * 32 + mt * 16 + g) * SMPAD + k0 + tg];
                a[0] = ap[0]; a[1] = ap[8 * SMPAD]; a[2] = ap[4]; a[3] = ap[8 * SMPAD + 4];
                #pragma unroll
                for (int nt = 0; nt < 8; nt++) MMA_TF32(acc2[mt][nt], a, b[nt]);
            }
        }
        __syncthreads();
    }

    #pragma unroll
    for (int mt = 0; mt < 2; mt++) {
        #pragma unroll
        for (int nt = 0; nt < 8; nt++) {
            int col = n0 + wn * 64 + nt * 8 + tg * 2;
            if (col >= K_N) continue;
            size_t r0 = (size_t)(m0 + wm * 32 + mt * 16 + g);
            size_t r1 = r0 + 8;
            *(float2*)(O1 + r0 * K_N + col) = make_float2(acc1[mt][nt][0], acc1[mt][nt][1]);
            *(float2*)(O1 + r1 * K_N + col) = make_float2(acc1[mt][nt][2], acc1[mt][nt][3]);
            *(float2*)(O2 + r0 * K_N + col) = make_float2(acc2[mt][nt][0], acc2[mt][nt][1]);
            *(float2*)(O2 + r1 * K_N + col) = make_float2(acc2[mt][nt][2], acc2[mt][nt][3]);
        }
    }
}

// ---------------- host orchestration ----------------
extern "C" void kernel_launch(void* const* d_in, const int* in_sizes, int n_in,
                              void* d_out, int out_size) {
    (void)in_sizes; (void)n_in; (void)out_size;
    const int*   student_id  = (const int*)d_in[0];
    const int*   exercise_id = (const int*)d_in[1];
    const float* stu_emb     = (const float*)d_in[3];
    const float* exer_emb    = (const float*)d_in[4];
    const float* know_emb    = (const float*)d_in[5];
    const float* impact_emb  = (const float*)d_in[6];
    const int*   s_rows = (const int*)d_in[7];
    const int*   s_cols = (const int*)d_in[8];
    const float* s_vals = (const float*)d_in[9];
    const int*   e_rows = (const int*)d_in[10];
    const int*   e_cols = (const int*)d_in[11];
    const float* e_vals = (const float*)d_in[12];
    const int*   k_rows = (const int*)d_in[13];
    const int*   k_cols = (const int*)d_in[14];
    const float* k_vals = (const float*)d_in[15];
    const float* W_stu  = (const float*)d_in[16];
    const float* b_stu  = (const float*)d_in[17];
    const float* W_exer = (const float*)d_in[18];
    const float* b_exer = (const float*)d_in[19];
    const float* W_know = (const float*)d_in[20];
    const float* b_know = (const float*)d_in[21];
    const float* W_disc = (const float*)d_in[22];
    const float* b_disc = (const float*)d_in[23];

    unsigned char* A = nullptr;
    cudaGetSymbolAddress((void**)&A, g_arena);

    int*  rp_s  = (int*)(A + O_RP_S);
    int*  rp_e  = (int*)(A + O_RP_E);
    int*  rp_k  = (int*)(A + O_RP_K);
    unsigned long long* lk = (unsigned long long*)(A + O_LK);
    int*  cur_s = (int*)(A + O_CUR_S);
    int*  cur_e = (int*)(A + O_CUR_E);
    int*  cur_k = (int*)(A + O_CUR_K);
    int2* pairs_s = (int2*)(A + O_PAIRS_S);
    int2* pairs_e = (int2*)(A + O_PAIRS_E);
    int2* pairs_k = (int2*)(A + O_PAIRS_K);
    float* x1_s = (float*)(A + O_X1_S);
    float* x2_s = (float*)(A + O_X2_S);
    float* x1_e = (float*)(A + O_X1_E);
    float* x2_e = (float*)(A + O_X2_E);
    float* x1_k = (float*)(A + O_X1_K);
    float* x2_k = (float*)(A + O_X2_K);
    float* x3_k = (float*)(A + O_X3_K);
    float* xg_s = (float*)(A + O_XG_S);
    float* xg_e = (float*)(A + O_XG_E);
    uint32_t* A1 = (uint32_t*)(A + O_A1);
    uint32_t* A2 = (uint32_t*)(A + O_A2);
    uint32_t* Bt32 = (uint32_t*)(A + O_BT32);

    // 1) CSR build
    zero_kernel<<<(ZERO_INTS + BT_PAD_WORDS + 1023) / 1024, 1024>>>(
        (int*)A, Bt32 + (size_t)K_N * 128);
    hist_all_kernel<<<(Q4_TOT + 255) / 256, 256>>>(
        (const int4*)s_rows, (const int4*)e_rows, (const int4*)k_rows, rp_s, rp_e, rp_k);
    scan_lookback_kernel<<<NB_TOT, 256>>>(rp_s, rp_e, rp_k, cur_s, cur_e, cur_k, lk);
    scatter_all_kernel<<<(Q4_TOT + 255) / 256, 256>>>(
        (const int4*)s_rows, (const int4*)s_cols, (const float4*)s_vals,
        (const int4*)e_rows, (const int4*)e_cols, (const float4*)e_vals,
        (const int4*)k_rows, (const int4*)k_cols, (const float4*)k_vals,
        cur_s, cur_e, cur_k, pairs_s, pairs_e, pairs_k);

    // 2) layers 1-2 full; layer 3 batch-restricted + full know
    const float* in_s[3] = {stu_emb, x1_s, x2_s};
    const float* in_e[3] = {exer_emb, x1_e, x2_e};
    const float* in_k[3] = {know_emb, x1_k, x2_k};
    for (int l = 0; l < 2; l++) {
        SpmmArgs sa;
        sa.rp[0] = rp_s;  sa.rp[1] = rp_e;  sa.rp[2] = rp_k;
        sa.pr[0] = pairs_s; sa.pr[1] = pairs_e; sa.pr[2] = pairs_k;
        sa.xin[0] = (const float4*)in_s[l]; sa.xin[1] = (const float4*)in_e[l]; sa.xin[2] = (const float4*)in_k[l];
        sa.xout[0] = (float4*)in_s[l + 1];  sa.xout[1] = (float4*)in_e[l + 1];  sa.xout[2] = (float4*)in_k[l + 1];
        sa.nrows[0] = S_N; sa.nrows[1] = E_N; sa.nrows[2] = K_N;
        spmm_all_kernel<<<GB_S + GB_E + GB_K, 256>>>(sa);
    }
    {
        Spmm3Args a3;
        a3.rp_s = rp_s; a3.pr_s = pairs_s; a3.x2_s = (const float4*)x2_s; a3.xg_s = (float4*)xg_s; a3.sid = student_id;
        a3.rp_e = rp_e; a3.pr_e = pairs_e; a3.x2_e = (const float4*)x2_e; a3.xg_e = (float4*)xg_e; a3.eid = exercise_id;
        a3.rp_k = rp_k; a3.pr_k = pairs_k; a3.x2_k = (const float4*)x2_k; a3.x3_k = (float4*)x3_k;
        spmm_l3_kernel<<<GL_S + GL_E + GL_K, 256>>>(a3);
    }

    // 3) output layout
    float* out   = (float*)d_out;
    float* O1    = out;
    float* O2    = O1 + (size_t)B_N * K_N;
    float* Odisc = O2 + (size_t)B_N * K_N;
    float* Okt   = Odisc + B_N;
    float* Oimp  = Okt + (size_t)K_N * FF;

    // 4) dense: tensor-core path for stu/exer (incl. disc), FFMA path for know + impact
    static bool attr_set = false;
    if (!attr_set) {
        cudaFuncSetAttribute(dense_mma_kernel,
                             cudaFuncAttributeMaxDynamicSharedMemorySize, DM_SMEM_BYTES);
        cudaFuncSetAttribute(big_gemm_tf32_dual,
                             cudaFuncAttributeMaxDynamicSharedMemorySize, GEMM_SMEM_BYTES);
        attr_set = true;
    }
    {
        DenseMmaArgs dm;
        dm.x0s = stu_emb;  dm.x1s = x1_s; dm.x2s = x2_s; dm.x3s = xg_s;
        dm.x0e = exer_emb; dm.x1e = x1_e; dm.x2e = x2_e; dm.x3e = xg_e;
        dm.sid = student_id; dm.eid = exercise_id;
        dm.Ws = W_stu; dm.bs = b_stu; dm.We = W_exer; dm.be = b_exer;
        dm.Wd = W_disc; dm.bd = b_disc;
        dm.A1 = A1; dm.A2 = A2; dm.Odisc = Odisc;
        dense_mma_kernel<<<512, 256, DM_SMEM_BYTES>>>(dm);
    }
    {
        DenseArgs da;
        da.xk0 = know_emb; da.xk1 = x1_k; da.xk2 = x2_k; da.xk3 = x3_k;
        da.eid = exercise_id;
        da.Wk = W_know; da.bk = b_know;
        da.imp = impact_emb;
        da.Okt = Okt; da.Oimp = Oimp; da.Bt32 = Bt32;
        dense_all_kernel<<<G_DENSE, 256>>>(da);
    }

    // 5) TF32 big GEMM pair
    dim3 grid(B_N / 128, 1024 / 128);
    big_gemm_tf32_dual<<<grid, 256, GEMM_SMEM_BYTES>>>(A1, A2, Bt32, O1, O2);
}

// round 9
// speedup vs baseline: 1.1890x; 1.0146x over previous
#include <cuda_runtime.h>
#include <cstdint>
#include <cstddef>

#define S_N 100000
#define E_N 30000
#define K_N 1000
#define DD 64
#define FF 128
#define B_N 16384
#define NNZ_S 1600000
#define NNZ_E 480000
#define NNZ_K 32000
#define NNZ_TOT (NNZ_S + NNZ_E + NNZ_K)
#define MOM 0.9f
#define LEAK_F 0.1f

#define NB_S 98
#define NB_E 30
#define NB_K 1
#define NB_TOT (NB_S + NB_E + NB_K)

static constexpr size_t al256(size_t x) { return (x + 255) & ~(size_t)255; }

// ---------------- static scratch arena ----------------
static constexpr size_t O_RP_S = 0;
static constexpr size_t O_RP_E = O_RP_S + (size_t)(S_N + 1) * 4;
static constexpr size_t O_RP_K = O_RP_E + (size_t)(E_N + 1) * 4;
static constexpr size_t RP_END = O_RP_K + (size_t)(K_N + 1) * 4;
static constexpr size_t O_LK   = al256(RP_END);
static constexpr size_t LK_END = O_LK + (size_t)NB_TOT * 8;
static constexpr int    ZERO_INTS = (int)(LK_END / 4);

static constexpr size_t O_CUR_S = al256(LK_END);
static constexpr size_t O_CUR_E = al256(O_CUR_S + (size_t)S_N * 4);
static constexpr size_t O_CUR_K = al256(O_CUR_E + (size_t)E_N * 4);
static constexpr size_t O_LOC   = al256(O_CUR_K + (size_t)K_N * 4);   // per-nnz within-row rank
static constexpr size_t O_PAIRS_S = al256(O_LOC + (size_t)NNZ_TOT * 4);
static constexpr size_t O_PAIRS_E = al256(O_PAIRS_S + (size_t)NNZ_S * 8);
static constexpr size_t O_PAIRS_K = al256(O_PAIRS_E + (size_t)NNZ_E * 8);
static constexpr size_t O_X1_S = al256(O_PAIRS_K + (size_t)NNZ_K * 8);
static constexpr size_t O_X2_S = al256(O_X1_S + (size_t)S_N * DD * 4);
static constexpr size_t O_X1_E = al256(O_X2_S + (size_t)S_N * DD * 4);
static constexpr size_t O_X2_E = al256(O_X1_E + (size_t)E_N * DD * 4);
static constexpr size_t O_X1_K = al256(O_X2_E + (size_t)E_N * DD * 4);
static constexpr size_t O_X2_K = al256(O_X1_K + (size_t)K_N * DD * 4);
static constexpr size_t O_X3_K = al256(O_X2_K + (size_t)K_N * DD * 4);
static constexpr size_t O_XG_S = al256(O_X3_K + (size_t)K_N * DD * 4);
static constexpr size_t O_XG_E = al256(O_XG_S + (size_t)B_N * DD * 4);
static constexpr size_t O_A1   = al256(O_XG_E + (size_t)B_N * DD * 4);
static constexpr size_t O_A2   = al256(O_A1 + (size_t)B_N * FF * 4);
static constexpr size_t O_BT32 = al256(O_A2 + (size_t)B_N * FF * 4);
static constexpr size_t ARENA_BYTES = al256(O_BT32 + (size_t)1024 * FF * 4);

__device__ __align__(256) unsigned char g_arena[ARENA_BYTES];

// ---------------- zero (rowptrs + lookback states + Bt32 pad) ----------------
#define BT_PAD_WORDS (24 * 128)
__global__ void zero_kernel(int* p, uint32_t* bt_pad) {
    int i = blockIdx.x * blockDim.x + threadIdx.x;
    if (i < ZERO_INTS) p[i] = 0;
    else if (i < ZERO_INTS + BT_PAD_WORDS) bt_pad[i - ZERO_INTS] = 0u;
}

// ---------------- histogram (x4 vectorized, emits within-row ranks) ----------------
#define Q4_S (NNZ_S / 4)
#define Q4_E (NNZ_E / 4)
#define Q4_K (NNZ_K / 4)
#define Q4_TOT (Q4_S + Q4_E + Q4_K)

__global__ void hist_all_kernel(const int4* __restrict__ s_rows, const int4* __restrict__ e_rows,
                                const int4* __restrict__ k_rows, int* __restrict__ rp_s,
                                int* __restrict__ rp_e, int* __restrict__ rp_k,
                                int4* __restrict__ loc) {
    int i = blockIdx.x * blockDim.x + threadIdx.x;
    int4 r; int* rp;
    if (i < Q4_S)             { r = __ldg(s_rows + i); rp = rp_s; }
    else if (i < Q4_S + Q4_E) { r = __ldg(e_rows + (i - Q4_S)); rp = rp_e; }
    else if (i < Q4_TOT)      { r = __ldg(k_rows + (i - Q4_S - Q4_E)); rp = rp_k; }
    else return;
    int4 l;
    l.x = atomicAdd(&rp[r.x + 1], 1);
    l.y = atomicAdd(&rp[r.y + 1], 1);
    l.z = atomicAdd(&rp[r.z + 1], 1);
    l.w = atomicAdd(&rp[r.w + 1], 1);
    loc[i] = l;
}

// ---------------- single-pass decoupled-lookback scan ----------------
__global__ void __launch_bounds__(256) scan_lookback_kernel(
    int* __restrict__ rp_s, int* __restrict__ rp_e, int* __restrict__ rp_k,
    int* __restrict__ cur_s, int* __restrict__ cur_e, int* __restrict__ cur_k,
    unsigned long long* __restrict__ lk) {
    __shared__ int wsum[8];
    __shared__ int s_excl;
    const unsigned FULL = 0xFFFFFFFFu;
    int b = blockIdx.x, t = threadIdx.x, lane = t & 31, wid = t >> 5;
    int *x, *c, n, lb;
    if (b < NB_S)             { x = rp_s; c = cur_s; n = S_N + 1; lb = b; }
    else if (b < NB_S + NB_E) { x = rp_e; c = cur_e; n = E_N + 1; lb = b - NB_S; }
    else                      { x = rp_k; c = cur_k; n = K_N + 1; lb = b - NB_S - NB_E; }
    int base = lb * 1024 + t * 4;
    int v0 = (base     < n) ? x[base]     : 0;
    int v1 = (base + 1 < n) ? x[base + 1] : 0;
    int v2 = (base + 2 < n) ? x[base + 2] : 0;
    int v3 = (base + 3 < n) ? x[base + 3] : 0;
    v1 += v0; v2 += v1; v3 += v2;
    int tin = v3;
    int incl = tin;
    #pragma unroll
    for (int off = 1; off < 32; off <<= 1) {
        int o = __shfl_up_sync(FULL, incl, off);
        if (lane >= off) incl += o;
    }
    if (lane == 31) wsum[wid] = incl;
    __syncthreads();
    if (wid == 0) {
        int ws = (lane < 8) ? wsum[lane] : 0;
        #pragma unroll
        for (int off = 1; off < 8; off <<= 1) {
            int o = __shfl_up_sync(FULL, ws, off);
            if (lane >= off) ws += o;
        }
        if (lane < 8) wsum[lane] = ws;
    }
    __syncthreads();
    int agg = wsum[7];
    int warp_excl = wid ? wsum[wid - 1] : 0;
    int thread_excl = warp_excl + (incl - tin);

    if (wid == 0) {
        volatile unsigned long long* vlk = (volatile unsigned long long*)lk;
        if (lb == 0) {
            if (lane == 0) { vlk[b] = (2ULL << 32) | (unsigned)agg; s_excl = 0; }
        } else {
            if (lane == 0) vlk[b] = (1ULL << 32) | (unsigned)agg;
            int gbase = b - lb;
            int running = 0;
            int j = lb - 1;
            while (true) {
                int idx = j - lane;
                bool valid = idx >= 0;
                unsigned long long w = 0; int st = 0;
                while (true) {
                    if (valid) { w = vlk[gbase + idx]; st = (int)(w >> 32); }
                    if (__all_sync(FULL, !valid || st != 0)) break;
                }
                unsigned pm = __ballot_sync(FULL, valid && st == 2);
                int lane_p = pm ? (__ffs(pm) - 1) : 32;
                int val = (valid && lane <= lane_p) ? (int)(unsigned)w : 0;
                #pragma unroll
                for (int off = 16; off; off >>= 1) val += __shfl_xor_sync(FULL, val, off);
                running += val;
                if (lane_p < 32) break;
                j -= 32;
            }
            if (lane == 0) {
                vlk[b] = (2ULL << 32) | (unsigned)(running + agg);
                s_excl = running;
            }
        }
    }
    __syncthreads();
    int off0 = s_excl + thread_excl;
    if (base < n)     { int val = v0 + off0; x[base]     = val; if (base     < n - 1) c[base]     = val; }
    if (base + 1 < n) { int val = v1 + off0; x[base + 1] = val; if (base + 1 < n - 1) c[base + 1] = val; }
    if (base + 2 < n) { int val = v2 + off0; x[base + 2] = val; if (base + 2 < n - 1) c[base + 2] = val; }
    if (base + 3 < n) { int val = v3 + off0; x[base + 3] = val; if (base + 3 < n - 1) c[base + 3] = val; }
}

// ---------------- scatter (atomic-free: pos = rowstart + rank) ----------------
__global__ void scatter_all_kernel(
    const int4* __restrict__ s_rows, const int4* __restrict__ s_cols, const float4* __restrict__ s_vals,
    const int4* __restrict__ e_rows, const int4* __restrict__ e_cols, const float4* __restrict__ e_vals,
    const int4* __restrict__ k_rows, const int4* __restrict__ k_cols, const float4* __restrict__ k_vals,
    const int* __restrict__ cur_s, const int* __restrict__ cur_e, const int* __restrict__ cur_k,
    const int4* __restrict__ loc,
    int2* __restrict__ pairs_s, int2* __restrict__ pairs_e, int2* __restrict__ pairs_k) {
    int i = blockIdx.x * blockDim.x + threadIdx.x;
    int4 r, cidx; float4 v; const int* cur; int2* pairs;
    if (i < Q4_S) {
        r = __ldg(s_rows + i); cidx = __ldg(s_cols + i); v = __ldg(s_vals + i);
        cur = cur_s; pairs = pairs_s;
    } else if (i < Q4_S + Q4_E) {
        int j = i - Q4_S;
        r = __ldg(e_rows + j); cidx = __ldg(e_cols + j); v = __ldg(e_vals + j);
        cur = cur_e; pairs = pairs_e;
    } else if (i < Q4_TOT) {
        int j = i - Q4_S - Q4_E;
        r = __ldg(k_rows + j); cidx = __ldg(k_cols + j); v = __ldg(k_vals + j);
        cur = cur_k; pairs = pairs_k;
    } else return;
    int4 l = __ldg(loc + i);
    pairs[__ldg(cur + r.x) + l.x] = make_int2(cidx.x, __float_as_int(v.x));
    pairs[__ldg(cur + r.y) + l.y] = make_int2(cidx.y, __float_as_int(v.y));
    pairs[__ldg(cur + r.z) + l.z] = make_int2(cidx.z, __float_as_int(v.z));
    pairs[__ldg(cur + r.w) + l.w] = make_int2(cidx.w, __float_as_int(v.w));
}

// ---------------- SpMM core ----------------
__device__ __forceinline__ float4 spmm_row(const int* __restrict__ rowptr,
                                           const int2* __restrict__ pairs,
                                           const float4* __restrict__ xin, int row, int d4) {
    int beg = __ldg(rowptr + row);
    int end = __ldg(rowptr + row + 1);
    float4 s = make_float4(0.f, 0.f, 0.f, 0.f);
    int j = beg;
    for (; j + 3 < end; j += 4) {
        int2 p0 = __ldg(pairs + j);
        int2 p1 = __ldg(pairs + j + 1);
        int2 p2 = __ldg(pairs + j + 2);
        int2 p3 = __ldg(pairs + j + 3);
        float4 v0 = __ldg(xin + ((size_t)p0.x << 4) + d4);
        float4 v1 = __ldg(xin + ((size_t)p1.x << 4) + d4);
        float4 v2 = __ldg(xin + ((size_t)p2.x << 4) + d4);
        float4 v3 = __ldg(xin + ((size_t)p3.x << 4) + d4);
        float w0 = __int_as_float(p0.y), w1 = __int_as_float(p1.y);
        float w2 = __int_as_float(p2.y), w3 = __int_as_float(p3.y);
        s.x = fmaf(w0, v0.x, s.x); s.y = fmaf(w0, v0.y, s.y); s.z = fmaf(w0, v0.z, s.z); s.w = fmaf(w0, v0.w, s.w);
        s.x = fmaf(w1, v1.x, s.x); s.y = fmaf(w1, v1.y, s.y); s.z = fmaf(w1, v1.z, s.z); s.w = fmaf(w1, v1.w, s.w);
        s.x = fmaf(w2, v2.x, s.x); s.y = fmaf(w2, v2.y, s.y); s.z = fmaf(w2, v2.z, s.z); s.w = fmaf(w2, v2.w, s.w);
        s.x = fmaf(w3, v3.x, s.x); s.y = fmaf(w3, v3.y, s.y); s.z = fmaf(w3, v3.z, s.z); s.w = fmaf(w3, v3.w, s.w);
    }
    for (; j < end; j++) {
        int2 p = __ldg(pairs + j);
        float w = __int_as_float(p.y);
        float4 v = __ldg(xin + ((size_t)p.x << 4) + d4);
        s.x = fmaf(w, v.x, s.x); s.y = fmaf(w, v.y, s.y); s.z = fmaf(w, v.z, s.z); s.w = fmaf(w, v.w, s.w);
    }
    return s;
}

#define GB_S 6250
#define GB_E 1875
#define GB_K 63

struct SpmmArgs {
    const int* rp[3];
    const int2* pr[3];
    const float4* xin[3];
    float4* xout[3];
    int nrows[3];
};

__global__ void __launch_bounds__(256) spmm_all_kernel(SpmmArgs a) {
    int b = blockIdx.x;
    int seg, lb;
    if (b < GB_S)             { seg = 0; lb = b; }
    else if (b < GB_S + GB_E) { seg = 1; lb = b - GB_S; }
    else                      { seg = 2; lb = b - GB_S - GB_E; }
    int row = lb * 16 + (threadIdx.x >> 4);
    int d4 = threadIdx.x & 15;
    if (row >= a.nrows[seg]) return;
    const float4* xin = a.xin[seg];
    float4 s = spmm_row(a.rp[seg], a.pr[seg], xin, row, d4);
    size_t o = ((size_t)row << 4) + d4;
    float4 m = xin[o];
    s.x += MOM * m.x; s.y += MOM * m.y; s.z += MOM * m.z; s.w += MOM * m.w;
    a.xout[seg][o] = s;
}

// ---------------- layer 3: batch-restricted stu/exer + full know ----------------
#define GL_S 1024
#define GL_E 1024
#define GL_K 63

struct Spmm3Args {
    const int* rp_s; const int2* pr_s; const float4* x2_s; float4* xg_s; const int* sid;
    const int* rp_e; const int2* pr_e; const float4* x2_e; float4* xg_e; const int* eid;
    const int* rp_k; const int2* pr_k; const float4* x2_k; float4* x3_k;
};

__global__ void __launch_bounds__(256) spmm_l3_kernel(Spmm3Args a) {
    int b = blockIdx.x;
    int d4 = threadIdx.x & 15;
    int lr = (threadIdx.x >> 4);
    if (b < GL_S) {
        int r = b * 16 + lr;
        int row = __ldg(a.sid + r);
        float4 s = spmm_row(a.rp_s, a.pr_s, a.x2_s, row, d4);
        float4 m = a.x2_s[((size_t)row << 4) + d4];
        s.x += MOM * m.x; s.y += MOM * m.y; s.z += MOM * m.z; s.w += MOM * m.w;
        a.xg_s[((size_t)r << 4) + d4] = s;
    } else if (b < GL_S + GL_E) {
        int r = (b - GL_S) * 16 + lr;
        int row = __ldg(a.eid + r);
        float4 s = spmm_row(a.rp_e, a.pr_e, a.x2_e, row, d4);
        float4 m = a.x2_e[((size_t)row << 4) + d4];
        s.x += MOM * m.x; s.y += MOM * m.y; s.z += MOM * m.z; s.w += MOM * m.w;
        a.xg_e[((size_t)r << 4) + d4] = s;
    } else {
        int row = (b - GL_S - GL_E) * 16 + lr;
        if (row >= K_N) return;
        float4 s = spmm_row(a.rp_k, a.pr_k, a.x2_k, row, d4);
        float4 m = a.x2_k[((size_t)row << 4) + d4];
        s.x += MOM * m.x; s.y += MOM * m.y; s.z += MOM * m.z; s.w += MOM * m.w;
        a.x3_k[((size_t)row << 4) + d4] = s;
    }
}

// ---------------- tf32 helpers / MMA macro ----------------
__device__ __forceinline__ uint32_t f2tf32(float f) {
    uint32_t u;
    asm("cvt.rna.tf32.f32 %0, %1;" : "=r"(u) : "f"(f));
    return u;
}

#define MMA_TF32(d, a, b)                                                     \
    asm volatile(                                                             \
        "mma.sync.aligned.m16n8k8.row.col.f32.tf32.tf32.f32 "                 \
        "{%0,%1,%2,%3}, {%4,%5,%6,%7}, {%8,%9}, {%0,%1,%2,%3};\n"             \
        : "+f"(d[0]), "+f"(d[1]), "+f"(d[2]), "+f"(d[3])                      \
        : "r"(a[0]), "r"(a[1]), "r"(a[2]), "r"(a[3]), "r"(b[0]), "r"(b[1]))

// ---------------- unified dense stage ----------------
// grid = 512 (mma stu/exer) + 125 (know FFMA) + 1024 (impact gather)
#define XS_STRIDE 68
#define WT_STRIDE 68
#define DM_XS_W   (64 * XS_STRIDE)
#define DM_WT_W   (128 * WT_STRIDE)
#define DM_SMEM_BYTES ((DM_XS_W + DM_WT_W + 128 + 64) * 4)
#define G_MMA 512
#define G_KNO 125
#define G_IMP 1024
#define G_DENSE (G_MMA + G_KNO + G_IMP)

struct DenseArgs {
    const float *x0s, *x1s, *x2s, *x3s;   // x3s compact [B_N,64]
    const float *x0e, *x1e, *x2e, *x3e;   // x3e compact
    const float *xk0, *xk1, *xk2, *xk3;
    const int *sid, *eid;
    const float *Ws, *bs, *We, *be, *Wk, *bk, *Wd, *bd;
    const float *imp;
    uint32_t *A1, *A2, *Bt32;
    float *Okt, *Odisc, *Oimp;
};

__global__ void __launch_bounds__(256) dense_all_kernel(DenseArgs a) {
    extern __shared__ uint32_t dsm[];
    const unsigned FULL = 0xFFFFFFFFu;
    int b = blockIdx.x, tid = threadIdx.x;

    if (b < G_MMA) {
        uint32_t* Xs = dsm;
        uint32_t* Wt = dsm + DM_XS_W;
        float* bsm = (float*)(dsm + DM_XS_W + DM_WT_W);
        float* wd  = bsm + 128;
        bool is_e = b >= 256;
        int r0 = (is_e ? b - 256 : b) * 64;
        const float* x0 = is_e ? a.x0e : a.x0s;
        const float* x1 = is_e ? a.x1e : a.x1s;
        const float* x2 = is_e ? a.x2e : a.x2s;
        const float* x3 = is_e ? a.x3e : a.x3s;
        const int* ids  = is_e ? a.eid : a.sid;
        const float* W  = is_e ? a.We : a.Ws;
        const float* bias = is_e ? a.be : a.bs;
        uint32_t* out = is_e ? a.A2 : a.A1;

        for (int i = tid; i < 8192; i += 256) {
            int k = i >> 7, n = i & 127;
            Wt[n * WT_STRIDE + k] = f2tf32(__ldg(W + i));
        }
        if (tid < 128) bsm[tid] = __ldg(bias + tid);
        if (is_e && tid < 64) wd[tid] = __ldg(a.Wd + tid);

        for (int i = tid; i < 1024; i += 256) {
            int rr = i >> 4, c4 = i & 15;
            int r = r0 + rr;
            int rid = __ldg(ids + r);
            size_t o  = ((size_t)rid << 4) + c4;
            size_t o3 = ((size_t)r << 4) + c4;
            float4 a0 = __ldg((const float4*)x0 + o);
            float4 a1 = __ldg((const float4*)x1 + o);
            float4 a2 = __ldg((const float4*)x2 + o);
            float4 a3 = __ldg((const float4*)x3 + o3);
            uint4 w;
            w.x = f2tf32(0.25f * (a0.x + a1.x + a2.x + a3.x));
            w.y = f2tf32(0.25f * (a0.y + a1.y + a2.y + a3.y));
            w.z = f2tf32(0.25f * (a0.z + a1.z + a2.z + a3.z));
            w.w = f2tf32(0.25f * (a0.w + a1.w + a2.w + a3.w));
            *(uint4*)&Xs[rr * XS_STRIDE + c4 * 4] = w;
        }
        __syncthreads();

        int warp = tid >> 5, lane = tid & 31, g = lane >> 2, tg = lane & 3;
        int wm = warp >> 1;
        int wn = warp & 1;
        float acc[8][4] = {};
        #pragma unroll
        for (int ks = 0; ks < 8; ks++) {
            int k0 = ks * 8;
            uint32_t A[4];
            const uint32_t* ap = &Xs[(wm * 16 + g) * XS_STRIDE + k0 + tg];
            A[0] = ap[0]; A[1] = ap[8 * XS_STRIDE]; A[2] = ap[4]; A[3] = ap[8 * XS_STRIDE + 4];
            #pragma unroll
            for (int nt = 0; nt < 8; nt++) {
                const uint32_t* bp = &Wt[(wn * 64 + nt * 8 + g) * WT_STRIDE + k0 + tg];
                uint32_t B[2] = {bp[0], bp[4]};
                MMA_TF32(acc[nt], A, B);
            }
        }

        #pragma unroll
        for (int nt = 0; nt < 8; nt++) {
            int col = wn * 64 + nt * 8 + tg * 2;
            float b0 = bsm[col], b1 = bsm[col + 1];
            size_t rA = (size_t)(r0 + wm * 16 + g);
            size_t rB = rA + 8;
            float v0 = acc[nt][0] + b0; v0 = (v0 > 0.f) ? v0 : LEAK_F * v0;
            float v1 = acc[nt][1] + b1; v1 = (v1 > 0.f) ? v1 : LEAK_F * v1;
            float v2 = acc[nt][2] + b0; v2 = (v2 > 0.f) ? v2 : LEAK_F * v2;
            float v3 = acc[nt][3] + b1; v3 = (v3 > 0.f) ? v3 : LEAK_F * v3;
            *(uint2*)(out + rA * 128 + col) = make_uint2(f2tf32(v0), f2tf32(v1));
            *(uint2*)(out + rB * 128 + col) = make_uint2(f2tf32(v2), f2tf32(v3));
        }

        if (is_e) {
            int row = tid >> 2, part = tid & 3;
            float s = 0.f;
            #pragma unroll
            for (int i = 0; i < 16; i++)
                s += __uint_as_float(Xs[row * XS_STRIDE + part * 16 + i]) * wd[part * 16 + i];
            s += __shfl_xor_sync(FULL, s, 1);
            s += __shfl_xor_sync(FULL, s, 2);
            if (part == 0) a.Odisc[r0 + row] = 1.f / (1.f + __expf(-(s + __ldg(a.bd))));
        }
    } else if (b < G_MMA + G_KNO) {
        float* Ws = (float*)dsm;              // 8192 floats
        float* Xs = Ws + 8192;                // 8*64 floats
        int r0 = (b - G_MMA) * 8;
        const float4* W4 = (const float4*)a.Wk;
        float4* Ws4 = (float4*)Ws;
        #pragma unroll
        for (int i = 0; i < 8; i++) Ws4[tid + i * 256] = W4[tid + i * 256];
        if (tid < 128) {
            int rr = tid >> 4;
            int c4 = tid & 15;
            int r = r0 + rr;
            float4 v = make_float4(0.f, 0.f, 0.f, 0.f);
            if (r < K_N) {
                size_t o = ((size_t)r << 4) + c4;
                float4 a0 = __ldg((const float4*)a.xk0 + o);
                float4 a1 = __ldg((const float4*)a.xk1 + o);
                float4 a2 = __ldg((const float4*)a.xk2 + o);
                float4 a3 = __ldg((const float4*)a.xk3 + o);
                v.x = 0.25f * (a0.x + a1.x + a2.x + a3.x);
                v.y = 0.25f * (a0.y + a1.y + a2.y + a3.y);
                v.z = 0.25f * (a0.z + a1.z + a2.z + a3.z);
                v.w = 0.25f * (a0.w + a1.w + a2.w + a3.w);
            }
            ((float4*)&Xs[rr * 64])[c4] = v;
        }
        __syncthreads();
        int col = tid & 127;
        int rbase = tid >> 7;
        float bv = __ldg(a.bk + col);
        #pragma unroll
        for (int rr = 0; rr < 4; rr++) {
            int lrow = rr * 2 + rbase;
            int r = r0 + lrow;
            if (r >= K_N) continue;
            float acc = bv;
            #pragma unroll
            for (int i = 0; i < 64; i++) acc = fmaf(Xs[lrow * 64 + i], Ws[i * 128 + col], acc);
            float rv = (acc > 0.f) ? acc : LEAK_F * acc;
            a.Okt[(size_t)r * 128 + col] = rv;
            a.Bt32[(size_t)r * 128 + col] = f2tf32(rv);
        }
    } else {
        int t = (b - G_MMA - G_KNO) * 256 + tid;
        int bi = t >> 4, q = t & 15;
        ((float4*)a.Oimp)[((size_t)bi << 4) + q] =
            __ldg((const float4*)a.imp + ((size_t)__ldg(a.eid + bi) << 4) + q);
    }
}

// ---------------- TF32 tensor-core big GEMM (128x128 tile, cp.async 2-stage) ----------------
#define SMPAD 36
#define STAGE_W (3 * 128 * SMPAD)
#define GEMM_SMEM_BYTES (2 * STAGE_W * 4)

__device__ __forceinline__ void cp16(uint32_t dst, const void* src) {
    asm volatile("cp.async.cg.shared.global [%0], [%1], 16;" :: "r"(dst), "l"(src));
}

__device__ __forceinline__ void load_stage(uint32_t sbase, const uint32_t* A1, const uint32_t* A2,
                                           const uint32_t* B32, int m0, int n0, int kc, int tid) {
    #pragma unroll
    for (int i = 0; i < 4; i++) {
        int idx = tid + i * 256;
        int row = idx >> 3, q = idx & 7;
        uint32_t off = (uint32_t)(row * SMPAD + q * 4) * 4;
        cp16(sbase + off,                       A1 + (size_t)(m0 + row) * 128 + kc + q * 4);
        cp16(sbase + 128 * SMPAD * 4 + off,     A2 + (size_t)(m0 + row) * 128 + kc + q * 4);
        cp16(sbase + 2 * 128 * SMPAD * 4 + off, B32 + (size_t)(n0 + row) * 128 + kc + q * 4);
    }
    asm volatile("cp.async.commit_group;");
}

__global__ void __launch_bounds__(256, 1) big_gemm_tf32_dual(
    const uint32_t* __restrict__ A1, const uint32_t* __restrict__ A2,
    const uint32_t* __restrict__ B32, float* __restrict__ O1, float* __restrict__ O2) {
    extern __shared__ uint32_t sm[];
    uint32_t sbase = (uint32_t)__cvta_generic_to_shared(sm);

    int tid = threadIdx.x;
    int warp = tid >> 5;
    int lane = tid & 31;
    int g = lane >> 2;
    int tg = lane & 3;
    int wm = warp >> 1;
    int wn = warp & 1;
    int m0 = blockIdx.x * 128;
    int n0 = blockIdx.y * 128;

    float acc1[2][8][4] = {};
    float acc2[2][8][4] = {};

    load_stage(sbase, A1, A2, B32, m0, n0, 0, tid);

    #pragma unroll
    for (int c = 0; c < 4; c++) {
        if (c < 3) {
            load_stage(sbase + ((c + 1) & 1) * STAGE_W * 4, A1, A2, B32, m0, n0, (c + 1) * 32, tid);
            asm volatile("cp.async.wait_group 1;");
        } else {
            asm volatile("cp.async.wait_group 0;");
        }
        __syncthreads();
        const uint32_t* As1 = sm + (c & 1) * STAGE_W;
        const uint32_t* As2 = As1 + 128 * SMPAD;
        const uint32_t* Bs  = As2 + 128 * SMPAD;

        #pragma unroll
        for (int ks = 0; ks < 4; ks++) {
            int k0 = ks * 8;
            uint32_t b[8][2];
            #pragma unroll
            for (int nt = 0; nt < 8; nt++) {
                const uint32_t* bp = &Bs[(wn * 64 + nt * 8 + g) * SMPAD + k0 + tg];
                b[nt][0] = bp[0];
                b[nt][1] = bp[4];
            }
            #pragma unroll
            for (int mt = 0; mt < 2; mt++) {
                uint32_t a[4];
                const uint32_t* ap = &As1[(wm * 32 + mt * 16 + g) * SMPAD + k0 + tg];
                a[0] = ap[0]; a[1] = ap[8 * SMPAD]; a[2] = ap[4]; a[3] = ap[8 * SMPAD + 4];
                #pragma unroll
                for (int nt = 0; nt < 8; nt++) MMA_TF32(acc1[mt][nt], a, b[nt]);
                ap = &As2[(wm * 32 + mt * 16 + g) * SMPAD + k0 + tg];
                a[0] = ap[0]; a[1] = ap[8 * SMPAD]; a[2] = ap[4]; a[3] = ap[8 * SMPAD + 4];
                #pragma unroll
                for (int nt = 0; nt < 8; nt++) MMA_TF32(acc2[mt][nt], a, b[nt]);
            }
        }
        __syncthreads();
    }

    #pragma unroll
    for (int mt = 0; mt < 2; mt++) {
        #pragma unroll
        for (int nt = 0; nt < 8; nt++) {
            int col = n0 + wn * 64 + nt * 8 + tg * 2;
            if (col >= K_N) continue;
            size_t r0 = (size_t)(m0 + wm * 32 + mt * 16 + g);
            size_t r1 = r0 + 8;
            *(float2*)(O1 + r0 * K_N + col) = make_float2(acc1[mt][nt][0], acc1[mt][nt][1]);
            *(float2*)(O1 + r1 * K_N + col) = make_float2(acc1[mt][nt][2], acc1[mt][nt][3]);
            *(float2*)(O2 + r0 * K_N + col) = make_float2(acc2[mt][nt][0], acc2[mt][nt][1]);
            *(float2*)(O2 + r1 * K_N + col) = make_float2(acc2[mt][nt][2], acc2[mt][nt][3]);
        }
    }
}

// ---------------- host orchestration ----------------
extern "C" void kernel_launch(void* const* d_in, const int* in_sizes, int n_in,
                              void* d_out, int out_size) {
    (void)in_sizes; (void)n_in; (void)out_size;
    const int*   student_id  = (const int*)d_in[0];
    const int*   exercise_id = (const int*)d_in[1];
    const float* stu_emb     = (const float*)d_in[3];
    const float* exer_emb    = (const float*)d_in[4];
    const float* know_emb    = (const float*)d_in[5];
    const float* impact_emb  = (const float*)d_in[6];
    const int*   s_rows = (const int*)d_in[7];
    const int*   s_cols = (const int*)d_in[8];
    const float* s_vals = (const float*)d_in[9];
    const int*   e_rows = (const int*)d_in[10];
    const int*   e_cols = (const int*)d_in[11];
    const float* e_vals = (const float*)d_in[12];
    const int*   k_rows = (const int*)d_in[13];
    const int*   k_cols = (const int*)d_in[14];
    const float* k_vals = (const float*)d_in[15];
    const float* W_stu  = (const float*)d_in[16];
    const float* b_stu  = (const float*)d_in[17];
    const float* W_exer = (const float*)d_in[18];
    const float* b_exer = (const float*)d_in[19];
    const float* W_know = (const float*)d_in[20];
    const float* b_know = (const float*)d_in[21];
    const float* W_disc = (const float*)d_in[22];
    const float* b_disc = (const float*)d_in[23];

    unsigned char* A = nullptr;
    cudaGetSymbolAddress((void**)&A, g_arena);

    int*  rp_s  = (int*)(A + O_RP_S);
    int*  rp_e  = (int*)(A + O_RP_E);
    int*  rp_k  = (int*)(A + O_RP_K);
    unsigned long long* lk = (unsigned long long*)(A + O_LK);
    int*  cur_s = (int*)(A + O_CUR_S);
    int*  cur_e = (int*)(A + O_CUR_E);
    int*  cur_k = (int*)(A + O_CUR_K);
    int*  loc   = (int*)(A + O_LOC);
    int2* pairs_s = (int2*)(A + O_PAIRS_S);
    int2* pairs_e = (int2*)(A + O_PAIRS_E);
    int2* pairs_k = (int2*)(A + O_PAIRS_K);
    float* x1_s = (float*)(A + O_X1_S);
    float* x2_s = (float*)(A + O_X2_S);
    float* x1_e = (float*)(A + O_X1_E);
    float* x2_e = (float*)(A + O_X2_E);
    float* x1_k = (float*)(A + O_X1_K);
    float* x2_k = (float*)(A + O_X2_K);
    float* x3_k = (float*)(A + O_X3_K);
    float* xg_s = (float*)(A + O_XG_S);
    float* xg_e = (float*)(A + O_XG_E);
    uint32_t* A1 = (uint32_t*)(A + O_A1);
    uint32_t* A2 = (uint32_t*)(A + O_A2);
    uint32_t* Bt32 = (uint32_t*)(A + O_BT32);

    // 1) CSR build (scatter is atomic-free via hist-emitted ranks)
    zero_kernel<<<(ZERO_INTS + BT_PAD_WORDS + 1023) / 1024, 1024>>>(
        (int*)A, Bt32 + (size_t)K_N * 128);
    hist_all_kernel<<<(Q4_TOT + 255) / 256, 256>>>(
        (const int4*)s_rows, (const int4*)e_rows, (const int4*)k_rows,
        rp_s, rp_e, rp_k, (int4*)loc);
    scan_lookback_kernel<<<NB_TOT, 256>>>(rp_s, rp_e, rp_k, cur_s, cur_e, cur_k, lk);
    scatter_all_kernel<<<(Q4_TOT + 255) / 256, 256>>>(
        (const int4*)s_rows, (const int4*)s_cols, (const float4*)s_vals,
        (const int4*)e_rows, (const int4*)e_cols, (const float4*)e_vals,
        (const int4*)k_rows, (const int4*)k_cols, (const float4*)k_vals,
        cur_s, cur_e, cur_k, (const int4*)loc, pairs_s, pairs_e, pairs_k);

    // 2) layers 1-2 full; layer 3 batch-restricted + full know
    const float* in_s[3] = {stu_emb, x1_s, x2_s};
    const float* in_e[3] = {exer_emb, x1_e, x2_e};
    const float* in_k[3] = {know_emb, x1_k, x2_k};
    for (int l = 0; l < 2; l++) {
        SpmmArgs sa;
        sa.rp[0] = rp_s;  sa.rp[1] = rp_e;  sa.rp[2] = rp_k;
        sa.pr[0] = pairs_s; sa.pr[1] = pairs_e; sa.pr[2] = pairs_k;
        sa.xin[0] = (const float4*)in_s[l]; sa.xin[1] = (const float4*)in_e[l]; sa.xin[2] = (const float4*)in_k[l];
        sa.xout[0] = (float4*)in_s[l + 1];  sa.xout[1] = (float4*)in_e[l + 1];  sa.xout[2] = (float4*)in_k[l + 1];
        sa.nrows[0] = S_N; sa.nrows[1] = E_N; sa.nrows[2] = K_N;
        spmm_all_kernel<<<GB_S + GB_E + GB_K, 256>>>(sa);
    }
    {
        Spmm3Args a3;
        a3.rp_s = rp_s; a3.pr_s = pairs_s; a3.x2_s = (const float4*)x2_s; a3.xg_s = (float4*)xg_s; a3.sid = student_id;
        a3.rp_e = rp_e; a3.pr_e = pairs_e; a3.x2_e = (const float4*)x2_e; a3.xg_e = (float4*)xg_e; a3.eid = exercise_id;
        a3.rp_k = rp_k; a3.pr_k = pairs_k; a3.x2_k = (const float4*)x2_k; a3.x3_k = (float4*)x3_k;
        spmm_l3_kernel<<<GL_S + GL_E + GL_K, 256>>>(a3);
    }

    // 3) output layout
    float* out   = (float*)d_out;
    float* O1    = out;
    float* O2    = O1 + (size_t)B_N * K_N;
    float* Odisc = O2 + (size_t)B_N * K_N;
    float* Okt   = Odisc + B_N;
    float* Oimp  = Okt + (size_t)K_N * FF;

    // 4) unified dense stage (1 launch)
    static bool attr_set = false;
    if (!attr_set) {
        cudaFuncSetAttribute(dense_all_kernel,
                             cudaFuncAttributeMaxDynamicSharedMemorySize, DM_SMEM_BYTES);
        cudaFuncSetAttribute(big_gemm_tf32_dual,
                             cudaFuncAttributeMaxDynamicSharedMemorySize, GEMM_SMEM_BYTES);
        attr_set = true;
    }
    {
        DenseArgs da;
        da.x0s = stu_emb;  da.x1s = x1_s; da.x2s = x2_s; da.x3s = xg_s;
        da.x0e = exer_emb; da.x1e = x1_e; da.x2e = x2_e; da.x3e = xg_e;
        da.xk0 = know_emb; da.xk1 = x1_k; da.xk2 = x2_k; da.xk3 = x3_k;
        da.sid = student_id; da.eid = exercise_id;
        da.Ws = W_stu; da.bs = b_stu; da.We = W_exer; da.be = b_exer;
        da.Wk = W_know; da.bk = b_know; da.Wd = W_disc; da.bd = b_disc;
        da.imp = impact_emb;
        da.A1 = A1; da.A2 = A2; da.Bt32 = Bt32;
        da.Okt = Okt; da.Odisc = Odisc; da.Oimp = Oimp;
        dense_all_kernel<<<G_DENSE, 256, DM_SMEM_BYTES>>>(da);
    }

    // 5) TF32 big GEMM pair
    dim3 grid(B_N / 128, 1024 / 128);
    big_gemm_tf32_dual<<<grid, 256, GEMM_SMEM_BYTES>>>(A1, A2, Bt32, O1, O2);
}

// round 11
// speedup vs baseline: 1.3673x; 1.1499x over previous
#include <cuda_runtime.h>
#include <cuda_fp16.h>
#include <cstdint>
#include <cstddef>

#define S_N 100000
#define E_N 30000
#define K_N 1000
#define DD 64
#define FF 128
#define B_N 16384
#define NNZ_S 1600000
#define NNZ_E 480000
#define NNZ_K 32000
#define NNZ_TOT (NNZ_S + NNZ_E + NNZ_K)
#define MOM 0.9f
#define LEAK_F 0.1f

#define NB_S 98
#define NB_E 30
#define NB_K 1
#define NB_TOT (NB_S + NB_E + NB_K)

static constexpr size_t al256(size_t x) { return (x + 255) & ~(size_t)255; }

// ---------------- static scratch arena ----------------
static constexpr size_t O_RP_S = 0;
static constexpr size_t O_RP_E = O_RP_S + (size_t)(S_N + 1) * 4;
static constexpr size_t O_RP_K = O_RP_E + (size_t)(E_N + 1) * 4;
static constexpr size_t RP_END = O_RP_K + (size_t)(K_N + 1) * 4;
static constexpr size_t O_LK   = al256(RP_END);
static constexpr size_t LK_END = O_LK + (size_t)NB_TOT * 8;
static constexpr int    ZERO_INTS = (int)(LK_END / 4);

static constexpr size_t O_CUR_S = al256(LK_END);
static constexpr size_t O_CUR_E = al256(O_CUR_S + (size_t)S_N * 4);
static constexpr size_t O_CUR_K = al256(O_CUR_E + (size_t)E_N * 4);
static constexpr size_t O_LOC   = al256(O_CUR_K + (size_t)K_N * 4);
static constexpr size_t O_PAIRS_S = al256(O_LOC + (size_t)NNZ_TOT * 4);
static constexpr size_t O_PAIRS_E = al256(O_PAIRS_S + (size_t)NNZ_S * 8);
static constexpr size_t O_PAIRS_K = al256(O_PAIRS_E + (size_t)NNZ_E * 8);
// fp16 conv buffers (2 bytes/elem)
static constexpr size_t O_E16_S = al256(O_PAIRS_K + (size_t)NNZ_K * 8);
static constexpr size_t O_E16_E = al256(O_E16_S + (size_t)S_N * DD * 2);
static constexpr size_t O_E16_K = al256(O_E16_E + (size_t)E_N * DD * 2);
static constexpr size_t O_X1_S  = al256(O_E16_K + (size_t)K_N * DD * 2);
static constexpr size_t O_X2_S  = al256(O_X1_S + (size_t)S_N * DD * 2);
static constexpr size_t O_X1_E  = al256(O_X2_S + (size_t)S_N * DD * 2);
static constexpr size_t O_X2_E  = al256(O_X1_E + (size_t)E_N * DD * 2);
static constexpr size_t O_X1_K  = al256(O_X2_E + (size_t)E_N * DD * 2);
static constexpr size_t O_X2_K  = al256(O_X1_K + (size_t)K_N * DD * 2);
static constexpr size_t O_X3_K  = al256(O_X2_K + (size_t)K_N * DD * 2);
static constexpr size_t O_XG_S  = al256(O_X3_K + (size_t)K_N * DD * 2);
static constexpr size_t O_XG_E  = al256(O_XG_S + (size_t)B_N * DD * 2);
static constexpr size_t O_A1    = al256(O_XG_E + (size_t)B_N * DD * 2);
static constexpr size_t O_A2    = al256(O_A1 + (size_t)B_N * FF * 4);
static constexpr size_t O_BT32  = al256(O_A2 + (size_t)B_N * FF * 4);
static constexpr size_t ARENA_BYTES = al256(O_BT32 + (size_t)1024 * FF * 4);

__device__ __align__(256) unsigned char g_arena[ARENA_BYTES];

// ---------------- half<->float helpers ----------------
__device__ __forceinline__ float4 h4tof4(uint2 h) {
    __half2 a = *(__half2*)&h.x;
    __half2 b = *(__half2*)&h.y;
    float2 fa = __half22float2(a), fb = __half22float2(b);
    return make_float4(fa.x, fa.y, fb.x, fb.y);
}
__device__ __forceinline__ uint2 f4toh4(float4 f) {
    __half2 a = __floats2half2_rn(f.x, f.y);
    __half2 b = __floats2half2_rn(f.z, f.w);
    uint2 r;
    r.x = *(uint32_t*)&a;
    r.y = *(uint32_t*)&b;
    return r;
}

// ---------------- zero (rowptrs + lookback states + Bt32 pad) ----------------
#define BT_PAD_WORDS (24 * 128)
__global__ void zero_kernel(int* p, uint32_t* bt_pad) {
    int i = blockIdx.x * blockDim.x + threadIdx.x;
    if (i < ZERO_INTS) p[i] = 0;
    else if (i < ZERO_INTS + BT_PAD_WORDS) bt_pad[i - ZERO_INTS] = 0u;
}

// ---------------- embedding -> fp16 conversion ----------------
#define N8_S (S_N * DD / 8)
#define N8_E (E_N * DD / 8)
#define N8_K (K_N * DD / 8)
#define N8_TOT (N8_S + N8_E + N8_K)

__global__ void conv16_kernel(const float4* __restrict__ es, const float4* __restrict__ ee,
                              const float4* __restrict__ ek, uint4* __restrict__ s16,
                              uint4* __restrict__ e16, uint4* __restrict__ k16) {
    int i = blockIdx.x * blockDim.x + threadIdx.x;
    const float4* src; uint4* dst; int j;
    if (i < N8_S)             { src = es; dst = s16; j = i; }
    else if (i < N8_S + N8_E) { src = ee; dst = e16; j = i - N8_S; }
    else if (i < N8_TOT)      { src = ek; dst = k16; j = i - N8_S - N8_E; }
    else return;
    float4 a = __ldg(src + 2 * j);
    float4 b = __ldg(src + 2 * j + 1);
    uint2 ha = f4toh4(a), hb = f4toh4(b);
    dst[j] = make_uint4(ha.x, ha.y, hb.x, hb.y);
}

// ---------------- histogram (x4 vectorized, emits within-row ranks) ----------------
#define Q4_S (NNZ_S / 4)
#define Q4_E (NNZ_E / 4)
#define Q4_K (NNZ_K / 4)
#define Q4_TOT (Q4_S + Q4_E + Q4_K)

__global__ void hist_all_kernel(const int4* __restrict__ s_rows, const int4* __restrict__ e_rows,
                                const int4* __restrict__ k_rows, int* __restrict__ rp_s,
                                int* __restrict__ rp_e, int* __restrict__ rp_k,
                                int4* __restrict__ loc) {
    int i = blockIdx.x * blockDim.x + threadIdx.x;
    int4 r; int* rp;
    if (i < Q4_S)             { r = __ldg(s_rows + i); rp = rp_s; }
    else if (i < Q4_S + Q4_E) { r = __ldg(e_rows + (i - Q4_S)); rp = rp_e; }
    else if (i < Q4_TOT)      { r = __ldg(k_rows + (i - Q4_S - Q4_E)); rp = rp_k; }
    else return;
    int4 l;
    l.x = atomicAdd(&rp[r.x + 1], 1);
    l.y = atomicAdd(&rp[r.y + 1], 1);
    l.z = atomicAdd(&rp[r.z + 1], 1);
    l.w = atomicAdd(&rp[r.w + 1], 1);
    loc[i] = l;
}

// ---------------- single-pass decoupled-lookback scan ----------------
__global__ void __launch_bounds__(256) scan_lookback_kernel(
    int* __restrict__ rp_s, int* __restrict__ rp_e, int* __restrict__ rp_k,
    int* __restrict__ cur_s, int* __restrict__ cur_e, int* __restrict__ cur_k,
    unsigned long long* __restrict__ lk) {
    __shared__ int wsum[8];
    __shared__ int s_excl;
    const unsigned FULL = 0xFFFFFFFFu;
    int b = blockIdx.x, t = threadIdx.x, lane = t & 31, wid = t >> 5;
    int *x, *c, n, lb;
    if (b < NB_S)             { x = rp_s; c = cur_s; n = S_N + 1; lb = b; }
    else if (b < NB_S + NB_E) { x = rp_e; c = cur_e; n = E_N + 1; lb = b - NB_S; }
    else                      { x = rp_k; c = cur_k; n = K_N + 1; lb = b - NB_S - NB_E; }
    int base = lb * 1024 + t * 4;
    int v0 = (base     < n) ? x[base]     : 0;
    int v1 = (base + 1 < n) ? x[base + 1] : 0;
    int v2 = (base + 2 < n) ? x[base + 2] : 0;
    int v3 = (base + 3 < n) ? x[base + 3] : 0;
    v1 += v0; v2 += v1; v3 += v2;
    int tin = v3;
    int incl = tin;
    #pragma unroll
    for (int off = 1; off < 32; off <<= 1) {
        int o = __shfl_up_sync(FULL, incl, off);
        if (lane >= off) incl += o;
    }
    if (lane == 31) wsum[wid] = incl;
    __syncthreads();
    if (wid == 0) {
        int ws = (lane < 8) ? wsum[lane] : 0;
        #pragma unroll
        for (int off = 1; off < 8; off <<= 1) {
            int o = __shfl_up_sync(FULL, ws, off);
            if (lane >= off) ws += o;
        }
        if (lane < 8) wsum[lane] = ws;
    }
    __syncthreads();
    int agg = wsum[7];
    int warp_excl = wid ? wsum[wid - 1] : 0;
    int thread_excl = warp_excl + (incl - tin);

    if (wid == 0) {
        volatile unsigned long long* vlk = (volatile unsigned long long*)lk;
        if (lb == 0) {
            if (lane == 0) { vlk[b] = (2ULL << 32) | (unsigned)agg; s_excl = 0; }
        } else {
            if (lane == 0) vlk[b] = (1ULL << 32) | (unsigned)agg;
            int gbase = b - lb;
            int running = 0;
            int j = lb - 1;
            while (true) {
                int idx = j - lane;
                bool valid = idx >= 0;
                unsigned long long w = 0; int st = 0;
                while (true) {
                    if (valid) { w = vlk[gbase + idx]; st = (int)(w >> 32); }
                    if (__all_sync(FULL, !valid || st != 0)) break;
                }
                unsigned pm = __ballot_sync(FULL, valid && st == 2);
                int lane_p = pm ? (__ffs(pm) - 1) : 32;
                int val = (valid && lane <= lane_p) ? (int)(unsigned)w : 0;
                #pragma unroll
                for (int off = 16; off; off >>= 1) val += __shfl_xor_sync(FULL, val, off);
                running += val;
                if (lane_p < 32) break;
                j -= 32;
            }
            if (lane == 0) {
                vlk[b] = (2ULL << 32) | (unsigned)(running + agg);
                s_excl = running;
            }
        }
    }
    __syncthreads();
    int off0 = s_excl + thread_excl;
    if (base < n)     { int val = v0 + off0; x[base]     = val; if (base     < n - 1) c[base]     = val; }
    if (base + 1 < n) { int val = v1 + off0; x[base + 1] = val; if (base + 1 < n - 1) c[base + 1] = val; }
    if (base + 2 < n) { int val = v2 + off0; x[base + 2] = val; if (base + 2 < n - 1) c[base + 2] = val; }
    if (base + 3 < n) { int val = v3 + off0; x[base + 3] = val; if (base + 3 < n - 1) c[base + 3] = val; }
}

// ---------------- scatter (atomic-free: pos = rowstart + rank) ----------------
__global__ void scatter_all_kernel(
    const int4* __restrict__ s_rows, const int4* __restrict__ s_cols, const float4* __restrict__ s_vals,
    const int4* __restrict__ e_rows, const int4* __restrict__ e_cols, const float4* __restrict__ e_vals,
    const int4* __restrict__ k_rows, const int4* __restrict__ k_cols, const float4* __restrict__ k_vals,
    const int* __restrict__ cur_s, const int* __restrict__ cur_e, const int* __restrict__ cur_k,
    const int4* __restrict__ loc,
    int2* __restrict__ pairs_s, int2* __restrict__ pairs_e, int2* __restrict__ pairs_k) {
    int i = blockIdx.x * blockDim.x + threadIdx.x;
    int4 r, cidx; float4 v; const int* cur; int2* pairs;
    if (i < Q4_S) {
        r = __ldg(s_rows + i); cidx = __ldg(s_cols + i); v = __ldg(s_vals + i);
        cur = cur_s; pairs = pairs_s;
    } else if (i < Q4_S + Q4_E) {
        int j = i - Q4_S;
        r = __ldg(e_rows + j); cidx = __ldg(e_cols + j); v = __ldg(e_vals + j);
        cur = cur_e; pairs = pairs_e;
    } else if (i < Q4_TOT) {
        int j = i - Q4_S - Q4_E;
        r = __ldg(k_rows + j); cidx = __ldg(k_cols + j); v = __ldg(k_vals + j);
        cur = cur_k; pairs = pairs_k;
    } else return;
    int4 l = __ldg(loc + i);
    pairs[__ldg(cur + r.x) + l.x] = make_int2(cidx.x, __float_as_int(v.x));
    pairs[__ldg(cur + r.y) + l.y] = make_int2(cidx.y, __float_as_int(v.y));
    pairs[__ldg(cur + r.z) + l.z] = make_int2(cidx.z, __float_as_int(v.z));
    pairs[__ldg(cur + r.w) + l.w] = make_int2(cidx.w, __float_as_int(v.w));
}

// ---------------- SpMM core (fp16 x, fp32 accumulate) ----------------
// xin unit = uint2 = 4 halfs; row stride = 16 units
__device__ __forceinline__ float4 spmm_row_h(const int* __restrict__ rowptr,
                                             const int2* __restrict__ pairs,
                                             const uint2* __restrict__ xin, int row, int d4) {
    int beg = __ldg(rowptr + row);
    int end = __ldg(rowptr + row + 1);
    float4 s = make_float4(0.f, 0.f, 0.f, 0.f);
    int j = beg;
    for (; j + 3 < end; j += 4) {
        int2 p0 = __ldg(pairs + j);
        int2 p1 = __ldg(pairs + j + 1);
        int2 p2 = __ldg(pairs + j + 2);
        int2 p3 = __ldg(pairs + j + 3);
        float4 v0 = h4tof4(__ldg(xin + ((size_t)p0.x << 4) + d4));
        float4 v1 = h4tof4(__ldg(xin + ((size_t)p1.x << 4) + d4));
        float4 v2 = h4tof4(__ldg(xin + ((size_t)p2.x << 4) + d4));
        float4 v3 = h4tof4(__ldg(xin + ((size_t)p3.x << 4) + d4));
        float w0 = __int_as_float(p0.y), w1 = __int_as_float(p1.y);
        float w2 = __int_as_float(p2.y), w3 = __int_as_float(p3.y);
        s.x = fmaf(w0, v0.x, s.x); s.y = fmaf(w0, v0.y, s.y); s.z = fmaf(w0, v0.z, s.z); s.w = fmaf(w0, v0.w, s.w);
        s.x = fmaf(w1, v1.x, s.x); s.y = fmaf(w1, v1.y, s.y); s.z = fmaf(w1, v1.z, s.z); s.w = fmaf(w1, v1.w, s.w);
        s.x = fmaf(w2, v2.x, s.x); s.y = fmaf(w2, v2.y, s.y); s.z = fmaf(w2, v2.z, s.z); s.w = fmaf(w2, v2.w, s.w);
        s.x = fmaf(w3, v3.x, s.x); s.y = fmaf(w3, v3.y, s.y); s.z = fmaf(w3, v3.z, s.z); s.w = fmaf(w3, v3.w, s.w);
    }
    for (; j < end; j++) {
        int2 p = __ldg(pairs + j);
        float w = __int_as_float(p.y);
        float4 v = h4tof4(__ldg(xin + ((size_t)p.x << 4) + d4));
        s.x = fmaf(w, v.x, s.x); s.y = fmaf(w, v.y, s.y); s.z = fmaf(w, v.z, s.z); s.w = fmaf(w, v.w, s.w);
    }
    return s;
}

#define GB_S 6250
#define GB_E 1875
#define GB_K 63

struct SpmmArgs {
    const int* rp[3];
    const int2* pr[3];
    const uint2* xin[3];
    uint2* xout[3];
    int nrows[3];
};

__global__ void __launch_bounds__(256) spmm_all_kernel(SpmmArgs a) {
    int b = blockIdx.x;
    int seg, lb;
    if (b < GB_S)             { seg = 0; lb = b; }
    else if (b < GB_S + GB_E) { seg = 1; lb = b - GB_S; }
    else                      { seg = 2; lb = b - GB_S - GB_E; }
    int row = lb * 16 + (threadIdx.x >> 4);
    int d4 = threadIdx.x & 15;
    if (row >= a.nrows[seg]) return;
    const uint2* xin = a.xin[seg];
    float4 s = spmm_row_h(a.rp[seg], a.pr[seg], xin, row, d4);
    size_t o = ((size_t)row << 4) + d4;
    float4 m = h4tof4(xin[o]);
    s.x += MOM * m.x; s.y += MOM * m.y; s.z += MOM * m.z; s.w += MOM * m.w;
    a.xout[seg][o] = f4toh4(s);
}

// ---------------- layer 3: batch-restricted stu/exer + full know ----------------
#define GL_S 1024
#define GL_E 1024
#define GL_K 63

struct Spmm3Args {
    const int* rp_s; const int2* pr_s; const uint2* x2_s; uint2* xg_s; const int* sid;
    const int* rp_e; const int2* pr_e; const uint2* x2_e; uint2* xg_e; const int* eid;
    const int* rp_k; const int2* pr_k; const uint2* x2_k; uint2* x3_k;
};

__global__ void __launch_bounds__(256) spmm_l3_kernel(Spmm3Args a) {
    int b = blockIdx.x;
    int d4 = threadIdx.x & 15;
    int lr = (threadIdx.x >> 4);
    if (b < GL_S) {
        int r = b * 16 + lr;
        int row = __ldg(a.sid + r);
        float4 s = spmm_row_h(a.rp_s, a.pr_s, a.x2_s, row, d4);
        float4 m = h4tof4(a.x2_s[((size_t)row << 4) + d4]);
        s.x += MOM * m.x; s.y += MOM * m.y; s.z += MOM * m.z; s.w += MOM * m.w;
        a.xg_s[((size_t)r << 4) + d4] = f4toh4(s);
    } else if (b < GL_S + GL_E) {
        int r = (b - GL_S) * 16 + lr;
        int row = __ldg(a.eid + r);
        float4 s = spmm_row_h(a.rp_e, a.pr_e, a.x2_e, row, d4);
        float4 m = h4tof4(a.x2_e[((size_t)row << 4) + d4]);
        s.x += MOM * m.x; s.y += MOM * m.y; s.z += MOM * m.z; s.w += MOM * m.w;
        a.xg_e[((size_t)r << 4) + d4] = f4toh4(s);
    } else {
        int row = (b - GL_S - GL_E) * 16 + lr;
        if (row >= K_N) return;
        float4 s = spmm_row_h(a.rp_k, a.pr_k, a.x2_k, row, d4);
        float4 m = h4tof4(a.x2_k[((size_t)row << 4) + d4]);
        s.x += MOM * m.x; s.y += MOM * m.y; s.z += MOM * m.z; s.w += MOM * m.w;
        a.x3_k[((size_t)row << 4) + d4] = f4toh4(s);
    }
}

// ---------------- tf32 helpers / MMA macro ----------------
__device__ __forceinline__ uint32_t f2tf32(float f) {
    uint32_t u;
    asm("cvt.rna.tf32.f32 %0, %1;" : "=r"(u) : "f"(f));
    return u;
}

#define MMA_TF32(d, a, b)                                                     \
    asm volatile(                                                             \
        "mma.sync.aligned.m16n8k8.row.col.f32.tf32.tf32.f32 "                 \
        "{%0,%1,%2,%3}, {%4,%5,%6,%7}, {%8,%9}, {%0,%1,%2,%3};\n"             \
        : "+f"(d[0]), "+f"(d[1]), "+f"(d[2]), "+f"(d[3])                      \
        : "r"(a[0]), "r"(a[1]), "r"(a[2]), "r"(a[3]), "r"(b[0]), "r"(b[1]))

// ---------------- unified dense stage ----------------
#define XS_STRIDE 68
#define WT_STRIDE 68
#define DM_XS_W   (64 * XS_STRIDE)
#define DM_WT_W   (128 * WT_STRIDE)
#define DM_SMEM_BYTES ((DM_XS_W + DM_WT_W + 128 + 64) * 4)
#define G_MMA 512
#define G_KNO 125
#define G_IMP 1024
#define G_DENSE (G_MMA + G_KNO + G_IMP)

struct DenseArgs {
    const float *x0s;  const uint2 *x1s, *x2s, *x3s;   // x3s compact [B_N,64]
    const float *x0e;  const uint2 *x1e, *x2e, *x3e;   // x3e compact
    const float *xk0;  const uint2 *xk1, *xk2, *xk3;
    const int *sid, *eid;
    const float *Ws, *bs, *We, *be, *Wk, *bk, *Wd, *bd;
    const float *imp;
    uint32_t *A1, *A2, *Bt32;
    float *Okt, *Odisc, *Oimp;
};

__global__ void __launch_bounds__(256) dense_all_kernel(DenseArgs a) {
    extern __shared__ uint32_t dsm[];
    const unsigned FULL = 0xFFFFFFFFu;
    int b = blockIdx.x, tid = threadIdx.x;

    if (b < G_MMA) {
        uint32_t* Xs = dsm;
        uint32_t* Wt = dsm + DM_XS_W;
        float* bsm = (float*)(dsm + DM_XS_W + DM_WT_W);
        float* wd  = bsm + 128;
        bool is_e = b >= 256;
        int r0 = (is_e ? b - 256 : b) * 64;
        const float* x0 = is_e ? a.x0e : a.x0s;
        const uint2* x1 = is_e ? a.x1e : a.x1s;
        const uint2* x2 = is_e ? a.x2e : a.x2s;
        const uint2* x3 = is_e ? a.x3e : a.x3s;
        const int* ids  = is_e ? a.eid : a.sid;
        const float* W  = is_e ? a.We : a.Ws;
        const float* bias = is_e ? a.be : a.bs;
        uint32_t* out = is_e ? a.A2 : a.A1;

        for (int i = tid; i < 8192; i += 256) {
            int k = i >> 7, n = i & 127;
            Wt[n * WT_STRIDE + k] = f2tf32(__ldg(W + i));
        }
        if (tid < 128) bsm[tid] = __ldg(bias + tid);
        if (is_e && tid < 64) wd[tid] = __ldg(a.Wd + tid);

        for (int i = tid; i < 1024; i += 256) {
            int rr = i >> 4, c4 = i & 15;
            int r = r0 + rr;
            int rid = __ldg(ids + r);
            size_t o  = ((size_t)rid << 4) + c4;
            size_t o3 = ((size_t)r << 4) + c4;
            float4 a0 = __ldg((const float4*)x0 + o);
            float4 a1 = h4tof4(__ldg(x1 + o));
            float4 a2 = h4tof4(__ldg(x2 + o));
            float4 a3 = h4tof4(__ldg(x3 + o3));
            uint4 w;
            w.x = f2tf32(0.25f * (a0.x + a1.x + a2.x + a3.x));
            w.y = f2tf32(0.25f * (a0.y + a1.y + a2.y + a3.y));
            w.z = f2tf32(0.25f * (a0.z + a1.z + a2.z + a3.z));
            w.w = f2tf32(0.25f * (a0.w + a1.w + a2.w + a3.w));
            *(uint4*)&Xs[rr * XS_STRIDE + c4 * 4] = w;
        }
        __syncthreads();

        int warp = tid >> 5, lane = tid & 31, g = lane >> 2, tg = lane & 3;
        int wm = warp >> 1;
        int wn = warp & 1;
        float acc[8][4] = {};
        #pragma unroll
        for (int ks = 0; ks < 8; ks++) {
            int k0 = ks * 8;
            uint32_t A[4];
            const uint32_t* ap = &Xs[(wm * 16 + g) * XS_STRIDE + k0 + tg];
            A[0] = ap[0]; A[1] = ap[8 * XS_STRIDE]; A[2] = ap[4]; A[3] = ap[8 * XS_STRIDE + 4];
            #pragma unroll
            for (int nt = 0; nt < 8; nt++) {
                const uint32_t* bp = &Wt[(wn * 64 + nt * 8 + g) * WT_STRIDE + k0 + tg];
                uint32_t B[2] = {bp[0], bp[4]};
                MMA_TF32(acc[nt], A, B);
            }
        }

        #pragma unroll
        for (int nt = 0; nt < 8; nt++) {
            int col = wn * 64 + nt * 8 + tg * 2;
            float b0 = bsm[col], b1 = bsm[col + 1];
            size_t rA = (size_t)(r0 + wm * 16 + g);
            size_t rB = rA + 8;
            float v0 = acc[nt][0] + b0; v0 = (v0 > 0.f) ? v0 : LEAK_F * v0;
            float v1 = acc[nt][1] + b1; v1 = (v1 > 0.f) ? v1 : LEAK_F * v1;
            float v2 = acc[nt][2] + b0; v2 = (v2 > 0.f) ? v2 : LEAK_F * v2;
            float v3 = acc[nt][3] + b1; v3 = (v3 > 0.f) ? v3 : LEAK_F * v3;
            *(uint2*)(out + rA * 128 + col) = make_uint2(f2tf32(v0), f2tf32(v1));
            *(uint2*)(out + rB * 128 + col) = make_uint2(f2tf32(v2), f2tf32(v3));
        }

        if (is_e) {
            int row = tid >> 2, part = tid & 3;
            float s = 0.f;
            #pragma unroll
            for (int i = 0; i < 16; i++)
                s += __uint_as_float(Xs[row * XS_STRIDE + part * 16 + i]) * wd[part * 16 + i];
            s += __shfl_xor_sync(FULL, s, 1);
            s += __shfl_xor_sync(FULL, s, 2);
            if (part == 0) a.Odisc[r0 + row] = 1.f / (1.f + __expf(-(s + __ldg(a.bd))));
        }
    } else if (b < G_MMA + G_KNO) {
        float* Ws = (float*)dsm;
        float* Xs = Ws + 8192;
        int r0 = (b - G_MMA) * 8;
        const float4* W4 = (const float4*)a.Wk;
        float4* Ws4 = (float4*)Ws;
        #pragma unroll
        for (int i = 0; i < 8; i++) Ws4[tid + i * 256] = W4[tid + i * 256];
        if (tid < 128) {
            int rr = tid >> 4;
            int c4 = tid & 15;
            int r = r0 + rr;
            float4 v = make_float4(0.f, 0.f, 0.f, 0.f);
            if (r < K_N) {
                size_t o = ((size_t)r << 4) + c4;
                float4 a0 = __ldg((const float4*)a.xk0 + o);
                float4 a1 = h4tof4(__ldg(a.xk1 + o));
                float4 a2 = h4tof4(__ldg(a.xk2 + o));
                float4 a3 = h4tof4(__ldg(a.xk3 + o));
                v.x = 0.25f * (a0.x + a1.x + a2.x + a3.x);
                v.y = 0.25f * (a0.y + a1.y + a2.y + a3.y);
                v.z = 0.25f * (a0.z + a1.z + a2.z + a3.z);
                v.w = 0.25f * (a0.w + a1.w + a2.w + a3.w);
            }
            ((float4*)&Xs[rr * 64])[c4] = v;
        }
        __syncthreads();
        int col = tid & 127;
        int rbase = tid >> 7;
        float bv = __ldg(a.bk + col);
        #pragma unroll
        for (int rr = 0; rr < 4; rr++) {
            int lrow = rr * 2 + rbase;
            int r = r0 + lrow;
            if (r >= K_N) continue;
            float acc = bv;
            #pragma unroll
            for (int i = 0; i < 64; i++) acc = fmaf(Xs[lrow * 64 + i], Ws[i * 128 + col], acc);
            float rv = (acc > 0.f) ? acc : LEAK_F * acc;
            a.Okt[(size_t)r * 128 + col] = rv;
            a.Bt32[(size_t)r * 128 + col] = f2tf32(rv);
        }
    } else {
        int t = (b - G_MMA - G_KNO) * 256 + tid;
        int bi = t >> 4, q = t & 15;
        ((float4*)a.Oimp)[((size_t)bi << 4) + q] =
            __ldg((const float4*)a.imp + ((size_t)__ldg(a.eid + bi) << 4) + q);
    }
}

// ---------------- TF32 tensor-core big GEMM (128x128 tile, cp.async 2-stage) ----------------
#define SMPAD 36
#define STAGE_W (3 * 128 * SMPAD)
#define GEMM_SMEM_BYTES (2 * STAGE_W * 4)

__device__ __forceinline__ void cp16(uint32_t dst, const void* src) {
    asm volatile("cp.async.cg.shared.global [%0], [%1], 16;" :: "r"(dst), "l"(src));
}

__device__ __forceinline__ void load_stage(uint32_t sbase, const uint32_t* A1, const uint32_t* A2,
                                           const uint32_t* B32, int m0, int n0, int kc, int tid) {
    #pragma unroll
    for (int i = 0; i < 4; i++) {
        int idx = tid + i * 256;
        int row = idx >> 3, q = idx & 7;
        uint32_t off = (uint32_t)(row * SMPAD + q * 4) * 4;
        cp16(sbase + off,                       A1 + (size_t)(m0 + row) * 128 + kc + q * 4);
        cp16(sbase + 128 * SMPAD * 4 + off,     A2 + (size_t)(m0 + row) * 128 + kc + q * 4);
        cp16(sbase + 2 * 128 * SMPAD * 4 + off, B32 + (size_t)(n0 + row) * 128 + kc + q * 4);
    }
    asm volatile("cp.async.commit_group;");
}

__global__ void __launch_bounds__(256, 1) big_gemm_tf32_dual(
    const uint32_t* __restrict__ A1, const uint32_t* __restrict__ A2,
    const uint32_t* __restrict__ B32, float* __restrict__ O1, float* __restrict__ O2) {
    extern __shared__ uint32_t sm[];
    uint32_t sbase = (uint32_t)__cvta_generic_to_shared(sm);

    int tid = threadIdx.x;
    int warp = tid >> 5;
    int lane = tid & 31;
    int g = lane >> 2;
    int tg = lane & 3;
    int wm = warp >> 1;
    int wn = warp & 1;
    int m0 = blockIdx.x * 128;
    int n0 = blockIdx.y * 128;

    float acc1[2][8][4] = {};
    float acc2[2][8][4] = {};

    load_stage(sbase, A1, A2, B32, m0, n0, 0, tid);

    #pragma unroll
    for (int c = 0; c < 4; c++) {
        if (c < 3) {
            load_stage(sbase + ((c + 1) & 1) * STAGE_W * 4, A1, A2, B32, m0, n0, (c + 1) * 32, tid);
            asm volatile("cp.async.wait_group 1;");
        } else {
            asm volatile("cp.async.wait_group 0;");
        }
        __syncthreads();
        const uint32_t* As1 = sm + (c & 1) * STAGE_W;
        const uint32_t* As2 = As1 + 128 * SMPAD;
        const uint32_t* Bs  = As2 + 128 * SMPAD;

        #pragma unroll
        for (int ks = 0; ks < 4; ks++) {
            int k0 = ks * 8;
            uint32_t b[8][2];
            #pragma unroll
            for (int nt = 0; nt < 8; nt++) {
                const uint32_t* bp = &Bs[(wn * 64 + nt * 8 + g) * SMPAD + k0 + tg];
                b[nt][0] = bp[0];
                b[nt][1] = bp[4];
            }
            #pragma unroll
            for (int mt = 0; mt < 2; mt++) {
                uint32_t a[4];
                const uint32_t* ap = &As1[(wm * 32 + mt * 16 + g) * SMPAD + k0 + tg];
                a[0] = ap[0]; a[1] = ap[8 * SMPAD]; a[2] = ap[4]; a[3] = ap[8 * SMPAD + 4];
                #pragma unroll
                for (int nt = 0; nt < 8; nt++) MMA_TF32(acc1[mt][nt], a, b[nt]);
                ap = &As2[(wm * 32 + mt * 16 + g) * SMPAD + k0 + tg];
                a[0] = ap[0]; a[1] = ap[8 * SMPAD]; a[2] = ap[4]; a[3] = ap[8 * SMPAD + 4];
                #pragma unroll
                for (int nt = 0; nt < 8; nt++) MMA_TF32(acc2[mt][nt], a, b[nt]);
            }
        }
        __syncthreads();
    }

    #pragma unroll
    for (int mt = 0; mt < 2; mt++) {
        #pragma unroll
        for (int nt = 0; nt < 8; nt++) {
            int col = n0 + wn * 64 + nt * 8 + tg * 2;
            if (col >= K_N) continue;
            size_t r0 = (size_t)(m0 + wm * 32 + mt * 16 + g);
            size_t r1 = r0 + 8;
            *(float2*)(O1 + r0 * K_N + col) = make_float2(acc1[mt][nt][0], acc1[mt][nt][1]);
            *(float2*)(O1 + r1 * K_N + col) = make_float2(acc1[mt][nt][2], acc1[mt][nt][3]);
            *(float2*)(O2 + r0 * K_N + col) = make_float2(acc2[mt][nt][0], acc2[mt][nt][1]);
            *(float2*)(O2 + r1 * K_N + col) = make_float2(acc2[mt][nt][2], acc2[mt][nt][3]);
        }
    }
}

// ---------------- host orchestration ----------------
extern "C" void kernel_launch(void* const* d_in, const int* in_sizes, int n_in,
                              void* d_out, int out_size) {
    (void)in_sizes; (void)n_in; (void)out_size;
    const int*   student_id  = (const int*)d_in[0];
    const int*   exercise_id = (const int*)d_in[1];
    const float* stu_emb     = (const float*)d_in[3];
    const float* exer_emb    = (const float*)d_in[4];
    const float* know_emb    = (const float*)d_in[5];
    const float* impact_emb  = (const float*)d_in[6];
    const int*   s_rows = (const int*)d_in[7];
    const int*   s_cols = (const int*)d_in[8];
    const float* s_vals = (const float*)d_in[9];
    const int*   e_rows = (const int*)d_in[10];
    const int*   e_cols = (const int*)d_in[11];
    const float* e_vals = (const float*)d_in[12];
    const int*   k_rows = (const int*)d_in[13];
    const int*   k_cols = (const int*)d_in[14];
    const float* k_vals = (const float*)d_in[15];
    const float* W_stu  = (const float*)d_in[16];
    const float* b_stu  = (const float*)d_in[17];
    const float* W_exer = (const float*)d_in[18];
    const float* b_exer = (const float*)d_in[19];
    const float* W_know = (const float*)d_in[20];
    const float* b_know = (const float*)d_in[21];
    const float* W_disc = (const float*)d_in[22];
    const float* b_disc = (const float*)d_in[23];

    unsigned char* A = nullptr;
    cudaGetSymbolAddress((void**)&A, g_arena);

    int*  rp_s  = (int*)(A + O_RP_S);
    int*  rp_e  = (int*)(A + O_RP_E);
    int*  rp_k  = (int*)(A + O_RP_K);
    unsigned long long* lk = (unsigned long long*)(A + O_LK);
    int*  cur_s = (int*)(A + O_CUR_S);
    int*  cur_e = (int*)(A + O_CUR_E);
    int*  cur_k = (int*)(A + O_CUR_K);
    int*  loc   = (int*)(A + O_LOC);
    int2* pairs_s = (int2*)(A + O_PAIRS_S);
    int2* pairs_e = (int2*)(A + O_PAIRS_E);
    int2* pairs_k = (int2*)(A + O_PAIRS_K);
    uint2* e16_s = (uint2*)(A + O_E16_S);
    uint2* e16_e = (uint2*)(A + O_E16_E);
    uint2* e16_k = (uint2*)(A + O_E16_K);
    uint2* x1_s = (uint2*)(A + O_X1_S);
    uint2* x2_s = (uint2*)(A + O_X2_S);
    uint2* x1_e = (uint2*)(A + O_X1_E);
    uint2* x2_e = (uint2*)(A + O_X2_E);
    uint2* x1_k = (uint2*)(A + O_X1_K);
    uint2* x2_k = (uint2*)(A + O_X2_K);
    uint2* x3_k = (uint2*)(A + O_X3_K);
    uint2* xg_s = (uint2*)(A + O_XG_S);
    uint2* xg_e = (uint2*)(A + O_XG_E);
    uint32_t* A1 = (uint32_t*)(A + O_A1);
    uint32_t* A2 = (uint32_t*)(A + O_A2);
    uint32_t* Bt32 = (uint32_t*)(A + O_BT32);

    // 1) CSR build + fp16 embedding conversion
    zero_kernel<<<(ZERO_INTS + BT_PAD_WORDS + 1023) / 1024, 1024>>>(
        (int*)A, Bt32 + (size_t)K_N * 128);
    conv16_kernel<<<(N8_TOT + 255) / 256, 256>>>(
        (const float4*)stu_emb, (const float4*)exer_emb, (const float4*)know_emb,
        (uint4*)e16_s, (uint4*)e16_e, (uint4*)e16_k);
    hist_all_kernel<<<(Q4_TOT + 255) / 256, 256>>>(
        (const int4*)s_rows, (const int4*)e_rows, (const int4*)k_rows,
        rp_s, rp_e, rp_k, (int4*)loc);
    scan_lookback_kernel<<<NB_TOT, 256>>>(rp_s, rp_e, rp_k, cur_s, cur_e, cur_k, lk);
    scatter_all_kernel<<<(Q4_TOT + 255) / 256, 256>>>(
        (const int4*)s_rows, (const int4*)s_cols, (const float4*)s_vals,
        (const int4*)e_rows, (const int4*)e_cols, (const float4*)e_vals,
        (const int4*)k_rows, (const int4*)k_cols, (const float4*)k_vals,
        cur_s, cur_e, cur_k, (const int4*)loc, pairs_s, pairs_e, pairs_k);

    // 2) layers 1-2 full (fp16 storage); layer 3 batch-restricted + full know
    const uint2* in_s[3] = {e16_s, x1_s, x2_s};
    const uint2* in_e[3] = {e16_e, x1_e, x2_e};
    const uint2* in_k[3] = {e16_k, x1_k, x2_k};
    uint2* out_s[3] = {x1_s, x2_s, nullptr};
    uint2* out_e[3] = {x1_e, x2_e, nullptr};
    uint2* out_k[3] = {x1_k, x2_k, nullptr};
    for (int l = 0; l < 2; l++) {
        SpmmArgs sa;
        sa.rp[0] = rp_s;  sa.rp[1] = rp_e;  sa.rp[2] = rp_k;
        sa.pr[0] = pairs_s; sa.pr[1] = pairs_e; sa.pr[2] = pairs_k;
        sa.xin[0] = in_s[l]; sa.xin[1] = in_e[l]; sa.xin[2] = in_k[l];
        sa.xout[0] = out_s[l]; sa.xout[1] = out_e[l]; sa.xout[2] = out_k[l];
        sa.nrows[0] = S_N; sa.nrows[1] = E_N; sa.nrows[2] = K_N;
        spmm_all_kernel<<<GB_S + GB_E + GB_K, 256>>>(sa);
    }
    {
        Spmm3Args a3;
        a3.rp_s = rp_s; a3.pr_s = pairs_s; a3.x2_s = x2_s; a3.xg_s = xg_s; a3.sid = student_id;
        a3.rp_e = rp_e; a3.pr_e = pairs_e; a3.x2_e = x2_e; a3.xg_e = xg_e; a3.eid = exercise_id;
        a3.rp_k = rp_k; a3.pr_k = pairs_k; a3.x2_k = x2_k; a3.x3_k = x3_k;
        spmm_l3_kernel<<<GL_S + GL_E + GL_K, 256>>>(a3);
    }

    // 3) output layout
    float* out   = (float*)d_out;
    float* O1    = out;
    float* O2    = O1 + (size_t)B_N * K_N;
    float* Odisc = O2 + (size_t)B_N * K_N;
    float* Okt   = Odisc + B_N;
    float* Oimp  = Okt + (size_t)K_N * FF;

    // 4) unified dense stage
    static bool attr_set = false;
    if (!attr_set) {
        cudaFuncSetAttribute(dense_all_kernel,
                             cudaFuncAttributeMaxDynamicSharedMemorySize, DM_SMEM_BYTES);
        cudaFuncSetAttribute(big_gemm_tf32_dual,
                             cudaFuncAttributeMaxDynamicSharedMemorySize, GEMM_SMEM_BYTES);
        attr_set = true;
    }
    {
        DenseArgs da;
        da.x0s = stu_emb;  da.x1s = x1_s; da.x2s = x2_s; da.x3s = xg_s;
        da.x0e = exer_emb; da.x1e = x1_e; da.x2e = x2_e; da.x3e = xg_e;
        da.xk0 = know_emb; da.xk1 = x1_k; da.xk2 = x2_k; da.xk3 = x3_k;
        da.sid = student_id; da.eid = exercise_id;
        da.Ws = W_stu; da.bs = b_stu; da.We = W_exer; da.be = b_exer;
        da.Wk = W_know; da.bk = b_know; da.Wd = W_disc; da.bd = b_disc;
        da.imp = impact_emb;
        da.A1 = A1; da.A2 = A2; da.Bt32 = Bt32;
        da.Okt = Okt; da.Odisc = Odisc; da.Oimp = Oimp;
        dense_all_kernel<<<G_DENSE, 256, DM_SMEM_BYTES>>>(da);
    }

    // 5) TF32 big GEMM pair
    dim3 grid(B_N / 128, 1024 / 128);
    big_gemm_tf32_dual<<<grid, 256, GEMM_SMEM_BYTES>>>(A1, A2, Bt32, O1, O2);
}

// round 12
// speedup vs baseline: 1.5777x; 1.1539x over previous
#include <cuda_runtime.h>
#include <cuda_fp16.h>
#include <cstdint>
#include <cstddef>

#define S_N 100000
#define E_N 30000
#define K_N 1000
#define DD 64
#define FF 128
#define B_N 16384
#define NNZ_S 1600000
#define NNZ_E 480000
#define NNZ_K 32000
#define NNZ_TOT (NNZ_S + NNZ_E + NNZ_K)
#define MOM 0.9f
#define LEAK_F 0.1f

#define NB_S 98
#define NB_E 30
#define NB_K 1
#define NB_TOT (NB_S + NB_E + NB_K)

static constexpr size_t al256(size_t x) { return (x + 255) & ~(size_t)255; }

// ---------------- static scratch arena ----------------
static constexpr size_t O_RP_S = 0;
static constexpr size_t O_RP_E = O_RP_S + (size_t)(S_N + 1) * 4;
static constexpr size_t O_RP_K = O_RP_E + (size_t)(E_N + 1) * 4;
static constexpr size_t RP_END = O_RP_K + (size_t)(K_N + 1) * 4;
static constexpr size_t O_LK   = al256(RP_END);
static constexpr size_t LK_END = O_LK + (size_t)NB_TOT * 8;
static constexpr int    ZERO_INTS = (int)(LK_END / 4);

static constexpr size_t O_CUR_S = al256(LK_END);
static constexpr size_t O_CUR_E = al256(O_CUR_S + (size_t)S_N * 4);
static constexpr size_t O_CUR_K = al256(O_CUR_E + (size_t)E_N * 4);
static constexpr size_t O_LOC   = al256(O_CUR_K + (size_t)K_N * 4);
static constexpr size_t O_PAIRS_S = al256(O_LOC + (size_t)NNZ_TOT * 4);
static constexpr size_t O_PAIRS_E = al256(O_PAIRS_S + (size_t)NNZ_S * 8);
static constexpr size_t O_PAIRS_K = al256(O_PAIRS_E + (size_t)NNZ_E * 8);
// fp16 conv buffers
static constexpr size_t O_E16_S = al256(O_PAIRS_K + (size_t)NNZ_K * 8);
static constexpr size_t O_E16_E = al256(O_E16_S + (size_t)S_N * DD * 2);
static constexpr size_t O_E16_K = al256(O_E16_E + (size_t)E_N * DD * 2);
static constexpr size_t O_X1_S  = al256(O_E16_K + (size_t)K_N * DD * 2);
static constexpr size_t O_X2_S  = al256(O_X1_S + (size_t)S_N * DD * 2);
static constexpr size_t O_X1_E  = al256(O_X2_S + (size_t)S_N * DD * 2);
static constexpr size_t O_X2_E  = al256(O_X1_E + (size_t)E_N * DD * 2);
static constexpr size_t O_X1_K  = al256(O_X2_E + (size_t)E_N * DD * 2);
static constexpr size_t O_X2_K  = al256(O_X1_K + (size_t)K_N * DD * 2);
static constexpr size_t O_X3_K  = al256(O_X2_K + (size_t)K_N * DD * 2);
static constexpr size_t O_XG_S  = al256(O_X3_K + (size_t)K_N * DD * 2);
static constexpr size_t O_XG_E  = al256(O_XG_S + (size_t)B_N * DD * 2);
// fp16 GEMM operands
static constexpr size_t O_A1    = al256(O_XG_E + (size_t)B_N * DD * 2);
static constexpr size_t O_A2    = al256(O_A1 + (size_t)B_N * FF * 2);
static constexpr size_t O_BT16  = al256(O_A2 + (size_t)B_N * FF * 2);
static constexpr size_t ARENA_BYTES = al256(O_BT16 + (size_t)1024 * FF * 2);

__device__ __align__(256) unsigned char g_arena[ARENA_BYTES];

// ---------------- half<->float helpers ----------------
__device__ __forceinline__ float4 h4tof4(uint2 h) {
    __half2 a = *(__half2*)&h.x;
    __half2 b = *(__half2*)&h.y;
    float2 fa = __half22float2(a), fb = __half22float2(b);
    return make_float4(fa.x, fa.y, fb.x, fb.y);
}
__device__ __forceinline__ uint2 f4toh4(float4 f) {
    __half2 a = __floats2half2_rn(f.x, f.y);
    __half2 b = __floats2half2_rn(f.z, f.w);
    uint2 r;
    r.x = *(uint32_t*)&a;
    r.y = *(uint32_t*)&b;
    return r;
}
__device__ __forceinline__ uint32_t f2toh2(float a, float b) {
    __half2 h = __floats2half2_rn(a, b);
    return *(uint32_t*)&h;
}

// ---------------- init: zero (rowptrs+lk+Bt16 pad) + fp16 embedding convert ----------------
#define BT16_PAD_WORDS (24 * 128 / 2)
#define N8_S (S_N * DD / 8)
#define N8_E (E_N * DD / 8)
#define N8_K (K_N * DD / 8)
#define N8_TOT (N8_S + N8_E + N8_K)
#define INIT_TOT (ZERO_INTS + BT16_PAD_WORDS + N8_TOT)

__global__ void init_kernel(int* p, uint32_t* bt_pad,
                            const float4* __restrict__ es, const float4* __restrict__ ee,
                            const float4* __restrict__ ek, uint4* __restrict__ s16,
                            uint4* __restrict__ e16, uint4* __restrict__ k16) {
    int i = blockIdx.x * blockDim.x + threadIdx.x;
    if (i < ZERO_INTS) { p[i] = 0; return; }
    if (i < ZERO_INTS + BT16_PAD_WORDS) { bt_pad[i - ZERO_INTS] = 0u; return; }
    int c = i - ZERO_INTS - BT16_PAD_WORDS;
    const float4* src; uint4* dst; int j;
    if (c < N8_S)             { src = es; dst = s16; j = c; }
    else if (c < N8_S + N8_E) { src = ee; dst = e16; j = c - N8_S; }
    else if (c < N8_TOT)      { src = ek; dst = k16; j = c - N8_S - N8_E; }
    else return;
    float4 a = __ldg(src + 2 * j);
    float4 b = __ldg(src + 2 * j + 1);
    uint2 ha = f4toh4(a), hb = f4toh4(b);
    dst[j] = make_uint4(ha.x, ha.y, hb.x, hb.y);
}

// ---------------- histogram (x4 vectorized, emits within-row ranks) ----------------
#define Q4_S (NNZ_S / 4)
#define Q4_E (NNZ_E / 4)
#define Q4_K (NNZ_K / 4)
#define Q4_TOT (Q4_S + Q4_E + Q4_K)

__global__ void hist_all_kernel(const int4* __restrict__ s_rows, const int4* __restrict__ e_rows,
                                const int4* __restrict__ k_rows, int* __restrict__ rp_s,
                                int* __restrict__ rp_e, int* __restrict__ rp_k,
                                int4* __restrict__ loc) {
    int i = blockIdx.x * blockDim.x + threadIdx.x;
    int4 r; int* rp;
    if (i < Q4_S)             { r = __ldg(s_rows + i); rp = rp_s; }
    else if (i < Q4_S + Q4_E) { r = __ldg(e_rows + (i - Q4_S)); rp = rp_e; }
    else if (i < Q4_TOT)      { r = __ldg(k_rows + (i - Q4_S - Q4_E)); rp = rp_k; }
    else return;
    int4 l;
    l.x = atomicAdd(&rp[r.x + 1], 1);
    l.y = atomicAdd(&rp[r.y + 1], 1);
    l.z = atomicAdd(&rp[r.z + 1], 1);
    l.w = atomicAdd(&rp[r.w + 1], 1);
    loc[i] = l;
}

// ---------------- single-pass decoupled-lookback scan ----------------
__global__ void __launch_bounds__(256) scan_lookback_kernel(
    int* __restrict__ rp_s, int* __restrict__ rp_e, int* __restrict__ rp_k,
    int* __restrict__ cur_s, int* __restrict__ cur_e, int* __restrict__ cur_k,
    unsigned long long* __restrict__ lk) {
    __shared__ int wsum[8];
    __shared__ int s_excl;
    const unsigned FULL = 0xFFFFFFFFu;
    int b = blockIdx.x, t = threadIdx.x, lane = t & 31, wid = t >> 5;
    int *x, *c, n, lb;
    if (b < NB_S)             { x = rp_s; c = cur_s; n = S_N + 1; lb = b; }
    else if (b < NB_S + NB_E) { x = rp_e; c = cur_e; n = E_N + 1; lb = b - NB_S; }
    else                      { x = rp_k; c = cur_k; n = K_N + 1; lb = b - NB_S - NB_E; }
    int base = lb * 1024 + t * 4;
    int v0 = (base     < n) ? x[base]     : 0;
    int v1 = (base + 1 < n) ? x[base + 1] : 0;
    int v2 = (base + 2 < n) ? x[base + 2] : 0;
    int v3 = (base + 3 < n) ? x[base + 3] : 0;
    v1 += v0; v2 += v1; v3 += v2;
    int tin = v3;
    int incl = tin;
    #pragma unroll
    for (int off = 1; off < 32; off <<= 1) {
        int o = __shfl_up_sync(FULL, incl, off);
        if (lane >= off) incl += o;
    }
    if (lane == 31) wsum[wid] = incl;
    __syncthreads();
    if (wid == 0) {
        int ws = (lane < 8) ? wsum[lane] : 0;
        #pragma unroll
        for (int off = 1; off < 8; off <<= 1) {
            int o = __shfl_up_sync(FULL, ws, off);
            if (lane >= off) ws += o;
        }
        if (lane < 8) wsum[lane] = ws;
    }
    __syncthreads();
    int agg = wsum[7];
    int warp_excl = wid ? wsum[wid - 1] : 0;
    int thread_excl = warp_excl + (incl - tin);

    if (wid == 0) {
        volatile unsigned long long* vlk = (volatile unsigned long long*)lk;
        if (lb == 0) {
            if (lane == 0) { vlk[b] = (2ULL << 32) | (unsigned)agg; s_excl = 0; }
        } else {
            if (lane == 0) vlk[b] = (1ULL << 32) | (unsigned)agg;
            int gbase = b - lb;
            int running = 0;
            int j = lb - 1;
            while (true) {
                int idx = j - lane;
                bool valid = idx >= 0;
                unsigned long long w = 0; int st = 0;
                while (true) {
                    if (valid) { w = vlk[gbase + idx]; st = (int)(w >> 32); }
                    if (__all_sync(FULL, !valid || st != 0)) break;
                }
                unsigned pm = __ballot_sync(FULL, valid && st == 2);
                int lane_p = pm ? (__ffs(pm) - 1) : 32;
                int val = (valid && lane <= lane_p) ? (int)(unsigned)w : 0;
                #pragma unroll
                for (int off = 16; off; off >>= 1) val += __shfl_xor_sync(FULL, val, off);
                running += val;
                if (lane_p < 32) break;
                j -= 32;
            }
            if (lane == 0) {
                vlk[b] = (2ULL << 32) | (unsigned)(running + agg);
                s_excl = running;
            }
        }
    }
    __syncthreads();
    int off0 = s_excl + thread_excl;
    if (base < n)     { int val = v0 + off0; x[base]     = val; if (base     < n - 1) c[base]     = val; }
    if (base + 1 < n) { int val = v1 + off0; x[base + 1] = val; if (base + 1 < n - 1) c[base + 1] = val; }
    if (base + 2 < n) { int val = v2 + off0; x[base + 2] = val; if (base + 2 < n - 1) c[base + 2] = val; }
    if (base + 3 < n) { int val = v3 + off0; x[base + 3] = val; if (base + 3 < n - 1) c[base + 3] = val; }
}

// ---------------- scatter (atomic-free: pos = rowstart + rank) ----------------
__global__ void scatter_all_kernel(
    const int4* __restrict__ s_rows, const int4* __restrict__ s_cols, const float4* __restrict__ s_vals,
    const int4* __restrict__ e_rows, const int4* __restrict__ e_cols, const float4* __restrict__ e_vals,
    const int4* __restrict__ k_rows, const int4* __restrict__ k_cols, const float4* __restrict__ k_vals,
    const int* __restrict__ cur_s, const int* __restrict__ cur_e, const int* __restrict__ cur_k,
    const int4* __restrict__ loc,
    int2* __restrict__ pairs_s, int2* __restrict__ pairs_e, int2* __restrict__ pairs_k) {
    int i = blockIdx.x * blockDim.x + threadIdx.x;
    int4 r, cidx; float4 v; const int* cur; int2* pairs;
    if (i < Q4_S) {
        r = __ldg(s_rows + i); cidx = __ldg(s_cols + i); v = __ldg(s_vals + i);
        cur = cur_s; pairs = pairs_s;
    } else if (i < Q4_S + Q4_E) {
        int j = i - Q4_S;
        r = __ldg(e_rows + j); cidx = __ldg(e_cols + j); v = __ldg(e_vals + j);
        cur = cur_e; pairs = pairs_e;
    } else if (i < Q4_TOT) {
        int j = i - Q4_S - Q4_E;
        r = __ldg(k_rows + j); cidx = __ldg(k_cols + j); v = __ldg(k_vals + j);
        cur = cur_k; pairs = pairs_k;
    } else return;
    int4 l = __ldg(loc + i);
    pairs[__ldg(cur + r.x) + l.x] = make_int2(cidx.x, __float_as_int(v.x));
    pairs[__ldg(cur + r.y) + l.y] = make_int2(cidx.y, __float_as_int(v.y));
    pairs[__ldg(cur + r.z) + l.z] = make_int2(cidx.z, __float_as_int(v.z));
    pairs[__ldg(cur + r.w) + l.w] = make_int2(cidx.w, __float_as_int(v.w));
}

// ---------------- SpMM core (fp16 x, fp32 accumulate) ----------------
__device__ __forceinline__ float4 spmm_row_h(const int* __restrict__ rowptr,
                                             const int2* __restrict__ pairs,
                                             const uint2* __restrict__ xin, int row, int d4) {
    int beg = __ldg(rowptr + row);
    int end = __ldg(rowptr + row + 1);
    float4 s = make_float4(0.f, 0.f, 0.f, 0.f);
    int j = beg;
    for (; j + 3 < end; j += 4) {
        int2 p0 = __ldg(pairs + j);
        int2 p1 = __ldg(pairs + j + 1);
        int2 p2 = __ldg(pairs + j + 2);
        int2 p3 = __ldg(pairs + j + 3);
        float4 v0 = h4tof4(__ldg(xin + ((size_t)p0.x << 4) + d4));
        float4 v1 = h4tof4(__ldg(xin + ((size_t)p1.x << 4) + d4));
        float4 v2 = h4tof4(__ldg(xin + ((size_t)p2.x << 4) + d4));
        float4 v3 = h4tof4(__ldg(xin + ((size_t)p3.x << 4) + d4));
        float w0 = __int_as_float(p0.y), w1 = __int_as_float(p1.y);
        float w2 = __int_as_float(p2.y), w3 = __int_as_float(p3.y);
        s.x = fmaf(w0, v0.x, s.x); s.y = fmaf(w0, v0.y, s.y); s.z = fmaf(w0, v0.z, s.z); s.w = fmaf(w0, v0.w, s.w);
        s.x = fmaf(w1, v1.x, s.x); s.y = fmaf(w1, v1.y, s.y); s.z = fmaf(w1, v1.z, s.z); s.w = fmaf(w1, v1.w, s.w);
        s.x = fmaf(w2, v2.x, s.x); s.y = fmaf(w2, v2.y, s.y); s.z = fmaf(w2, v2.z, s.z); s.w = fmaf(w2, v2.w, s.w);
        s.x = fmaf(w3, v3.x, s.x); s.y = fmaf(w3, v3.y, s.y); s.z = fmaf(w3, v3.z, s.z); s.w = fmaf(w3, v3.w, s.w);
    }
    for (; j < end; j++) {
        int2 p = __ldg(pairs + j);
        float w = __int_as_float(p.y);
        float4 v = h4tof4(__ldg(xin + ((size_t)p.x << 4) + d4));
        s.x = fmaf(w, v.x, s.x); s.y = fmaf(w, v.y, s.y); s.z = fmaf(w, v.z, s.z); s.w = fmaf(w, v.w, s.w);
    }
    return s;
}

#define GB_S 6250
#define GB_E 1875
#define GB_K 63

struct SpmmArgs {
    const int* rp[3];
    const int2* pr[3];
    const uint2* xin[3];
    uint2* xout[3];
    int nrows[3];
};

__global__ void __launch_bounds__(256) spmm_all_kernel(SpmmArgs a) {
    int b = blockIdx.x;
    int seg, lb;
    if (b < GB_S)             { seg = 0; lb = b; }
    else if (b < GB_S + GB_E) { seg = 1; lb = b - GB_S; }
    else                      { seg = 2; lb = b - GB_S - GB_E; }
    int row = lb * 16 + (threadIdx.x >> 4);
    int d4 = threadIdx.x & 15;
    if (row >= a.nrows[seg]) return;
    const uint2* xin = a.xin[seg];
    float4 s = spmm_row_h(a.rp[seg], a.pr[seg], xin, row, d4);
    size_t o = ((size_t)row << 4) + d4;
    float4 m = h4tof4(xin[o]);
    s.x += MOM * m.x; s.y += MOM * m.y; s.z += MOM * m.z; s.w += MOM * m.w;
    a.xout[seg][o] = f4toh4(s);
}

// ---------------- layer 3: batch-restricted stu/exer + full know ----------------
#define GL_S 1024
#define GL_E 1024
#define GL_K 63

struct Spmm3Args {
    const int* rp_s; const int2* pr_s; const uint2* x2_s; uint2* xg_s; const int* sid;
    const int* rp_e; const int2* pr_e; const uint2* x2_e; uint2* xg_e; const int* eid;
    const int* rp_k; const int2* pr_k; const uint2* x2_k; uint2* x3_k;
};

__global__ void __launch_bounds__(256) spmm_l3_kernel(Spmm3Args a) {
    int b = blockIdx.x;
    int d4 = threadIdx.x & 15;
    int lr = (threadIdx.x >> 4);
    if (b < GL_S) {
        int r = b * 16 + lr;
        int row = __ldg(a.sid + r);
        float4 s = spmm_row_h(a.rp_s, a.pr_s, a.x2_s, row, d4);
        float4 m = h4tof4(a.x2_s[((size_t)row << 4) + d4]);
        s.x += MOM * m.x; s.y += MOM * m.y; s.z += MOM * m.z; s.w += MOM * m.w;
        a.xg_s[((size_t)r << 4) + d4] = f4toh4(s);
    } else if (b < GL_S + GL_E) {
        int r = (b - GL_S) * 16 + lr;
        int row = __ldg(a.eid + r);
        float4 s = spmm_row_h(a.rp_e, a.pr_e, a.x2_e, row, d4);
        float4 m = h4tof4(a.x2_e[((size_t)row << 4) + d4]);
        s.x += MOM * m.x; s.y += MOM * m.y; s.z += MOM * m.z; s.w += MOM * m.w;
        a.xg_e[((size_t)r << 4) + d4] = f4toh4(s);
    } else {
        int row = (b - GL_S - GL_E) * 16 + lr;
        if (row >= K_N) return;
        float4 s = spmm_row_h(a.rp_k, a.pr_k, a.x2_k, row, d4);
        float4 m = h4tof4(a.x2_k[((size_t)row << 4) + d4]);
        s.x += MOM * m.x; s.y += MOM * m.y; s.z += MOM * m.z; s.w += MOM * m.w;
        a.x3_k[((size_t)row << 4) + d4] = f4toh4(s);
    }
}

// ---------------- tf32 helper / MMA macros ----------------
__device__ __forceinline__ uint32_t f2tf32(float f) {
    uint32_t u;
    asm("cvt.rna.tf32.f32 %0, %1;" : "=r"(u) : "f"(f));
    return u;
}

#define MMA_TF32(d, a, b)                                                     \
    asm volatile(                                                             \
        "mma.sync.aligned.m16n8k8.row.col.f32.tf32.tf32.f32 "                 \
        "{%0,%1,%2,%3}, {%4,%5,%6,%7}, {%8,%9}, {%0,%1,%2,%3};\n"             \
        : "+f"(d[0]), "+f"(d[1]), "+f"(d[2]), "+f"(d[3])                      \
        : "r"(a[0]), "r"(a[1]), "r"(a[2]), "r"(a[3]), "r"(b[0]), "r"(b[1]))

#define MMA_F16(d, a, b)                                                      \
    asm volatile(                                                             \
        "mma.sync.aligned.m16n8k16.row.col.f32.f16.f16.f32 "                  \
        "{%0,%1,%2,%3}, {%4,%5,%6,%7}, {%8,%9}, {%0,%1,%2,%3};\n"             \
        : "+f"(d[0]), "+f"(d[1]), "+f"(d[2]), "+f"(d[3])                      \
        : "r"(a[0]), "r"(a[1]), "r"(a[2]), "r"(a[3]), "r"(b[0]), "r"(b[1]))

// ---------------- unified dense stage ----------------
#define XS_STRIDE 68
#define WT_STRIDE 68
#define DM_XS_W   (64 * XS_STRIDE)
#define DM_WT_W   (128 * WT_STRIDE)
#define DM_SMEM_BYTES ((DM_XS_W + DM_WT_W + 128 + 64) * 4)
#define G_MMA 512
#define G_KNO 125
#define G_IMP 1024
#define G_DENSE (G_MMA + G_KNO + G_IMP)

struct DenseArgs {
    const float *x0s;  const uint2 *x1s, *x2s, *x3s;
    const float *x0e;  const uint2 *x1e, *x2e, *x3e;
    const float *xk0;  const uint2 *xk1, *xk2, *xk3;
    const int *sid, *eid;
    const float *Ws, *bs, *We, *be, *Wk, *bk, *Wd, *bd;
    const float *imp;
    uint32_t *A1h, *A2h;     // fp16 outputs, 2 halfs/word, row = 64 words
    __half *Bt16;            // fp16 knowledge_ts copy [1024][128]
    float *Okt, *Odisc, *Oimp;
};

__global__ void __launch_bounds__(256) dense_all_kernel(DenseArgs a) {
    extern __shared__ uint32_t dsm[];
    const unsigned FULL = 0xFFFFFFFFu;
    int b = blockIdx.x, tid = threadIdx.x;

    if (b < G_MMA) {
        uint32_t* Xs = dsm;
        uint32_t* Wt = dsm + DM_XS_W;
        float* bsm = (float*)(dsm + DM_XS_W + DM_WT_W);
        float* wd  = bsm + 128;
        bool is_e = b >= 256;
        int r0 = (is_e ? b - 256 : b) * 64;
        const float* x0 = is_e ? a.x0e : a.x0s;
        const uint2* x1 = is_e ? a.x1e : a.x1s;
        const uint2* x2 = is_e ? a.x2e : a.x2s;
        const uint2* x3 = is_e ? a.x3e : a.x3s;
        const int* ids  = is_e ? a.eid : a.sid;
        const float* W  = is_e ? a.We : a.Ws;
        const float* bias = is_e ? a.be : a.bs;
        uint32_t* out = is_e ? a.A2h : a.A1h;

        for (int i = tid; i < 8192; i += 256) {
            int k = i >> 7, n = i & 127;
            Wt[n * WT_STRIDE + k] = f2tf32(__ldg(W + i));
        }
        if (tid < 128) bsm[tid] = __ldg(bias + tid);
        if (is_e && tid < 64) wd[tid] = __ldg(a.Wd + tid);

        for (int i = tid; i < 1024; i += 256) {
            int rr = i >> 4, c4 = i & 15;
            int r = r0 + rr;
            int rid = __ldg(ids + r);
            size_t o  = ((size_t)rid << 4) + c4;
            size_t o3 = ((size_t)r << 4) + c4;
            float4 a0 = __ldg((const float4*)x0 + o);
            float4 a1 = h4tof4(__ldg(x1 + o));
            float4 a2 = h4tof4(__ldg(x2 + o));
            float4 a3 = h4tof4(__ldg(x3 + o3));
            uint4 w;
            w.x = f2tf32(0.25f * (a0.x + a1.x + a2.x + a3.x));
            w.y = f2tf32(0.25f * (a0.y + a1.y + a2.y + a3.y));
            w.z = f2tf32(0.25f * (a0.z + a1.z + a2.z + a3.z));
            w.w = f2tf32(0.25f * (a0.w + a1.w + a2.w + a3.w));
            *(uint4*)&Xs[rr * XS_STRIDE + c4 * 4] = w;
        }
        __syncthreads();

        int warp = tid >> 5, lane = tid & 31, g = lane >> 2, tg = lane & 3;
        int wm = warp >> 1;
        int wn = warp & 1;
        float acc[8][4] = {};
        #pragma unroll
        for (int ks = 0; ks < 8; ks++) {
            int k0 = ks * 8;
            uint32_t A[4];
            const uint32_t* ap = &Xs[(wm * 16 + g) * XS_STRIDE + k0 + tg];
            A[0] = ap[0]; A[1] = ap[8 * XS_STRIDE]; A[2] = ap[4]; A[3] = ap[8 * XS_STRIDE + 4];
            #pragma unroll
            for (int nt = 0; nt < 8; nt++) {
                const uint32_t* bp = &Wt[(wn * 64 + nt * 8 + g) * WT_STRIDE + k0 + tg];
                uint32_t B[2] = {bp[0], bp[4]};
                MMA_TF32(acc[nt], A, B);
            }
        }

        #pragma unroll
        for (int nt = 0; nt < 8; nt++) {
            int col = wn * 64 + nt * 8 + tg * 2;
            float b0 = bsm[col], b1 = bsm[col + 1];
            size_t rA = (size_t)(r0 + wm * 16 + g);
            size_t rB = rA + 8;
            float v0 = acc[nt][0] + b0; v0 = (v0 > 0.f) ? v0 : LEAK_F * v0;
            float v1 = acc[nt][1] + b1; v1 = (v1 > 0.f) ? v1 : LEAK_F * v1;
            float v2 = acc[nt][2] + b0; v2 = (v2 > 0.f) ? v2 : LEAK_F * v2;
            float v3 = acc[nt][3] + b1; v3 = (v3 > 0.f) ? v3 : LEAK_F * v3;
            out[rA * 64 + (col >> 1)] = f2toh2(v0, v1);
            out[rB * 64 + (col >> 1)] = f2toh2(v2, v3);
        }

        if (is_e) {
            int row = tid >> 2, part = tid & 3;
            float s = 0.f;
            #pragma unroll
            for (int i = 0; i < 16; i++)
                s += __uint_as_float(Xs[row * XS_STRIDE + part * 16 + i]) * wd[part * 16 + i];
            s += __shfl_xor_sync(FULL, s, 1);
            s += __shfl_xor_sync(FULL, s, 2);
            if (part == 0) a.Odisc[r0 + row] = 1.f / (1.f + __expf(-(s + __ldg(a.bd))));
        }
    } else if (b < G_MMA + G_KNO) {
        float* Ws = (float*)dsm;
        float* Xs = Ws + 8192;
        int r0 = (b - G_MMA) * 8;
        const float4* W4 = (const float4*)a.Wk;
        float4* Ws4 = (float4*)Ws;
        #pragma unroll
        for (int i = 0; i < 8; i++) Ws4[tid + i * 256] = W4[tid + i * 256];
        if (tid < 128) {
            int rr = tid >> 4;
            int c4 = tid & 15;
            int r = r0 + rr;
            float4 v = make_float4(0.f, 0.f, 0.f, 0.f);
            if (r < K_N) {
                size_t o = ((size_t)r << 4) + c4;
                float4 a0 = __ldg((const float4*)a.xk0 + o);
                float4 a1 = h4tof4(__ldg(a.xk1 + o));
                float4 a2 = h4tof4(__ldg(a.xk2 + o));
                float4 a3 = h4tof4(__ldg(a.xk3 + o));
                v.x = 0.25f * (a0.x + a1.x + a2.x + a3.x);
                v.y = 0.25f * (a0.y + a1.y + a2.y + a3.y);
                v.z = 0.25f * (a0.z + a1.z + a2.z + a3.z);
                v.w = 0.25f * (a0.w + a1.w + a2.w + a3.w);
            }
            ((float4*)&Xs[rr * 64])[c4] = v;
        }
        __syncthreads();
        int col = tid & 127;
        int rbase = tid >> 7;
        float bv = __ldg(a.bk + col);
        #pragma unroll
        for (int rr = 0; rr < 4; rr++) {
            int lrow = rr * 2 + rbase;
            int r = r0 + lrow;
            if (r >= K_N) continue;
            float acc = bv;
            #pragma unroll
            for (int i = 0; i < 64; i++) acc = fmaf(Xs[lrow * 64 + i], Ws[i * 128 + col], acc);
            float rv = (acc > 0.f) ? acc : LEAK_F * acc;
            a.Okt[(size_t)r * 128 + col] = rv;
            a.Bt16[(size_t)r * 128 + col] = __float2half_rn(rv);
        }
    } else {
        int t = (b - G_MMA - G_KNO) * 256 + tid;
        int bi = t >> 4, q = t & 15;
        ((float4*)a.Oimp)[((size_t)bi << 4) + q] =
            __ldg((const float4*)a.imp + ((size_t)__ldg(a.eid + bi) << 4) + q);
    }
}

// ---------------- fp16 tensor-core big GEMM (128x128 tile, whole-K in smem) ----------------
#define SMH 68                           // words per smem row (64 data + 4 pad)
#define HG_W (128 * SMH)
#define HGEMM_SMEM_BYTES (3 * HG_W * 4)  // 104448

__device__ __forceinline__ void cp16(uint32_t dst, const void* src) {
    asm volatile("cp.async.cg.shared.global [%0], [%1], 16;" :: "r"(dst), "l"(src));
}

__global__ void __launch_bounds__(256, 1) big_gemm_f16_dual(
    const uint32_t* __restrict__ A1h, const uint32_t* __restrict__ A2h,
    const uint32_t* __restrict__ Bh, float* __restrict__ O1, float* __restrict__ O2) {
    extern __shared__ uint32_t sm[];
    uint32_t sbase = (uint32_t)__cvta_generic_to_shared(sm);
    const uint32_t* A1s = sm;
    const uint32_t* A2s = sm + HG_W;
    const uint32_t* Bs  = sm + 2 * HG_W;

    int tid = threadIdx.x;
    int warp = tid >> 5;
    int lane = tid & 31;
    int g = lane >> 2;
    int tg = lane & 3;
    int wm = warp >> 1;
    int wn = warp & 1;
    int m0 = blockIdx.x * 128;
    int n0 = blockIdx.y * 128;

    // load entire K=128 tiles (64 words/row) via cp.async
    #pragma unroll
    for (int i = 0; i < 8; i++) {
        int idx = tid + i * 256;          // 0..2047
        int row = idx >> 4, q = idx & 15; // q*4 in 0..60
        uint32_t off = (uint32_t)(row * SMH + q * 4) * 4;
        cp16(sbase + off,                A1h + (size_t)(m0 + row) * 64 + q * 4);
        cp16(sbase + HG_W * 4 + off,     A2h + (size_t)(m0 + row) * 64 + q * 4);
        cp16(sbase + 2 * HG_W * 4 + off, Bh + (size_t)(n0 + row) * 64 + q * 4);
    }
    asm volatile("cp.async.commit_group;");
    asm volatile("cp.async.wait_group 0;");
    __syncthreads();

    float acc1[2][8][4] = {};
    float acc2[2][8][4] = {};

    #pragma unroll
    for (int ks = 0; ks < 8; ks++) {
        int w0 = ks * 8;                  // word offset (16 halfs per k-step)
        uint32_t b[8][2];
        #pragma unroll
        for (int nt = 0; nt < 8; nt++) {
            const uint32_t* bp = &Bs[(wn * 64 + nt * 8 + g) * SMH + w0 + tg];
            b[nt][0] = bp[0];
            b[nt][1] = bp[4];
        }
        #pragma unroll
        for (int mt = 0; mt < 2; mt++) {
            uint32_t a[4];
            const uint32_t* ap = &A1s[(wm * 32 + mt * 16 + g) * SMH + w0 + tg];
            a[0] = ap[0]; a[1] = ap[8 * SMH]; a[2] = ap[4]; a[3] = ap[8 * SMH + 4];
            #pragma unroll
            for (int nt = 0; nt < 8; nt++) MMA_F16(acc1[mt][nt], a, b[nt]);
            ap = &A2s[(wm * 32 + mt * 16 + g) * SMH + w0 + tg];
            a[0] = ap[0]; a[1] = ap[8 * SMH]; a[2] = ap[4]; a[3] = ap[8 * SMH + 4];
            #pragma unroll
            for (int nt = 0; nt < 8; nt++) MMA_F16(acc2[mt][nt], a, b[nt]);
        }
    }

    #pragma unroll
    for (int mt = 0; mt < 2; mt++) {
        #pragma unroll
        for (int nt = 0; nt < 8; nt++) {
            int col = n0 + wn * 64 + nt * 8 + tg * 2;
            if (col >= K_N) continue;
            size_t r0 = (size_t)(m0 + wm * 32 + mt * 16 + g);
            size_t r1 = r0 + 8;
            *(float2*)(O1 + r0 * K_N + col) = make_float2(acc1[mt][nt][0], acc1[mt][nt][1]);
            *(float2*)(O1 + r1 * K_N + col) = make_float2(acc1[mt][nt][2], acc1[mt][nt][3]);
            *(float2*)(O2 + r0 * K_N + col) = make_float2(acc2[mt][nt][0], acc2[mt][nt][1]);
            *(float2*)(O2 + r1 * K_N + col) = make_float2(acc2[mt][nt][2], acc2[mt][nt][3]);
        }
    }
}

// ---------------- host orchestration ----------------
extern "C" void kernel_launch(void* const* d_in, const int* in_sizes, int n_in,
                              void* d_out, int out_size) {
    (void)in_sizes; (void)n_in; (void)out_size;
    const int*   student_id  = (const int*)d_in[0];
    const int*   exercise_id = (const int*)d_in[1];
    const float* stu_emb     = (const float*)d_in[3];
    const float* exer_emb    = (const float*)d_in[4];
    const float* know_emb    = (const float*)d_in[5];
    const float* impact_emb  = (const float*)d_in[6];
    const int*   s_rows = (const int*)d_in[7];
    const int*   s_cols = (const int*)d_in[8];
    const float* s_vals = (const float*)d_in[9];
    const int*   e_rows = (const int*)d_in[10];
    const int*   e_cols = (const int*)d_in[11];
    const float* e_vals = (const float*)d_in[12];
    const int*   k_rows = (const int*)d_in[13];
    const int*   k_cols = (const int*)d_in[14];
    const float* k_vals = (const float*)d_in[15];
    const float* W_stu  = (const float*)d_in[16];
    const float* b_stu  = (const float*)d_in[17];
    const float* W_exer = (const float*)d_in[18];
    const float* b_exer = (const float*)d_in[19];
    const float* W_know = (const float*)d_in[20];
    const float* b_know = (const float*)d_in[21];
    const float* W_disc = (const float*)d_in[22];
    const float* b_disc = (const float*)d_in[23];

    unsigned char* A = nullptr;
    cudaGetSymbolAddress((void**)&A, g_arena);

    int*  rp_s  = (int*)(A + O_RP_S);
    int*  rp_e  = (int*)(A + O_RP_E);
    int*  rp_k  = (int*)(A + O_RP_K);
    unsigned long long* lk = (unsigned long long*)(A + O_LK);
    int*  cur_s = (int*)(A + O_CUR_S);
    int*  cur_e = (int*)(A + O_CUR_E);
    int*  cur_k = (int*)(A + O_CUR_K);
    int*  loc   = (int*)(A + O_LOC);
    int2* pairs_s = (int2*)(A + O_PAIRS_S);
    int2* pairs_e = (int2*)(A + O_PAIRS_E);
    int2* pairs_k = (int2*)(A + O_PAIRS_K);
    uint2* e16_s = (uint2*)(A + O_E16_S);
    uint2* e16_e = (uint2*)(A + O_E16_E);
    uint2* e16_k = (uint2*)(A + O_E16_K);
    uint2* x1_s = (uint2*)(A + O_X1_S);
    uint2* x2_s = (uint2*)(A + O_X2_S);
    uint2* x1_e = (uint2*)(A + O_X1_E);
    uint2* x2_e = (uint2*)(A + O_X2_E);
    uint2* x1_k = (uint2*)(A + O_X1_K);
    uint2* x2_k = (uint2*)(A + O_X2_K);
    uint2* x3_k = (uint2*)(A + O_X3_K);
    uint2* xg_s = (uint2*)(A + O_XG_S);
    uint2* xg_e = (uint2*)(A + O_XG_E);
    uint32_t* A1h = (uint32_t*)(A + O_A1);
    uint32_t* A2h = (uint32_t*)(A + O_A2);
    __half* Bt16 = (__half*)(A + O_BT16);

    // 1) init (zero + fp16 embedding convert) + CSR build
    init_kernel<<<(INIT_TOT + 255) / 256, 256>>>(
        (int*)A, (uint32_t*)(Bt16 + (size_t)K_N * 128),
        (const float4*)stu_emb, (const float4*)exer_emb, (const float4*)know_emb,
        (uint4*)e16_s, (uint4*)e16_e, (uint4*)e16_k);
    hist_all_kernel<<<(Q4_TOT + 255) / 256, 256>>>(
        (const int4*)s_rows, (const int4*)e_rows, (const int4*)k_rows,
        rp_s, rp_e, rp_k, (int4*)loc);
    scan_lookback_kernel<<<NB_TOT, 256>>>(rp_s, rp_e, rp_k, cur_s, cur_e, cur_k, lk);
    scatter_all_kernel<<<(Q4_TOT + 255) / 256, 256>>>(
        (const int4*)s_rows, (const int4*)s_cols, (const float4*)s_vals,
        (const int4*)e_rows, (const int4*)e_cols, (const float4*)e_vals,
        (const int4*)k_rows, (const int4*)k_cols, (const float4*)k_vals,
        cur_s, cur_e, cur_k, (const int4*)loc, pairs_s, pairs_e, pairs_k);

    // 2) layers 1-2 full (fp16 storage); layer 3 batch-restricted + full know
    const uint2* in_s[3] = {e16_s, x1_s, x2_s};
    const uint2* in_e[3] = {e16_e, x1_e, x2_e};
    const uint2* in_k[3] = {e16_k, x1_k, x2_k};
    uint2* out_s[2] = {x1_s, x2_s};
    uint2* out_e[2] = {x1_e, x2_e};
    uint2* out_k[2] = {x1_k, x2_k};
    for (int l = 0; l < 2; l++) {
        SpmmArgs sa;
        sa.rp[0] = rp_s;  sa.rp[1] = rp_e;  sa.rp[2] = rp_k;
        sa.pr[0] = pairs_s; sa.pr[1] = pairs_e; sa.pr[2] = pairs_k;
        sa.xin[0] = in_s[l]; sa.xin[1] = in_e[l]; sa.xin[2] = in_k[l];
        sa.xout[0] = out_s[l]; sa.xout[1] = out_e[l]; sa.xout[2] = out_k[l];
        sa.nrows[0] = S_N; sa.nrows[1] = E_N; sa.nrows[2] = K_N;
        spmm_all_kernel<<<GB_S + GB_E + GB_K, 256>>>(sa);
    }
    {
        Spmm3Args a3;
        a3.rp_s = rp_s; a3.pr_s = pairs_s; a3.x2_s = x2_s; a3.xg_s = xg_s; a3.sid = student_id;
        a3.rp_e = rp_e; a3.pr_e = pairs_e; a3.x2_e = x2_e; a3.xg_e = xg_e; a3.eid = exercise_id;
        a3.rp_k = rp_k; a3.pr_k = pairs_k; a3.x2_k = x2_k; a3.x3_k = x3_k;
        spmm_l3_kernel<<<GL_S + GL_E + GL_K, 256>>>(a3);
    }

    // 3) output layout
    float* out   = (float*)d_out;
    float* O1    = out;
    float* O2    = O1 + (size_t)B_N * K_N;
    float* Odisc = O2 + (size_t)B_N * K_N;
    float* Okt   = Odisc + B_N;
    float* Oimp  = Okt + (size_t)K_N * FF;

    // 4) unified dense stage
    static bool attr_set = false;
    if (!attr_set) {
        cudaFuncSetAttribute(dense_all_kernel,
                             cudaFuncAttributeMaxDynamicSharedMemorySize, DM_SMEM_BYTES);
        cudaFuncSetAttribute(big_gemm_f16_dual,
                             cudaFuncAttributeMaxDynamicSharedMemorySize, HGEMM_SMEM_BYTES);
        attr_set = true;
    }
    {
        DenseArgs da;
        da.x0s = stu_emb;  da.x1s = x1_s; da.x2s = x2_s; da.x3s = xg_s;
        da.x0e = exer_emb; da.x1e = x1_e; da.x2e = x2_e; da.x3e = xg_e;
        da.xk0 = know_emb; da.xk1 = x1_k; da.xk2 = x2_k; da.xk3 = x3_k;
        da.sid = student_id; da.eid = exercise_id;
        da.Ws = W_stu; da.bs = b_stu; da.We = W_exer; da.be = b_exer;
        da.Wk = W_know; da.bk = b_know; da.Wd = W_disc; da.bd = b_disc;
        da.imp = impact_emb;
        da.A1h = A1h; da.A2h = A2h; da.Bt16 = Bt16;
        da.Okt = Okt; da.Odisc = Odisc; da.Oimp = Oimp;
        dense_all_kernel<<<G_DENSE, 256, DM_SMEM_BYTES>>>(da);
    }

    // 5) fp16 big GEMM pair
    dim3 grid(B_N / 128, 1024 / 128);
    big_gemm_f16_dual<<<grid, 256, HGEMM_SMEM_BYTES>>>(
        A1h, A2h, (const uint32_t*)Bt16, O1, O2);
}

// round 13
// speedup vs baseline: 1.7409x; 1.1035x over previous
#include <cuda_runtime.h>
#include <cuda_fp16.h>
#include <cstdint>
#include <cstddef>

#define S_N 100000
#define E_N 30000
#define K_N 1000
#define DD 64
#define FF 128
#define B_N 16384
#define NNZ_S 1600000
#define NNZ_E 480000
#define NNZ_K 32000
#define NNZ_TOT (NNZ_S + NNZ_E + NNZ_K)
#define MOM 0.9f
#define LEAK_F 0.1f

#define NB_S 98
#define NB_E 30
#define NB_K 1
#define NB_TOT (NB_S + NB_E + NB_K)

#define PNB 740   // 148 SMs x 5 blocks (guaranteed resident via __launch_bounds__(256,5))

static constexpr size_t al256(size_t x) { return (x + 255) & ~(size_t)255; }

// ---------------- static scratch arena ----------------
static constexpr size_t O_RP_S = 0;
static constexpr size_t O_RP_E = O_RP_S + (size_t)(S_N + 1) * 4;
static constexpr size_t O_RP_K = O_RP_E + (size_t)(E_N + 1) * 4;
static constexpr size_t RP_END = O_RP_K + (size_t)(K_N + 1) * 4;
static constexpr size_t O_LK   = al256(RP_END);
static constexpr size_t LK_END = O_LK + (size_t)NB_TOT * 8;
static constexpr int    ZERO_INTS = (int)(LK_END / 4);

static constexpr size_t O_CUR_S = al256(LK_END);
static constexpr size_t O_CUR_E = al256(O_CUR_S + (size_t)S_N * 4);
static constexpr size_t O_CUR_K = al256(O_CUR_E + (size_t)E_N * 4);
static constexpr size_t O_LOC   = al256(O_CUR_K + (size_t)K_N * 4);
static constexpr size_t O_PAIRS_S = al256(O_LOC + (size_t)NNZ_TOT * 4);
static constexpr size_t O_PAIRS_E = al256(O_PAIRS_S + (size_t)NNZ_S * 8);
static constexpr size_t O_PAIRS_K = al256(O_PAIRS_E + (size_t)NNZ_E * 8);
static constexpr size_t O_E16_S = al256(O_PAIRS_K + (size_t)NNZ_K * 8);
static constexpr size_t O_E16_E = al256(O_E16_S + (size_t)S_N * DD * 2);
static constexpr size_t O_E16_K = al256(O_E16_E + (size_t)E_N * DD * 2);
static constexpr size_t O_X1_S  = al256(O_E16_K + (size_t)K_N * DD * 2);
static constexpr size_t O_X2_S  = al256(O_X1_S + (size_t)S_N * DD * 2);
static constexpr size_t O_X1_E  = al256(O_X2_S + (size_t)S_N * DD * 2);
static constexpr size_t O_X2_E  = al256(O_X1_E + (size_t)E_N * DD * 2);
static constexpr size_t O_X1_K  = al256(O_X2_E + (size_t)E_N * DD * 2);
static constexpr size_t O_X2_K  = al256(O_X1_K + (size_t)K_N * DD * 2);
static constexpr size_t O_X3_K  = al256(O_X2_K + (size_t)K_N * DD * 2);
static constexpr size_t O_XG_S  = al256(O_X3_K + (size_t)K_N * DD * 2);
static constexpr size_t O_XG_E  = al256(O_XG_S + (size_t)B_N * DD * 2);
static constexpr size_t O_A1    = al256(O_XG_E + (size_t)B_N * DD * 2);
static constexpr size_t O_A2    = al256(O_A1 + (size_t)B_N * FF * 2);
static constexpr size_t O_BT16  = al256(O_A2 + (size_t)B_N * FF * 2);
static constexpr size_t ARENA_BYTES = al256(O_BT16 + (size_t)1024 * FF * 2);

__device__ __align__(256) unsigned char g_arena[ARENA_BYTES];

// barrier counters (zero-initialized at module load; invariantly restored to 0 each run)
__device__ int g_bar_csr[3];
__device__ int g_bar_spmm[2];

// ---------------- software grid barrier (all PNB blocks resident) ----------------
__device__ __forceinline__ void gbar(int* cnt, int nb) {
    __syncthreads();
    if (threadIdx.x == 0) {
        __threadfence();
        atomicAdd(cnt, 1);
        while (*(volatile int*)cnt < nb) { }
        __threadfence();
    }
    __syncthreads();
}

// ---------------- half<->float helpers ----------------
__device__ __forceinline__ float4 h4tof4(uint2 h) {
    __half2 a = *(__half2*)&h.x;
    __half2 b = *(__half2*)&h.y;
    float2 fa = __half22float2(a), fb = __half22float2(b);
    return make_float4(fa.x, fa.y, fb.x, fb.y);
}
__device__ __forceinline__ uint2 f4toh4(float4 f) {
    __half2 a = __floats2half2_rn(f.x, f.y);
    __half2 b = __floats2half2_rn(f.z, f.w);
    uint2 r;
    r.x = *(uint32_t*)&a;
    r.y = *(uint32_t*)&b;
    return r;
}
__device__ __forceinline__ uint32_t f2toh2(float a, float b) {
    __half2 h = __floats2half2_rn(a, b);
    return *(uint32_t*)&h;
}

#define BT16_PAD_WORDS (24 * 128 / 2)
#define N8_S (S_N * DD / 8)
#define N8_E (E_N * DD / 8)
#define N8_K (K_N * DD / 8)
#define N8_TOT (N8_S + N8_E + N8_K)
#define INIT_TOT (ZERO_INTS + BT16_PAD_WORDS + N8_TOT)

#define Q4_S (NNZ_S / 4)
#define Q4_E (NNZ_E / 4)
#define Q4_K (NNZ_K / 4)
#define Q4_TOT (Q4_S + Q4_E + Q4_K)

// ---------------- persistent CSR build: init | hist | scan | scatter ----------------
struct CsrArgs {
    const int4 *s_rows, *s_cols; const float4 *s_vals;
    const int4 *e_rows, *e_cols; const float4 *e_vals;
    const int4 *k_rows, *k_cols; const float4 *k_vals;
    int *rp_s, *rp_e, *rp_k;
    int *cur_s, *cur_e, *cur_k;
    int4 *loc;
    int2 *pairs_s, *pairs_e, *pairs_k;
    unsigned long long* lk;
    uint32_t* bt_pad;
    const float4 *es, *ee, *ek;
    uint4 *s16, *e16, *k16;
    int* zero_base;
};

__global__ void __launch_bounds__(256, 5) csr_build_kernel(CsrArgs a) {
    int tid = threadIdx.x;
    int gid0 = blockIdx.x * 256 + tid;

    // P0: zero rowptrs+lk + Bt16 pad, convert embeddings to fp16
    for (int i = gid0; i < INIT_TOT; i += PNB * 256) {
        if (i < ZERO_INTS) { a.zero_base[i] = 0; continue; }
        if (i < ZERO_INTS + BT16_PAD_WORDS) { a.bt_pad[i - ZERO_INTS] = 0u; continue; }
        int c = i - ZERO_INTS - BT16_PAD_WORDS;
        const float4* src; uint4* dst; int j;
        if (c < N8_S)             { src = a.es; dst = a.s16; j = c; }
        else if (c < N8_S + N8_E) { src = a.ee; dst = a.e16; j = c - N8_S; }
        else                      { src = a.ek; dst = a.k16; j = c - N8_S - N8_E; }
        float4 x = __ldg(src + 2 * j);
        float4 y = __ldg(src + 2 * j + 1);
        uint2 hx = f4toh4(x), hy = f4toh4(y);
        dst[j] = make_uint4(hx.x, hx.y, hy.x, hy.y);
    }
    gbar(&g_bar_csr[0], PNB);

    // P1: histogram (emits within-row ranks)
    for (int i = gid0; i < Q4_TOT; i += PNB * 256) {
        int4 r; int* rp; int4* lp = a.loc + i;
        if (i < Q4_S)             { r = __ldg(a.s_rows + i); rp = a.rp_s; }
        else if (i < Q4_S + Q4_E) { r = __ldg(a.e_rows + (i - Q4_S)); rp = a.rp_e; }
        else                      { r = __ldg(a.k_rows + (i - Q4_S - Q4_E)); rp = a.rp_k; }
        int4 l;
        l.x = atomicAdd(&rp[r.x + 1], 1);
        l.y = atomicAdd(&rp[r.y + 1], 1);
        l.z = atomicAdd(&rp[r.z + 1], 1);
        l.w = atomicAdd(&rp[r.w + 1], 1);
        *lp = l;
    }
    gbar(&g_bar_csr[1], PNB);
    if (blockIdx.x == 0 && tid == 0) g_bar_csr[0] = 0;   // safe: all passed BAR0

    // P2: single-pass decoupled-lookback scan (first NB_TOT blocks)
    if (blockIdx.x < NB_TOT) {
        __shared__ int wsum[8];
        __shared__ int s_excl;
        const unsigned FULL = 0xFFFFFFFFu;
        int b = blockIdx.x, lane = tid & 31, wid = tid >> 5;
        int *x, *c, n, lb;
        if (b < NB_S)             { x = a.rp_s; c = a.cur_s; n = S_N + 1; lb = b; }
        else if (b < NB_S + NB_E) { x = a.rp_e; c = a.cur_e; n = E_N + 1; lb = b - NB_S; }
        else                      { x = a.rp_k; c = a.cur_k; n = K_N + 1; lb = b - NB_S - NB_E; }
        int base = lb * 1024 + tid * 4;
        int v0 = (base     < n) ? x[base]     : 0;
        int v1 = (base + 1 < n) ? x[base + 1] : 0;
        int v2 = (base + 2 < n) ? x[base + 2] : 0;
        int v3 = (base + 3 < n) ? x[base + 3] : 0;
        v1 += v0; v2 += v1; v3 += v2;
        int tin = v3;
        int incl = tin;
        #pragma unroll
        for (int off = 1; off < 32; off <<= 1) {
            int o = __shfl_up_sync(FULL, incl, off);
            if (lane >= off) incl += o;
        }
        if (lane == 31) wsum[wid] = incl;
        __syncthreads();
        if (wid == 0) {
            int ws = (lane < 8) ? wsum[lane] : 0;
            #pragma unroll
            for (int off = 1; off < 8; off <<= 1) {
                int o = __shfl_up_sync(FULL, ws, off);
                if (lane >= off) ws += o;
            }
            if (lane < 8) wsum[lane] = ws;
        }
        __syncthreads();
        int agg = wsum[7];
        int warp_excl = wid ? wsum[wid - 1] : 0;
        int thread_excl = warp_excl + (incl - tin);

        if (wid == 0) {
            volatile unsigned long long* vlk = (volatile unsigned long long*)a.lk;
            if (lb == 0) {
                if (lane == 0) { vlk[b] = (2ULL << 32) | (unsigned)agg; s_excl = 0; }
            } else {
                if (lane == 0) vlk[b] = (1ULL << 32) | (unsigned)agg;
                int gbase = b - lb;
                int running = 0;
                int j = lb - 1;
                while (true) {
                    int idx = j - lane;
                    bool valid = idx >= 0;
                    unsigned long long w = 0; int st = 0;
                    while (true) {
                        if (valid) { w = vlk[gbase + idx]; st = (int)(w >> 32); }
                        if (__all_sync(FULL, !valid || st != 0)) break;
                    }
                    unsigned pm = __ballot_sync(FULL, valid && st == 2);
                    int lane_p = pm ? (__ffs(pm) - 1) : 32;
                    int val = (valid && lane <= lane_p) ? (int)(unsigned)w : 0;
                    #pragma unroll
                    for (int off = 16; off; off >>= 1) val += __shfl_xor_sync(FULL, val, off);
                    running += val;
                    if (lane_p < 32) break;
                    j -= 32;
                }
                if (lane == 0) {
                    vlk[b] = (2ULL << 32) | (unsigned)(running + agg);
                    s_excl = running;
                }
            }
        }
        __syncthreads();
        int off0 = s_excl + thread_excl;
        if (base < n)     { int v = v0 + off0; x[base]     = v; if (base     < n - 1) c[base]     = v; }
        if (base + 1 < n) { int v = v1 + off0; x[base + 1] = v; if (base + 1 < n - 1) c[base + 1] = v; }
        if (base + 2 < n) { int v = v2 + off0; x[base + 2] = v; if (base + 2 < n - 1) c[base + 2] = v; }
        if (base + 3 < n) { int v = v3 + off0; x[base + 3] = v; if (base + 3 < n - 1) c[base + 3] = v; }
    }
    gbar(&g_bar_csr[2], PNB);
    if (blockIdx.x == 0 && tid == 0) g_bar_csr[1] = 0;   // safe: all passed BAR1

    // P3: scatter (atomic-free)
    for (int i = gid0; i < Q4_TOT; i += PNB * 256) {
        int4 r, cidx; float4 v; const int* cur; int2* pairs;
        if (i < Q4_S) {
            r = __ldg(a.s_rows + i); cidx = __ldg(a.s_cols + i); v = __ldg(a.s_vals + i);
            cur = a.cur_s; pairs = a.pairs_s;
        } else if (i < Q4_S + Q4_E) {
            int j = i - Q4_S;
            r = __ldg(a.e_rows + j); cidx = __ldg(a.e_cols + j); v = __ldg(a.e_vals + j);
            cur = a.cur_e; pairs = a.pairs_e;
        } else {
            int j = i - Q4_S - Q4_E;
            r = __ldg(a.k_rows + j); cidx = __ldg(a.k_cols + j); v = __ldg(a.k_vals + j);
            cur = a.cur_k; pairs = a.pairs_k;
        }
        int4 l = __ldg(a.loc + i);
        pairs[__ldg(cur + r.x) + l.x] = make_int2(cidx.x, __float_as_int(v.x));
        pairs[__ldg(cur + r.y) + l.y] = make_int2(cidx.y, __float_as_int(v.y));
        pairs[__ldg(cur + r.z) + l.z] = make_int2(cidx.z, __float_as_int(v.z));
        pairs[__ldg(cur + r.w) + l.w] = make_int2(cidx.w, __float_as_int(v.w));
    }
    // g_bar_csr[2] is reset by spmm3_kernel (runs strictly after this kernel)
}

// ---------------- SpMM core (fp16 x, fp32 accumulate) ----------------
__device__ __forceinline__ float4 spmm_row_h(const int* __restrict__ rowptr,
                                             const int2* __restrict__ pairs,
                                             const uint2* __restrict__ xin, int row, int d4) {
    int beg = __ldg(rowptr + row);
    int end = __ldg(rowptr + row + 1);
    float4 s = make_float4(0.f, 0.f, 0.f, 0.f);
    int j = beg;
    for (; j + 3 < end; j += 4) {
        int2 p0 = __ldg(pairs + j);
        int2 p1 = __ldg(pairs + j + 1);
        int2 p2 = __ldg(pairs + j + 2);
        int2 p3 = __ldg(pairs + j + 3);
        float4 v0 = h4tof4(__ldg(xin + ((size_t)p0.x << 4) + d4));
        float4 v1 = h4tof4(__ldg(xin + ((size_t)p1.x << 4) + d4));
        float4 v2 = h4tof4(__ldg(xin + ((size_t)p2.x << 4) + d4));
        float4 v3 = h4tof4(__ldg(xin + ((size_t)p3.x << 4) + d4));
        float w0 = __int_as_float(p0.y), w1 = __int_as_float(p1.y);
        float w2 = __int_as_float(p2.y), w3 = __int_as_float(p3.y);
        s.x = fmaf(w0, v0.x, s.x); s.y = fmaf(w0, v0.y, s.y); s.z = fmaf(w0, v0.z, s.z); s.w = fmaf(w0, v0.w, s.w);
        s.x = fmaf(w1, v1.x, s.x); s.y = fmaf(w1, v1.y, s.y); s.z = fmaf(w1, v1.z, s.z); s.w = fmaf(w1, v1.w, s.w);
        s.x = fmaf(w2, v2.x, s.x); s.y = fmaf(w2, v2.y, s.y); s.z = fmaf(w2, v2.z, s.z); s.w = fmaf(w2, v2.w, s.w);
        s.x = fmaf(w3, v3.x, s.x); s.y = fmaf(w3, v3.y, s.y); s.z = fmaf(w3, v3.z, s.z); s.w = fmaf(w3, v3.w, s.w);
    }
    for (; j < end; j++) {
        int2 p = __ldg(pairs + j);
        float w = __int_as_float(p.y);
        float4 v = h4tof4(__ldg(xin + ((size_t)p.x << 4) + d4));
        s.x = fmaf(w, v.x, s.x); s.y = fmaf(w, v.y, s.y); s.z = fmaf(w, v.z, s.z); s.w = fmaf(w, v.w, s.w);
    }
    return s;
}

#define GB_S 6250
#define GB_E 1875
#define GB_K 63
#define GB_TOT (GB_S + GB_E + GB_K)
#define GL_S 1024
#define GL_E 1024
#define GL_K 63
#define GL_TOT (GL_S + GL_E + GL_K)

// persistent SpMM: L1 | L2 | L3(batch-restricted)
struct Spmm3Args {
    const int* rp[3];
    const int2* pr[3];
    const uint2* e16[3];    // layer-1 inputs
    uint2* x1[3];
    uint2* x2[3];
    int nrows[3];
    const int *sid, *eid;
    uint2 *xg_s, *xg_e, *x3_k;
};

__device__ __forceinline__ void spmm_layer_v(const Spmm3Args& a, int v,
                                             const uint2* const* xin_arr, uint2* const* xout_arr) {
    int seg, lb;
    if (v < GB_S)             { seg = 0; lb = v; }
    else if (v < GB_S + GB_E) { seg = 1; lb = v - GB_S; }
    else                      { seg = 2; lb = v - GB_S - GB_E; }
    int row = lb * 16 + (threadIdx.x >> 4);
    int d4 = threadIdx.x & 15;
    if (row >= a.nrows[seg]) return;
    const uint2* xin = xin_arr[seg];
    float4 s = spmm_row_h(a.rp[seg], a.pr[seg], xin, row, d4);
    size_t o = ((size_t)row << 4) + d4;
    float4 m = h4tof4(xin[o]);
    s.x += MOM * m.x; s.y += MOM * m.y; s.z += MOM * m.z; s.w += MOM * m.w;
    xout_arr[seg][o] = f4toh4(s);
}

__global__ void __launch_bounds__(256, 5) spmm3_kernel(Spmm3Args a) {
    if (blockIdx.x == 0 && threadIdx.x == 0) g_bar_csr[2] = 0;  // reset csr's final barrier
    // L1: e16 -> x1
    for (int v = blockIdx.x; v < GB_TOT; v += PNB)
        spmm_layer_v(a, v, a.e16, a.x1);
    gbar(&g_bar_spmm[0], PNB);
    // L2: x1 -> x2
    for (int v = blockIdx.x; v < GB_TOT; v += PNB)
        spmm_layer_v(a, v, (const uint2* const*)a.x1, a.x2);
    gbar(&g_bar_spmm[1], PNB);
    if (blockIdx.x == 0 && threadIdx.x == 0) g_bar_spmm[0] = 0;
    // L3: batch-restricted stu/exer + full know
    int d4 = threadIdx.x & 15;
    int lr = threadIdx.x >> 4;
    for (int v = blockIdx.x; v < GL_TOT; v += PNB) {
        if (v < GL_S) {
            int r = v * 16 + lr;
            int row = __ldg(a.sid + r);
            float4 s = spmm_row_h(a.rp[0], a.pr[0], a.x2[0], row, d4);
            float4 m = h4tof4(a.x2[0][((size_t)row << 4) + d4]);
            s.x += MOM * m.x; s.y += MOM * m.y; s.z += MOM * m.z; s.w += MOM * m.w;
            a.xg_s[((size_t)r << 4) + d4] = f4toh4(s);
        } else if (v < GL_S + GL_E) {
            int r = (v - GL_S) * 16 + lr;
            int row = __ldg(a.eid + r);
            float4 s = spmm_row_h(a.rp[1], a.pr[1], a.x2[1], row, d4);
            float4 m = h4tof4(a.x2[1][((size_t)row << 4) + d4]);
            s.x += MOM * m.x; s.y += MOM * m.y; s.z += MOM * m.z; s.w += MOM * m.w;
            a.xg_e[((size_t)r << 4) + d4] = f4toh4(s);
        } else {
            int row = (v - GL_S - GL_E) * 16 + lr;
            if (row >= K_N) continue;
            float4 s = spmm_row_h(a.rp[2], a.pr[2], a.x2[2], row, d4);
            float4 m = h4tof4(a.x2[2][((size_t)row << 4) + d4]);
            s.x += MOM * m.x; s.y += MOM * m.y; s.z += MOM * m.z; s.w += MOM * m.w;
            a.x3_k[((size_t)row << 4) + d4] = f4toh4(s);
        }
    }
    // g_bar_spmm[1] reset by dense_all_kernel
}

// ---------------- tf32 helper / MMA macros ----------------
__device__ __forceinline__ uint32_t f2tf32(float f) {
    uint32_t u;
    asm("cvt.rna.tf32.f32 %0, %1;" : "=r"(u) : "f"(f));
    return u;
}

#define MMA_TF32(d, a, b)                                                     \
    asm volatile(                                                             \
        "mma.sync.aligned.m16n8k8.row.col.f32.tf32.tf32.f32 "                 \
        "{%0,%1,%2,%3}, {%4,%5,%6,%7}, {%8,%9}, {%0,%1,%2,%3};\n"             \
        : "+f"(d[0]), "+f"(d[1]), "+f"(d[2]), "+f"(d[3])                      \
        : "r"(a[0]), "r"(a[1]), "r"(a[2]), "r"(a[3]), "r"(b[0]), "r"(b[1]))

#define MMA_F16(d, a, b)                                                      \
    asm volatile(                                                             \
        "mma.sync.aligned.m16n8k16.row.col.f32.f16.f16.f32 "                  \
        "{%0,%1,%2,%3}, {%4,%5,%6,%7}, {%8,%9}, {%0,%1,%2,%3};\n"             \
        : "+f"(d[0]), "+f"(d[1]), "+f"(d[2]), "+f"(d[3])                      \
        : "r"(a[0]), "r"(a[1]), "r"(a[2]), "r"(a[3]), "r"(b[0]), "r"(b[1]))

// ---------------- unified dense stage ----------------
#define XS_STRIDE 68
#define WT_STRIDE 68
#define DM_XS_W   (64 * XS_STRIDE)
#define DM_WT_W   (128 * WT_STRIDE)
#define DM_SMEM_BYTES ((DM_XS_W + DM_WT_W + 128 + 64) * 4)
#define G_MMA 512
#define G_KNO 125
#define G_IMP 1024
#define G_DENSE (G_MMA + G_KNO + G_IMP)

struct DenseArgs {
    const float *x0s;  const uint2 *x1s, *x2s, *x3s;
    const float *x0e;  const uint2 *x1e, *x2e, *x3e;
    const float *xk0;  const uint2 *xk1, *xk2, *xk3;
    const int *sid, *eid;
    const float *Ws, *bs, *We, *be, *Wk, *bk, *Wd, *bd;
    const float *imp;
    uint32_t *A1h, *A2h;
    __half *Bt16;
    float *Okt, *Odisc, *Oimp;
};

__global__ void __launch_bounds__(256) dense_all_kernel(DenseArgs a) {
    extern __shared__ uint32_t dsm[];
    const unsigned FULL = 0xFFFFFFFFu;
    int b = blockIdx.x, tid = threadIdx.x;
    if (b == 0 && tid == 0) g_bar_spmm[1] = 0;   // reset spmm's final barrier

    if (b < G_MMA) {
        uint32_t* Xs = dsm;
        uint32_t* Wt = dsm + DM_XS_W;
        float* bsm = (float*)(dsm + DM_XS_W + DM_WT_W);
        float* wd  = bsm + 128;
        bool is_e = b >= 256;
        int r0 = (is_e ? b - 256 : b) * 64;
        const float* x0 = is_e ? a.x0e : a.x0s;
        const uint2* x1 = is_e ? a.x1e : a.x1s;
        const uint2* x2 = is_e ? a.x2e : a.x2s;
        const uint2* x3 = is_e ? a.x3e : a.x3s;
        const int* ids  = is_e ? a.eid : a.sid;
        const float* W  = is_e ? a.We : a.Ws;
        const float* bias = is_e ? a.be : a.bs;
        uint32_t* out = is_e ? a.A2h : a.A1h;

        for (int i = tid; i < 8192; i += 256) {
            int k = i >> 7, n = i & 127;
            Wt[n * WT_STRIDE + k] = f2tf32(__ldg(W + i));
        }
        if (tid < 128) bsm[tid] = __ldg(bias + tid);
        if (is_e && tid < 64) wd[tid] = __ldg(a.Wd + tid);

        for (int i = tid; i < 1024; i += 256) {
            int rr = i >> 4, c4 = i & 15;
            int r = r0 + rr;
            int rid = __ldg(ids + r);
            size_t o  = ((size_t)rid << 4) + c4;
            size_t o3 = ((size_t)r << 4) + c4;
            float4 a0 = __ldg((const float4*)x0 + o);
            float4 a1 = h4tof4(__ldg(x1 + o));
            float4 a2 = h4tof4(__ldg(x2 + o));
            float4 a3 = h4tof4(__ldg(x3 + o3));
            uint4 w;
            w.x = f2tf32(0.25f * (a0.x + a1.x + a2.x + a3.x));
            w.y = f2tf32(0.25f * (a0.y + a1.y + a2.y + a3.y));
            w.z = f2tf32(0.25f * (a0.z + a1.z + a2.z + a3.z));
            w.w = f2tf32(0.25f * (a0.w + a1.w + a2.w + a3.w));
            *(uint4*)&Xs[rr * XS_STRIDE + c4 * 4] = w;
        }
        __syncthreads();

        int warp = tid >> 5, lane = tid & 31, g = lane >> 2, tg = lane & 3;
        int wm = warp >> 1;
        int wn = warp & 1;
        float acc[8][4] = {};
        #pragma unroll
        for (int ks = 0; ks < 8; ks++) {
            int k0 = ks * 8;
            uint32_t A[4];
            const uint32_t* ap = &Xs[(wm * 16 + g) * XS_STRIDE + k0 + tg];
            A[0] = ap[0]; A[1] = ap[8 * XS_STRIDE]; A[2] = ap[4]; A[3] = ap[8 * XS_STRIDE + 4];
            #pragma unroll
            for (int nt = 0; nt < 8; nt++) {
                const uint32_t* bp = &Wt[(wn * 64 + nt * 8 + g) * WT_STRIDE + k0 + tg];
                uint32_t B[2] = {bp[0], bp[4]};
                MMA_TF32(acc[nt], A, B);
            }
        }

        #pragma unroll
        for (int nt = 0; nt < 8; nt++) {
            int col = wn * 64 + nt * 8 + tg * 2;
            float b0 = bsm[col], b1 = bsm[col + 1];
            size_t rA = (size_t)(r0 + wm * 16 + g);
            size_t rB = rA + 8;
            float v0 = acc[nt][0] + b0; v0 = (v0 > 0.f) ? v0 : LEAK_F * v0;
            float v1 = acc[nt][1] + b1; v1 = (v1 > 0.f) ? v1 : LEAK_F * v1;
            float v2 = acc[nt][2] + b0; v2 = (v2 > 0.f) ? v2 : LEAK_F * v2;
            float v3 = acc[nt][3] + b1; v3 = (v3 > 0.f) ? v3 : LEAK_F * v3;
            out[rA * 64 + (col >> 1)] = f2toh2(v0, v1);
            out[rB * 64 + (col >> 1)] = f2toh2(v2, v3);
        }

        if (is_e) {
            int row = tid >> 2, part = tid & 3;
            float s = 0.f;
            #pragma unroll
            for (int i = 0; i < 16; i++)
                s += __uint_as_float(Xs[row * XS_STRIDE + part * 16 + i]) * wd[part * 16 + i];
            s += __shfl_xor_sync(FULL, s, 1);
            s += __shfl_xor_sync(FULL, s, 2);
            if (part == 0) a.Odisc[r0 + row] = 1.f / (1.f + __expf(-(s + __ldg(a.bd))));
        }
    } else if (b < G_MMA + G_KNO) {
        float* Ws = (float*)dsm;
        float* Xs = Ws + 8192;
        int r0 = (b - G_MMA) * 8;
        const float4* W4 = (const float4*)a.Wk;
        float4* Ws4 = (float4*)Ws;
        #pragma unroll
        for (int i = 0; i < 8; i++) Ws4[tid + i * 256] = W4[tid + i * 256];
        if (tid < 128) {
            int rr = tid >> 4;
            int c4 = tid & 15;
            int r = r0 + rr;
            float4 v = make_float4(0.f, 0.f, 0.f, 0.f);
            if (r < K_N) {
                size_t o = ((size_t)r << 4) + c4;
                float4 a0 = __ldg((const float4*)a.xk0 + o);
                float4 a1 = h4tof4(__ldg(a.xk1 + o));
                float4 a2 = h4tof4(__ldg(a.xk2 + o));
                float4 a3 = h4tof4(__ldg(a.xk3 + o));
                v.x = 0.25f * (a0.x + a1.x + a2.x + a3.x);
                v.y = 0.25f * (a0.y + a1.y + a2.y + a3.y);
                v.z = 0.25f * (a0.z + a1.z + a2.z + a3.z);
                v.w = 0.25f * (a0.w + a1.w + a2.w + a3.w);
            }
            ((float4*)&Xs[rr * 64])[c4] = v;
        }
        __syncthreads();
        int col = tid & 127;
        int rbase = tid >> 7;
        float bv = __ldg(a.bk + col);
        #pragma unroll
        for (int rr = 0; rr < 4; rr++) {
            int lrow = rr * 2 + rbase;
            int r = r0 + lrow;
            if (r >= K_N) continue;
            float acc = bv;
            #pragma unroll
            for (int i = 0; i < 64; i++) acc = fmaf(Xs[lrow * 64 + i], Ws[i * 128 + col], acc);
            float rv = (acc > 0.f) ? acc : LEAK_F * acc;
            a.Okt[(size_t)r * 128 + col] = rv;
            a.Bt16[(size_t)r * 128 + col] = __float2half_rn(rv);
        }
    } else {
        int t = (b - G_MMA - G_KNO) * 256 + tid;
        int bi = t >> 4, q = t & 15;
        ((float4*)a.Oimp)[((size_t)bi << 4) + q] =
            __ldg((const float4*)a.imp + ((size_t)__ldg(a.eid + bi) << 4) + q);
    }
}

// ---------------- fp16 tensor-core big GEMM (128x128 tile, whole-K in smem) ----------------
#define SMH 68
#define HG_W (128 * SMH)
#define HGEMM_SMEM_BYTES (3 * HG_W * 4)

__device__ __forceinline__ void cp16(uint32_t dst, const void* src) {
    asm volatile("cp.async.cg.shared.global [%0], [%1], 16;" :: "r"(dst), "l"(src));
}

__global__ void __launch_bounds__(256, 1) big_gemm_f16_dual(
    const uint32_t* __restrict__ A1h, const uint32_t* __restrict__ A2h,
    const uint32_t* __restrict__ Bh, float* __restrict__ O1, float* __restrict__ O2) {
    extern __shared__ uint32_t sm[];
    uint32_t sbase = (uint32_t)__cvta_generic_to_shared(sm);
    const uint32_t* A1s = sm;
    const uint32_t* A2s = sm + HG_W;
    const uint32_t* Bs  = sm + 2 * HG_W;

    int tid = threadIdx.x;
    int warp = tid >> 5;
    int lane = tid & 31;
    int g = lane >> 2;
    int tg = lane & 3;
    int wm = warp >> 1;
    int wn = warp & 1;
    int m0 = blockIdx.x * 128;
    int n0 = blockIdx.y * 128;

    #pragma unroll
    for (int i = 0; i < 8; i++) {
        int idx = tid + i * 256;
        int row = idx >> 4, q = idx & 15;
        uint32_t off = (uint32_t)(row * SMH + q * 4) * 4;
        cp16(sbase + off,                A1h + (size_t)(m0 + row) * 64 + q * 4);
        cp16(sbase + HG_W * 4 + off,     A2h + (size_t)(m0 + row) * 64 + q * 4);
        cp16(sbase + 2 * HG_W * 4 + off, Bh + (size_t)(n0 + row) * 64 + q * 4);
    }
    asm volatile("cp.async.commit_group;");
    asm volatile("cp.async.wait_group 0;");
    __syncthreads();

    float acc1[2][8][4] = {};
    float acc2[2][8][4] = {};

    #pragma unroll
    for (int ks = 0; ks < 8; ks++) {
        int w0 = ks * 8;
        uint32_t b[8][2];
        #pragma unroll
        for (int nt = 0; nt < 8; nt++) {
            const uint32_t* bp = &Bs[(wn * 64 + nt * 8 + g) * SMH + w0 + tg];
            b[nt][0] = bp[0];
            b[nt][1] = bp[4];
        }
        #pragma unroll
        for (int mt = 0; mt < 2; mt++) {
            uint32_t a[4];
            const uint32_t* ap = &A1s[(wm * 32 + mt * 16 + g) * SMH + w0 + tg];
            a[0] = ap[0]; a[1] = ap[8 * SMH]; a[2] = ap[4]; a[3] = ap[8 * SMH + 4];
            #pragma unroll
            for (int nt = 0; nt < 8; nt++) MMA_F16(acc1[mt][nt], a, b[nt]);
            ap = &A2s[(wm * 32 + mt * 16 + g) * SMH + w0 + tg];
            a[0] = ap[0]; a[1] = ap[8 * SMH]; a[2] = ap[4]; a[3] = ap[8 * SMH + 4];
            #pragma unroll
            for (int nt = 0; nt < 8; nt++) MMA_F16(acc2[mt][nt], a, b[nt]);
        }
    }

    #pragma unroll
    for (int mt = 0; mt < 2; mt++) {
        #pragma unroll
        for (int nt = 0; nt < 8; nt++) {
            int col = n0 + wn * 64 + nt * 8 + tg * 2;
            if (col >= K_N) continue;
            size_t r0 = (size_t)(m0 + wm * 32 + mt * 16 + g);
            size_t r1 = r0 + 8;
            *(float2*)(O1 + r0 * K_N + col) = make_float2(acc1[mt][nt][0], acc1[mt][nt][1]);
            *(float2*)(O1 + r1 * K_N + col) = make_float2(acc1[mt][nt][2], acc1[mt][nt][3]);
            *(float2*)(O2 + r0 * K_N + col) = make_float2(acc2[mt][nt][0], acc2[mt][nt][1]);
            *(float2*)(O2 + r1 * K_N + col) = make_float2(acc2[mt][nt][2], acc2[mt][nt][3]);
        }
    }
}

// ---------------- host orchestration ----------------
extern "C" void kernel_launch(void* const* d_in, const int* in_sizes, int n_in,
                              void* d_out, int out_size) {
    (void)in_sizes; (void)n_in; (void)out_size;
    const int*   student_id  = (const int*)d_in[0];
    const int*   exercise_id = (const int*)d_in[1];
    const float* stu_emb     = (const float*)d_in[3];
    const float* exer_emb    = (const float*)d_in[4];
    const float* know_emb    = (const float*)d_in[5];
    const float* impact_emb  = (const float*)d_in[6];
    const int*   s_rows = (const int*)d_in[7];
    const int*   s_cols = (const int*)d_in[8];
    const float* s_vals = (const float*)d_in[9];
    const int*   e_rows = (const int*)d_in[10];
    const int*   e_cols = (const int*)d_in[11];
    const float* e_vals = (const float*)d_in[12];
    const int*   k_rows = (const int*)d_in[13];
    const int*   k_cols = (const int*)d_in[14];
    const float* k_vals = (const float*)d_in[15];
    const float* W_stu  = (const float*)d_in[16];
    const float* b_stu  = (const float*)d_in[17];
    const float* W_exer = (const float*)d_in[18];
    const float* b_exer = (const float*)d_in[19];
    const float* W_know = (const float*)d_in[20];
    const float* b_know = (const float*)d_in[21];
    const float* W_disc = (const float*)d_in[22];
    const float* b_disc = (const float*)d_in[23];

    unsigned char* A = nullptr;
    cudaGetSymbolAddress((void**)&A, g_arena);

    int*  rp_s  = (int*)(A + O_RP_S);
    int*  rp_e  = (int*)(A + O_RP_E);
    int*  rp_k  = (int*)(A + O_RP_K);
    unsigned long long* lk = (unsigned long long*)(A + O_LK);
    int*  cur_s = (int*)(A + O_CUR_S);
    int*  cur_e = (int*)(A + O_CUR_E);
    int*  cur_k = (int*)(A + O_CUR_K);
    int*  loc   = (int*)(A + O_LOC);
    int2* pairs_s = (int2*)(A + O_PAIRS_S);
    int2* pairs_e = (int2*)(A + O_PAIRS_E);
    int2* pairs_k = (int2*)(A + O_PAIRS_K);
    uint2* e16_s = (uint2*)(A + O_E16_S);
    uint2* e16_e = (uint2*)(A + O_E16_E);
    uint2* e16_k = (uint2*)(A + O_E16_K);
    uint2* x1_s = (uint2*)(A + O_X1_S);
    uint2* x2_s = (uint2*)(A + O_X2_S);
    uint2* x1_e = (uint2*)(A + O_X1_E);
    uint2* x2_e = (uint2*)(A + O_X2_E);
    uint2* x1_k = (uint2*)(A + O_X1_K);
    uint2* x2_k = (uint2*)(A + O_X2_K);
    uint2* x3_k = (uint2*)(A + O_X3_K);
    uint2* xg_s = (uint2*)(A + O_XG_S);
    uint2* xg_e = (uint2*)(A + O_XG_E);
    uint32_t* A1h = (uint32_t*)(A + O_A1);
    uint32_t* A2h = (uint32_t*)(A + O_A2);
    __half* Bt16 = (__half*)(A + O_BT16);

    // 1) persistent CSR build (init | hist | scan | scatter)
    {
        CsrArgs ca;
        ca.s_rows = (const int4*)s_rows; ca.s_cols = (const int4*)s_cols; ca.s_vals = (const float4*)s_vals;
        ca.e_rows = (const int4*)e_rows; ca.e_cols = (const int4*)e_cols; ca.e_vals = (const float4*)e_vals;
        ca.k_rows = (const int4*)k_rows; ca.k_cols = (const int4*)k_cols; ca.k_vals = (const float4*)k_vals;
        ca.rp_s = rp_s; ca.rp_e = rp_e; ca.rp_k = rp_k;
        ca.cur_s = cur_s; ca.cur_e = cur_e; ca.cur_k = cur_k;
        ca.loc = (int4*)loc;
        ca.pairs_s = pairs_s; ca.pairs_e = pairs_e; ca.pairs_k = pairs_k;
        ca.lk = lk;
        ca.bt_pad = (uint32_t*)(Bt16 + (size_t)K_N * 128);
        ca.es = (const float4*)stu_emb; ca.ee = (const float4*)exer_emb; ca.ek = (const float4*)know_emb;
        ca.s16 = (uint4*)e16_s; ca.e16 = (uint4*)e16_e; ca.k16 = (uint4*)e16_k;
        ca.zero_base = (int*)A;
        csr_build_kernel<<<PNB, 256>>>(ca);
    }

    // 2) persistent SpMM (L1 | L2 | L3)
    {
        Spmm3Args sa;
        sa.rp[0] = rp_s;  sa.rp[1] = rp_e;  sa.rp[2] = rp_k;
        sa.pr[0] = pairs_s; sa.pr[1] = pairs_e; sa.pr[2] = pairs_k;
        sa.e16[0] = e16_s; sa.e16[1] = e16_e; sa.e16[2] = e16_k;
        sa.x1[0] = x1_s; sa.x1[1] = x1_e; sa.x1[2] = x1_k;
        sa.x2[0] = x2_s; sa.x2[1] = x2_e; sa.x2[2] = x2_k;
        sa.nrows[0] = S_N; sa.nrows[1] = E_N; sa.nrows[2] = K_N;
        sa.sid = student_id; sa.eid = exercise_id;
        sa.xg_s = xg_s; sa.xg_e = xg_e; sa.x3_k = x3_k;
        spmm3_kernel<<<PNB, 256>>>(sa);
    }

    // 3) output layout
    float* out   = (float*)d_out;
    float* O1    = out;
    float* O2    = O1 + (size_t)B_N * K_N;
    float* Odisc = O2 + (size_t)B_N * K_N;
    float* Okt   = Odisc + B_N;
    float* Oimp  = Okt + (size_t)K_N * FF;

    // 4) unified dense stage
    static bool attr_set = false;
    if (!attr_set) {
        cudaFuncSetAttribute(dense_all_kernel,
                             cudaFuncAttributeMaxDynamicSharedMemorySize, DM_SMEM_BYTES);
        cudaFuncSetAttribute(big_gemm_f16_dual,
                             cudaFuncAttributeMaxDynamicSharedMemorySize, HGEMM_SMEM_BYTES);
        attr_set = true;
    }
    {
        DenseArgs da;
        da.x0s = stu_emb;  da.x1s = x1_s; da.x2s = x2_s; da.x3s = xg_s;
        da.x0e = exer_emb; da.x1e = x1_e; da.x2e = x2_e; da.x3e = xg_e;
        da.xk0 = know_emb; da.xk1 = x1_k; da.xk2 = x2_k; da.xk3 = x3_k;
        da.sid = student_id; da.eid = exercise_id;
        da.Ws = W_stu; da.bs = b_stu; da.We = W_exer; da.be = b_exer;
        da.Wk = W_know; da.bk = b_know; da.Wd = W_disc; da.bd = b_disc;
        da.imp = impact_emb;
        da.A1h = A1h; da.A2h = A2h; da.Bt16 = Bt16;
        da.Okt = Okt; da.Odisc = Odisc; da.Oimp = Oimp;
        dense_all_kernel<<<G_DENSE, 256, DM_SMEM_BYTES>>>(da);
    }

    // 5) fp16 big GEMM pair
    dim3 grid(B_N / 128, 1024 / 128);
    big_gemm_f16_dual<<<grid, 256, HGEMM_SMEM_BYTES>>>(
        A1h, A2h, (const uint32_t*)Bt16, O1, O2);
}

// round 14
// speedup vs baseline: 1.7709x; 1.0172x over previous
#include <cuda_runtime.h>
#include <cuda_fp16.h>
#include <cstdint>
#include <cstddef>

#define S_N 100000
#define E_N 30000
#define K_N 1000
#define DD 64
#define FF 128
#define B_N 16384
#define NNZ_S 1600000
#define NNZ_E 480000
#define NNZ_K 32000
#define NNZ_TOT (NNZ_S + NNZ_E + NNZ_K)
#define MOM 0.9f
#define LEAK_F 0.1f

#define NB_S 98
#define NB_E 30
#define NB_K 1
#define NB_TOT (NB_S + NB_E + NB_K)

#define PNB 740   // 148 SMs x 5 blocks (resident via __launch_bounds__(256,5))

static constexpr size_t al256(size_t x) { return (x + 255) & ~(size_t)255; }

// ---------------- static scratch arena ----------------
static constexpr size_t O_RP_S = 0;
static constexpr size_t O_RP_E = O_RP_S + (size_t)(S_N + 1) * 4;
static constexpr size_t O_RP_K = O_RP_E + (size_t)(E_N + 1) * 4;
static constexpr size_t RP_END = O_RP_K + (size_t)(K_N + 1) * 4;
static constexpr size_t O_LK   = al256(RP_END);
static constexpr size_t LK_END = O_LK + (size_t)NB_TOT * 8;
static constexpr int    ZERO_INTS = (int)(LK_END / 4);

static constexpr size_t O_CUR_S = al256(LK_END);
static constexpr size_t O_CUR_E = al256(O_CUR_S + (size_t)S_N * 4);
static constexpr size_t O_CUR_K = al256(O_CUR_E + (size_t)E_N * 4);
static constexpr size_t O_LOC   = al256(O_CUR_K + (size_t)K_N * 4);
static constexpr size_t O_PAIRS_S = al256(O_LOC + (size_t)NNZ_TOT * 4);
static constexpr size_t O_PAIRS_E = al256(O_PAIRS_S + (size_t)NNZ_S * 8);
static constexpr size_t O_PAIRS_K = al256(O_PAIRS_E + (size_t)NNZ_E * 8);
static constexpr size_t O_E16_S = al256(O_PAIRS_K + (size_t)NNZ_K * 8);
static constexpr size_t O_E16_E = al256(O_E16_S + (size_t)S_N * DD * 2);
static constexpr size_t O_E16_K = al256(O_E16_E + (size_t)E_N * DD * 2);
static constexpr size_t O_X1_S  = al256(O_E16_K + (size_t)K_N * DD * 2);
static constexpr size_t O_X2_S  = al256(O_X1_S + (size_t)S_N * DD * 2);
static constexpr size_t O_X1_E  = al256(O_X2_S + (size_t)S_N * DD * 2);
static constexpr size_t O_X2_E  = al256(O_X1_E + (size_t)E_N * DD * 2);
static constexpr size_t O_X1_K  = al256(O_X2_E + (size_t)E_N * DD * 2);
static constexpr size_t O_X2_K  = al256(O_X1_K + (size_t)K_N * DD * 2);
static constexpr size_t O_X3_K  = al256(O_X2_K + (size_t)K_N * DD * 2);
static constexpr size_t O_XG_S  = al256(O_X3_K + (size_t)K_N * DD * 2);
static constexpr size_t O_XG_E  = al256(O_XG_S + (size_t)B_N * DD * 2);
static constexpr size_t O_A1    = al256(O_XG_E + (size_t)B_N * DD * 2);
static constexpr size_t O_A2    = al256(O_A1 + (size_t)B_N * FF * 2);
static constexpr size_t O_BT16  = al256(O_A2 + (size_t)B_N * FF * 2);
static constexpr size_t ARENA_BYTES = al256(O_BT16 + (size_t)1024 * FF * 2);

__device__ __align__(256) unsigned char g_arena[ARENA_BYTES];

__device__ int g_bar_csr[3];
__device__ int g_bar_spmm[2];

__device__ __forceinline__ void gbar(int* cnt, int nb) {
    __syncthreads();
    if (threadIdx.x == 0) {
        __threadfence();
        atomicAdd(cnt, 1);
        while (*(volatile int*)cnt < nb) { }
        __threadfence();
    }
    __syncthreads();
}

// ---------------- half<->float helpers ----------------
__device__ __forceinline__ float4 h4tof4(uint2 h) {
    __half2 a = *(__half2*)&h.x;
    __half2 b = *(__half2*)&h.y;
    float2 fa = __half22float2(a), fb = __half22float2(b);
    return make_float4(fa.x, fa.y, fb.x, fb.y);
}
__device__ __forceinline__ uint2 f4toh4(float4 f) {
    __half2 a = __floats2half2_rn(f.x, f.y);
    __half2 b = __floats2half2_rn(f.z, f.w);
    uint2 r;
    r.x = *(uint32_t*)&a;
    r.y = *(uint32_t*)&b;
    return r;
}
__device__ __forceinline__ uint32_t f2toh2(float a, float b) {
    __half2 h = __floats2half2_rn(a, b);
    return *(uint32_t*)&h;
}

#define BT16_PAD_WORDS (24 * 128 / 2)
#define N8_S (S_N * DD / 8)
#define N8_E (E_N * DD / 8)
#define N8_K (K_N * DD / 8)
#define N8_TOT (N8_S + N8_E + N8_K)
#define INIT_TOT (ZERO_INTS + BT16_PAD_WORDS + N8_TOT)

#define Q4_S (NNZ_S / 4)
#define Q4_E (NNZ_E / 4)
#define Q4_K (NNZ_K / 4)
#define Q4_TOT (Q4_S + Q4_E + Q4_K)

// ---------------- persistent CSR build: init | hist | scan | scatter ----------------
struct CsrArgs {
    const int4 *s_rows, *s_cols; const float4 *s_vals;
    const int4 *e_rows, *e_cols; const float4 *e_vals;
    const int4 *k_rows, *k_cols; const float4 *k_vals;
    int *rp_s, *rp_e, *rp_k;
    int *cur_s, *cur_e, *cur_k;
    int4 *loc;
    int2 *pairs_s, *pairs_e, *pairs_k;
    unsigned long long* lk;
    uint32_t* bt_pad;
    const float4 *es, *ee, *ek;
    uint4 *s16, *e16, *k16;
    int* zero_base;
};

__global__ void __launch_bounds__(256, 5) csr_build_kernel(CsrArgs a) {
    int tid = threadIdx.x;
    int gid0 = blockIdx.x * 256 + tid;

    for (int i = gid0; i < INIT_TOT; i += PNB * 256) {
        if (i < ZERO_INTS) { a.zero_base[i] = 0; continue; }
        if (i < ZERO_INTS + BT16_PAD_WORDS) { a.bt_pad[i - ZERO_INTS] = 0u; continue; }
        int c = i - ZERO_INTS - BT16_PAD_WORDS;
        const float4* src; uint4* dst; int j;
        if (c < N8_S)             { src = a.es; dst = a.s16; j = c; }
        else if (c < N8_S + N8_E) { src = a.ee; dst = a.e16; j = c - N8_S; }
        else                      { src = a.ek; dst = a.k16; j = c - N8_S - N8_E; }
        float4 x = __ldg(src + 2 * j);
        float4 y = __ldg(src + 2 * j + 1);
        uint2 hx = f4toh4(x), hy = f4toh4(y);
        dst[j] = make_uint4(hx.x, hx.y, hy.x, hy.y);
    }
    gbar(&g_bar_csr[0], PNB);

    for (int i = gid0; i < Q4_TOT; i += PNB * 256) {
        int4 r; int* rp; int4* lp = a.loc + i;
        if (i < Q4_S)             { r = __ldg(a.s_rows + i); rp = a.rp_s; }
        else if (i < Q4_S + Q4_E) { r = __ldg(a.e_rows + (i - Q4_S)); rp = a.rp_e; }
        else                      { r = __ldg(a.k_rows + (i - Q4_S - Q4_E)); rp = a.rp_k; }
        int4 l;
        l.x = atomicAdd(&rp[r.x + 1], 1);
        l.y = atomicAdd(&rp[r.y + 1], 1);
        l.z = atomicAdd(&rp[r.z + 1], 1);
        l.w = atomicAdd(&rp[r.w + 1], 1);
        *lp = l;
    }
    gbar(&g_bar_csr[1], PNB);
    if (blockIdx.x == 0 && tid == 0) g_bar_csr[0] = 0;

    if (blockIdx.x < NB_TOT) {
        __shared__ int wsum[8];
        __shared__ int s_excl;
        const unsigned FULL = 0xFFFFFFFFu;
        int b = blockIdx.x, lane = tid & 31, wid = tid >> 5;
        int *x, *c, n, lb;
        if (b < NB_S)             { x = a.rp_s; c = a.cur_s; n = S_N + 1; lb = b; }
        else if (b < NB_S + NB_E) { x = a.rp_e; c = a.cur_e; n = E_N + 1; lb = b - NB_S; }
        else                      { x = a.rp_k; c = a.cur_k; n = K_N + 1; lb = b - NB_S - NB_E; }
        int base = lb * 1024 + tid * 4;
        int v0 = (base     < n) ? x[base]     : 0;
        int v1 = (base + 1 < n) ? x[base + 1] : 0;
        int v2 = (base + 2 < n) ? x[base + 2] : 0;
        int v3 = (base + 3 < n) ? x[base + 3] : 0;
        v1 += v0; v2 += v1; v3 += v2;
        int tin = v3;
        int incl = tin;
        #pragma unroll
        for (int off = 1; off < 32; off <<= 1) {
            int o = __shfl_up_sync(FULL, incl, off);
            if (lane >= off) incl += o;
        }
        if (lane == 31) wsum[wid] = incl;
        __syncthreads();
        if (wid == 0) {
            int ws = (lane < 8) ? wsum[lane] : 0;
            #pragma unroll
            for (int off = 1; off < 8; off <<= 1) {
                int o = __shfl_up_sync(FULL, ws, off);
                if (lane >= off) ws += o;
            }
            if (lane < 8) wsum[lane] = ws;
        }
        __syncthreads();
        int agg = wsum[7];
        int warp_excl = wid ? wsum[wid - 1] : 0;
        int thread_excl = warp_excl + (incl - tin);

        if (wid == 0) {
            volatile unsigned long long* vlk = (volatile unsigned long long*)a.lk;
            if (lb == 0) {
                if (lane == 0) { vlk[b] = (2ULL << 32) | (unsigned)agg; s_excl = 0; }
            } else {
                if (lane == 0) vlk[b] = (1ULL << 32) | (unsigned)agg;
                int gbase = b - lb;
                int running = 0;
                int j = lb - 1;
                while (true) {
                    int idx = j - lane;
                    bool valid = idx >= 0;
                    unsigned long long w = 0; int st = 0;
                    while (true) {
                        if (valid) { w = vlk[gbase + idx]; st = (int)(w >> 32); }
                        if (__all_sync(FULL, !valid || st != 0)) break;
                    }
                    unsigned pm = __ballot_sync(FULL, valid && st == 2);
                    int lane_p = pm ? (__ffs(pm) - 1) : 32;
                    int val = (valid && lane <= lane_p) ? (int)(unsigned)w : 0;
                    #pragma unroll
                    for (int off = 16; off; off >>= 1) val += __shfl_xor_sync(FULL, val, off);
                    running += val;
                    if (lane_p < 32) break;
                    j -= 32;
                }
                if (lane == 0) {
                    vlk[b] = (2ULL << 32) | (unsigned)(running + agg);
                    s_excl = running;
                }
            }
        }
        __syncthreads();
        int off0 = s_excl + thread_excl;
        if (base < n)     { int v = v0 + off0; x[base]     = v; if (base     < n - 1) c[base]     = v; }
        if (base + 1 < n) { int v = v1 + off0; x[base + 1] = v; if (base + 1 < n - 1) c[base + 1] = v; }
        if (base + 2 < n) { int v = v2 + off0; x[base + 2] = v; if (base + 2 < n - 1) c[base + 2] = v; }
        if (base + 3 < n) { int v = v3 + off0; x[base + 3] = v; if (base + 3 < n - 1) c[base + 3] = v; }
    }
    gbar(&g_bar_csr[2], PNB);
    if (blockIdx.x == 0 && tid == 0) g_bar_csr[1] = 0;

    for (int i = gid0; i < Q4_TOT; i += PNB * 256) {
        int4 r, cidx; float4 v; const int* cur; int2* pairs;
        if (i < Q4_S) {
            r = __ldg(a.s_rows + i); cidx = __ldg(a.s_cols + i); v = __ldg(a.s_vals + i);
            cur = a.cur_s; pairs = a.pairs_s;
        } else if (i < Q4_S + Q4_E) {
            int j = i - Q4_S;
            r = __ldg(a.e_rows + j); cidx = __ldg(a.e_cols + j); v = __ldg(a.e_vals + j);
            cur = a.cur_e; pairs = a.pairs_e;
        } else {
            int j = i - Q4_S - Q4_E;
            r = __ldg(a.k_rows + j); cidx = __ldg(a.k_cols + j); v = __ldg(a.k_vals + j);
            cur = a.cur_k; pairs = a.pairs_k;
        }
        int4 l = __ldg(a.loc + i);
        pairs[__ldg(cur + r.x) + l.x] = make_int2(cidx.x, __float_as_int(v.x));
        pairs[__ldg(cur + r.y) + l.y] = make_int2(cidx.y, __float_as_int(v.y));
        pairs[__ldg(cur + r.z) + l.z] = make_int2(cidx.z, __float_as_int(v.z));
        pairs[__ldg(cur + r.w) + l.w] = make_int2(cidx.w, __float_as_int(v.w));
    }
}

// ---------------- SpMM core (fp16 x, fp32 accumulate) ----------------
__device__ __forceinline__ float4 spmm_row_h(const int* __restrict__ rowptr,
                                             const int2* __restrict__ pairs,
                                             const uint2* __restrict__ xin, int row, int d4) {
    int beg = __ldg(rowptr + row);
    int end = __ldg(rowptr + row + 1);
    float4 s = make_float4(0.f, 0.f, 0.f, 0.f);
    int j = beg;
    for (; j + 3 < end; j += 4) {
        int2 p0 = __ldg(pairs + j);
        int2 p1 = __ldg(pairs + j + 1);
        int2 p2 = __ldg(pairs + j + 2);
        int2 p3 = __ldg(pairs + j + 3);
        float4 v0 = h4tof4(__ldg(xin + ((size_t)p0.x << 4) + d4));
        float4 v1 = h4tof4(__ldg(xin + ((size_t)p1.x << 4) + d4));
        float4 v2 = h4tof4(__ldg(xin + ((size_t)p2.x << 4) + d4));
        float4 v3 = h4tof4(__ldg(xin + ((size_t)p3.x << 4) + d4));
        float w0 = __int_as_float(p0.y), w1 = __int_as_float(p1.y);
        float w2 = __int_as_float(p2.y), w3 = __int_as_float(p3.y);
        s.x = fmaf(w0, v0.x, s.x); s.y = fmaf(w0, v0.y, s.y); s.z = fmaf(w0, v0.z, s.z); s.w = fmaf(w0, v0.w, s.w);
        s.x = fmaf(w1, v1.x, s.x); s.y = fmaf(w1, v1.y, s.y); s.z = fmaf(w1, v1.z, s.z); s.w = fmaf(w1, v1.w, s.w);
        s.x = fmaf(w2, v2.x, s.x); s.y = fmaf(w2, v2.y, s.y); s.z = fmaf(w2, v2.z, s.z); s.w = fmaf(w2, v2.w, s.w);
        s.x = fmaf(w3, v3.x, s.x); s.y = fmaf(w3, v3.y, s.y); s.z = fmaf(w3, v3.z, s.z); s.w = fmaf(w3, v3.w, s.w);
    }
    for (; j < end; j++) {
        int2 p = __ldg(pairs + j);
        float w = __int_as_float(p.y);
        float4 v = h4tof4(__ldg(xin + ((size_t)p.x << 4) + d4));
        s.x = fmaf(w, v.x, s.x); s.y = fmaf(w, v.y, s.y); s.z = fmaf(w, v.z, s.z); s.w = fmaf(w, v.w, s.w);
    }
    return s;
}

#define GB_S 6250
#define GB_E 1875
#define GB_K 63
#define GB_TOT (GB_S + GB_E + GB_K)
#define GL_S 1024
#define GL_E 1024
#define GL_K 63
#define GL_TOT (GL_S + GL_E + GL_K)

struct Spmm3Args {
    const int* rp[3];
    const int2* pr[3];
    const uint2* e16[3];
    uint2* x1[3];
    uint2* x2[3];
    int nrows[3];
    const int *sid, *eid;
    uint2 *xg_s, *xg_e, *x3_k;
};

__device__ __forceinline__ void spmm_layer_v(const Spmm3Args& a, int v,
                                             const uint2* const* xin_arr, uint2* const* xout_arr) {
    int seg, lb;
    if (v < GB_S)             { seg = 0; lb = v; }
    else if (v < GB_S + GB_E) { seg = 1; lb = v - GB_S; }
    else                      { seg = 2; lb = v - GB_S - GB_E; }
    int row = lb * 16 + (threadIdx.x >> 4);
    int d4 = threadIdx.x & 15;
    if (row >= a.nrows[seg]) return;
    const uint2* xin = xin_arr[seg];
    float4 s = spmm_row_h(a.rp[seg], a.pr[seg], xin, row, d4);
    size_t o = ((size_t)row << 4) + d4;
    float4 m = h4tof4(xin[o]);
    s.x += MOM * m.x; s.y += MOM * m.y; s.z += MOM * m.z; s.w += MOM * m.w;
    xout_arr[seg][o] = f4toh4(s);
}

__global__ void __launch_bounds__(256, 5) spmm3_kernel(Spmm3Args a) {
    if (blockIdx.x == 0 && threadIdx.x == 0) g_bar_csr[2] = 0;
    for (int v = blockIdx.x; v < GB_TOT; v += PNB)
        spmm_layer_v(a, v, a.e16, a.x1);
    gbar(&g_bar_spmm[0], PNB);
    for (int v = blockIdx.x; v < GB_TOT; v += PNB)
        spmm_layer_v(a, v, (const uint2* const*)a.x1, a.x2);
    gbar(&g_bar_spmm[1], PNB);
    if (blockIdx.x == 0 && threadIdx.x == 0) g_bar_spmm[0] = 0;
    int d4 = threadIdx.x & 15;
    int lr = threadIdx.x >> 4;
    for (int v = blockIdx.x; v < GL_TOT; v += PNB) {
        if (v < GL_S) {
            int r = v * 16 + lr;
            int row = __ldg(a.sid + r);
            float4 s = spmm_row_h(a.rp[0], a.pr[0], a.x2[0], row, d4);
            float4 m = h4tof4(a.x2[0][((size_t)row << 4) + d4]);
            s.x += MOM * m.x; s.y += MOM * m.y; s.z += MOM * m.z; s.w += MOM * m.w;
            a.xg_s[((size_t)r << 4) + d4] = f4toh4(s);
        } else if (v < GL_S + GL_E) {
            int r = (v - GL_S) * 16 + lr;
            int row = __ldg(a.eid + r);
            float4 s = spmm_row_h(a.rp[1], a.pr[1], a.x2[1], row, d4);
            float4 m = h4tof4(a.x2[1][((size_t)row << 4) + d4]);
            s.x += MOM * m.x; s.y += MOM * m.y; s.z += MOM * m.z; s.w += MOM * m.w;
            a.xg_e[((size_t)r << 4) + d4] = f4toh4(s);
        } else {
            int row = (v - GL_S - GL_E) * 16 + lr;
            if (row >= K_N) continue;
            float4 s = spmm_row_h(a.rp[2], a.pr[2], a.x2[2], row, d4);
            float4 m = h4tof4(a.x2[2][((size_t)row << 4) + d4]);
            s.x += MOM * m.x; s.y += MOM * m.y; s.z += MOM * m.z; s.w += MOM * m.w;
            a.x3_k[((size_t)row << 4) + d4] = f4toh4(s);
        }
    }
}

// ---------------- tf32 helper / MMA macros ----------------
__device__ __forceinline__ uint32_t f2tf32(float f) {
    uint32_t u;
    asm("cvt.rna.tf32.f32 %0, %1;" : "=r"(u) : "f"(f));
    return u;
}

#define MMA_TF32(d, a, b)                                                     \
    asm volatile(                                                             \
        "mma.sync.aligned.m16n8k8.row.col.f32.tf32.tf32.f32 "                 \
        "{%0,%1,%2,%3}, {%4,%5,%6,%7}, {%8,%9}, {%0,%1,%2,%3};\n"             \
        : "+f"(d[0]), "+f"(d[1]), "+f"(d[2]), "+f"(d[3])                      \
        : "r"(a[0]), "r"(a[1]), "r"(a[2]), "r"(a[3]), "r"(b[0]), "r"(b[1]))

#define MMA_F16(d, a, b)                                                      \
    asm volatile(                                                             \
        "mma.sync.aligned.m16n8k16.row.col.f32.f16.f16.f32 "                  \
        "{%0,%1,%2,%3}, {%4,%5,%6,%7}, {%8,%9}, {%0,%1,%2,%3};\n"             \
        : "+f"(d[0]), "+f"(d[1]), "+f"(d[2]), "+f"(d[3])                      \
        : "r"(a[0]), "r"(a[1]), "r"(a[2]), "r"(a[3]), "r"(b[0]), "r"(b[1]))

// ---------------- unified dense stage ----------------
#define XS_STRIDE 68
#define WT_STRIDE 68
#define DM_XS_W   (64 * XS_STRIDE)
#define DM_WT_W   (128 * WT_STRIDE)
#define DM_SMEM_BYTES ((DM_XS_W + DM_WT_W + 128 + 64) * 4)
#define G_MMA 512
#define G_KNO 125
#define G_IMP 1024
#define G_DENSE (G_MMA + G_KNO + G_IMP)

struct DenseArgs {
    const float *x0s;  const uint2 *x1s, *x2s, *x3s;
    const float *x0e;  const uint2 *x1e, *x2e, *x3e;
    const float *xk0;  const uint2 *xk1, *xk2, *xk3;
    const int *sid, *eid;
    const float *Ws, *bs, *We, *be, *Wk, *bk, *Wd, *bd;
    const float *imp;
    uint32_t *A1h, *A2h;
    __half *Bt16;
    float *Okt, *Odisc, *Oimp;
};

__global__ void __launch_bounds__(256) dense_all_kernel(DenseArgs a) {
    extern __shared__ uint32_t dsm[];
    const unsigned FULL = 0xFFFFFFFFu;
    int b = blockIdx.x, tid = threadIdx.x;
    if (b == 0 && tid == 0) g_bar_spmm[1] = 0;

    if (b < G_MMA) {
        uint32_t* Xs = dsm;
        uint32_t* Wt = dsm + DM_XS_W;
        float* bsm = (float*)(dsm + DM_XS_W + DM_WT_W);
        float* wd  = bsm + 128;
        bool is_e = b >= 256;
        int r0 = (is_e ? b - 256 : b) * 64;
        const float* x0 = is_e ? a.x0e : a.x0s;
        const uint2* x1 = is_e ? a.x1e : a.x1s;
        const uint2* x2 = is_e ? a.x2e : a.x2s;
        const uint2* x3 = is_e ? a.x3e : a.x3s;
        const int* ids  = is_e ? a.eid : a.sid;
        const float* W  = is_e ? a.We : a.Ws;
        const float* bias = is_e ? a.be : a.bs;
        uint32_t* out = is_e ? a.A2h : a.A1h;

        for (int i = tid; i < 8192; i += 256) {
            int k = i >> 7, n = i & 127;
            Wt[n * WT_STRIDE + k] = f2tf32(__ldg(W + i));
        }
        if (tid < 128) bsm[tid] = __ldg(bias + tid);
        if (is_e && tid < 64) wd[tid] = __ldg(a.Wd + tid);

        for (int i = tid; i < 1024; i += 256) {
            int rr = i >> 4, c4 = i & 15;
            int r = r0 + rr;
            int rid = __ldg(ids + r);
            size_t o  = ((size_t)rid << 4) + c4;
            size_t o3 = ((size_t)r << 4) + c4;
            float4 a0 = __ldg((const float4*)x0 + o);
            float4 a1 = h4tof4(__ldg(x1 + o));
            float4 a2 = h4tof4(__ldg(x2 + o));
            float4 a3 = h4tof4(__ldg(x3 + o3));
            uint4 w;
            w.x = f2tf32(0.25f * (a0.x + a1.x + a2.x + a3.x));
            w.y = f2tf32(0.25f * (a0.y + a1.y + a2.y + a3.y));
            w.z = f2tf32(0.25f * (a0.z + a1.z + a2.z + a3.z));
            w.w = f2tf32(0.25f * (a0.w + a1.w + a2.w + a3.w));
            *(uint4*)&Xs[rr * XS_STRIDE + c4 * 4] = w;
        }
        __syncthreads();

        int warp = tid >> 5, lane = tid & 31, g = lane >> 2, tg = lane & 3;
        int wm = warp >> 1;
        int wn = warp & 1;
        float acc[8][4] = {};
        #pragma unroll
        for (int ks = 0; ks < 8; ks++) {
            int k0 = ks * 8;
            uint32_t A[4];
            const uint32_t* ap = &Xs[(wm * 16 + g) * XS_STRIDE + k0 + tg];
            A[0] = ap[0]; A[1] = ap[8 * XS_STRIDE]; A[2] = ap[4]; A[3] = ap[8 * XS_STRIDE + 4];
            #pragma unroll
            for (int nt = 0; nt < 8; nt++) {
                const uint32_t* bp = &Wt[(wn * 64 + nt * 8 + g) * WT_STRIDE + k0 + tg];
                uint32_t B[2] = {bp[0], bp[4]};
                MMA_TF32(acc[nt], A, B);
            }
        }

        #pragma unroll
        for (int nt = 0; nt < 8; nt++) {
            int col = wn * 64 + nt * 8 + tg * 2;
            float b0 = bsm[col], b1 = bsm[col + 1];
            size_t rA = (size_t)(r0 + wm * 16 + g);
            size_t rB = rA + 8;
            float v0 = acc[nt][0] + b0; v0 = (v0 > 0.f) ? v0 : LEAK_F * v0;
            float v1 = acc[nt][1] + b1; v1 = (v1 > 0.f) ? v1 : LEAK_F * v1;
            float v2 = acc[nt][2] + b0; v2 = (v2 > 0.f) ? v2 : LEAK_F * v2;
            float v3 = acc[nt][3] + b1; v3 = (v3 > 0.f) ? v3 : LEAK_F * v3;
            out[rA * 64 + (col >> 1)] = f2toh2(v0, v1);
            out[rB * 64 + (col >> 1)] = f2toh2(v2, v3);
        }

        if (is_e) {
            int row = tid >> 2, part = tid & 3;
            float s = 0.f;
            #pragma unroll
            for (int i = 0; i < 16; i++)
                s += __uint_as_float(Xs[row * XS_STRIDE + part * 16 + i]) * wd[part * 16 + i];
            s += __shfl_xor_sync(FULL, s, 1);
            s += __shfl_xor_sync(FULL, s, 2);
            if (part == 0) a.Odisc[r0 + row] = 1.f / (1.f + __expf(-(s + __ldg(a.bd))));
        }
    } else if (b < G_MMA + G_KNO) {
        float* Ws = (float*)dsm;
        float* Xs = Ws + 8192;
        int r0 = (b - G_MMA) * 8;
        const float4* W4 = (const float4*)a.Wk;
        float4* Ws4 = (float4*)Ws;
        #pragma unroll
        for (int i = 0; i < 8; i++) Ws4[tid + i * 256] = W4[tid + i * 256];
        if (tid < 128) {
            int rr = tid >> 4;
            int c4 = tid & 15;
            int r = r0 + rr;
            float4 v = make_float4(0.f, 0.f, 0.f, 0.f);
            if (r < K_N) {
                size_t o = ((size_t)r << 4) + c4;
                float4 a0 = __ldg((const float4*)a.xk0 + o);
                float4 a1 = h4tof4(__ldg(a.xk1 + o));
                float4 a2 = h4tof4(__ldg(a.xk2 + o));
                float4 a3 = h4tof4(__ldg(a.xk3 + o));
                v.x = 0.25f * (a0.x + a1.x + a2.x + a3.x);
                v.y = 0.25f * (a0.y + a1.y + a2.y + a3.y);
                v.z = 0.25f * (a0.z + a1.z + a2.z + a3.z);
                v.w = 0.25f * (a0.w + a1.w + a2.w + a3.w);
            }
            ((float4*)&Xs[rr * 64])[c4] = v;
        }
        __syncthreads();
        int col = tid & 127;
        int rbase = tid >> 7;
        float bv = __ldg(a.bk + col);
        #pragma unroll
        for (int rr = 0; rr < 4; rr++) {
            int lrow = rr * 2 + rbase;
            int r = r0 + lrow;
            if (r >= K_N) continue;
            float acc = bv;
            #pragma unroll
            for (int i = 0; i < 64; i++) acc = fmaf(Xs[lrow * 64 + i], Ws[i * 128 + col], acc);
            float rv = (acc > 0.f) ? acc : LEAK_F * acc;
            a.Okt[(size_t)r * 128 + col] = rv;
            a.Bt16[(size_t)r * 128 + col] = __float2half_rn(rv);
        }
    } else {
        int t = (b - G_MMA - G_KNO) * 256 + tid;
        int bi = t >> 4, q = t & 15;
        ((float4*)a.Oimp)[((size_t)bi << 4) + q] =
            __ldg((const float4*)a.imp + ((size_t)__ldg(a.eid + bi) << 4) + q);
    }
}

// ---------------- fp16 big GEMM: one output matrix per block (2048 blocks) ----------------
#define SMH 68
#define HG_W (128 * SMH)
#define HGEMM_SMEM_BYTES (2 * HG_W * 4)   // 69632

__device__ __forceinline__ void cp16(uint32_t dst, const void* src) {
    asm volatile("cp.async.cg.shared.global [%0], [%1], 16;" :: "r"(dst), "l"(src));
}

__global__ void __launch_bounds__(256, 2) big_gemm_f16(
    const uint32_t* __restrict__ A1h, const uint32_t* __restrict__ A2h,
    const uint32_t* __restrict__ Bh, float* __restrict__ O1, float* __restrict__ O2) {
    extern __shared__ uint32_t sm[];
    uint32_t sbase = (uint32_t)__cvta_generic_to_shared(sm);
    const uint32_t* As = sm;
    const uint32_t* Bs = sm + HG_W;

    int tid = threadIdx.x;
    int warp = tid >> 5;
    int lane = tid & 31;
    int g = lane >> 2;
    int tg = lane & 3;
    int wm = warp >> 1;
    int wn = warp & 1;
    int m0 = blockIdx.x * 128;
    int n0 = blockIdx.y * 128;
    bool second = blockIdx.z != 0;
    const uint32_t* Ah = second ? A2h : A1h;
    float* O = second ? O2 : O1;

    #pragma unroll
    for (int i = 0; i < 8; i++) {
        int idx = tid + i * 256;
        int row = idx >> 4, q = idx & 15;
        uint32_t off = (uint32_t)(row * SMH + q * 4) * 4;
        cp16(sbase + off,            Ah + (size_t)(m0 + row) * 64 + q * 4);
        cp16(sbase + HG_W * 4 + off, Bh + (size_t)(n0 + row) * 64 + q * 4);
    }
    asm volatile("cp.async.commit_group;");
    asm volatile("cp.async.wait_group 0;");
    __syncthreads();

    float acc[2][8][4] = {};

    #pragma unroll
    for (int ks = 0; ks < 8; ks++) {
        int w0 = ks * 8;
        uint32_t b[8][2];
        #pragma unroll
        for (int nt = 0; nt < 8; nt++) {
            const uint32_t* bp = &Bs[(wn * 64 + nt * 8 + g) * SMH + w0 + tg];
            b[nt][0] = bp[0];
            b[nt][1] = bp[4];
        }
        #pragma unroll
        for (int mt = 0; mt < 2; mt++) {
            uint32_t a[4];
            const uint32_t* ap = &As[(wm * 32 + mt * 16 + g) * SMH + w0 + tg];
            a[0] = ap[0]; a[1] = ap[8 * SMH]; a[2] = ap[4]; a[3] = ap[8 * SMH + 4];
            #pragma unroll
            for (int nt = 0; nt < 8; nt++) MMA_F16(acc[mt][nt], a, b[nt]);
        }
    }

    #pragma unroll
    for (int mt = 0; mt < 2; mt++) {
        #pragma unroll
        for (int nt = 0; nt < 8; nt++) {
            int col = n0 + wn * 64 + nt * 8 + tg * 2;
            if (col >= K_N) continue;
            size_t r0 = (size_t)(m0 + wm * 32 + mt * 16 + g);
            size_t r1 = r0 + 8;
            *(float2*)(O + r0 * K_N + col) = make_float2(acc[mt][nt][0], acc[mt][nt][1]);
            *(float2*)(O + r1 * K_N + col) = make_float2(acc[mt][nt][2], acc[mt][nt][3]);
        }
    }
}

// ---------------- host orchestration ----------------
extern "C" void kernel_launch(void* const* d_in, const int* in_sizes, int n_in,
                              void* d_out, int out_size) {
    (void)in_sizes; (void)n_in; (void)out_size;
    const int*   student_id  = (const int*)d_in[0];
    const int*   exercise_id = (const int*)d_in[1];
    const float* stu_emb     = (const float*)d_in[3];
    const float* exer_emb    = (const float*)d_in[4];
    const float* know_emb    = (const float*)d_in[5];
    const float* impact_emb  = (const float*)d_in[6];
    const int*   s_rows = (const int*)d_in[7];
    const int*   s_cols = (const int*)d_in[8];
    const float* s_vals = (const float*)d_in[9];
    const int*   e_rows = (const int*)d_in[10];
    const int*   e_cols = (const int*)d_in[11];
    const float* e_vals = (const float*)d_in[12];
    const int*   k_rows = (const int*)d_in[13];
    const int*   k_cols = (const int*)d_in[14];
    const float* k_vals = (const float*)d_in[15];
    const float* W_stu  = (const float*)d_in[16];
    const float* b_stu  = (const float*)d_in[17];
    const float* W_exer = (const float*)d_in[18];
    const float* b_exer = (const float*)d_in[19];
    const float* W_know = (const float*)d_in[20];
    const float* b_know = (const float*)d_in[21];
    const float* W_disc = (const float*)d_in[22];
    const float* b_disc = (const float*)d_in[23];

    unsigned char* A = nullptr;
    cudaGetSymbolAddress((void**)&A, g_arena);

    int*  rp_s  = (int*)(A + O_RP_S);
    int*  rp_e  = (int*)(A + O_RP_E);
    int*  rp_k  = (int*)(A + O_RP_K);
    unsigned long long* lk = (unsigned long long*)(A + O_LK);
    int*  cur_s = (int*)(A + O_CUR_S);
    int*  cur_e = (int*)(A + O_CUR_E);
    int*  cur_k = (int*)(A + O_CUR_K);
    int*  loc   = (int*)(A + O_LOC);
    int2* pairs_s = (int2*)(A + O_PAIRS_S);
    int2* pairs_e = (int2*)(A + O_PAIRS_E);
    int2* pairs_k = (int2*)(A + O_PAIRS_K);
    uint2* e16_s = (uint2*)(A + O_E16_S);
    uint2* e16_e = (uint2*)(A + O_E16_E);
    uint2* e16_k = (uint2*)(A + O_E16_K);
    uint2* x1_s = (uint2*)(A + O_X1_S);
    uint2* x2_s = (uint2*)(A + O_X2_S);
    uint2* x1_e = (uint2*)(A + O_X1_E);
    uint2* x2_e = (uint2*)(A + O_X2_E);
    uint2* x1_k = (uint2*)(A + O_X1_K);
    uint2* x2_k = (uint2*)(A + O_X2_K);
    uint2* x3_k = (uint2*)(A + O_X3_K);
    uint2* xg_s = (uint2*)(A + O_XG_S);
    uint2* xg_e = (uint2*)(A + O_XG_E);
    uint32_t* A1h = (uint32_t*)(A + O_A1);
    uint32_t* A2h = (uint32_t*)(A + O_A2);
    __half* Bt16 = (__half*)(A + O_BT16);

    // 1) persistent CSR build
    {
        CsrArgs ca;
        ca.s_rows = (const int4*)s_rows; ca.s_cols = (const int4*)s_cols; ca.s_vals = (const float4*)s_vals;
        ca.e_rows = (const int4*)e_rows; ca.e_cols = (const int4*)e_cols; ca.e_vals = (const float4*)e_vals;
        ca.k_rows = (const int4*)k_rows; ca.k_cols = (const int4*)k_cols; ca.k_vals = (const float4*)k_vals;
        ca.rp_s = rp_s; ca.rp_e = rp_e; ca.rp_k = rp_k;
        ca.cur_s = cur_s; ca.cur_e = cur_e; ca.cur_k = cur_k;
        ca.loc = (int4*)loc;
        ca.pairs_s = pairs_s; ca.pairs_e = pairs_e; ca.pairs_k = pairs_k;
        ca.lk = lk;
        ca.bt_pad = (uint32_t*)(Bt16 + (size_t)K_N * 128);
        ca.es = (const float4*)stu_emb; ca.ee = (const float4*)exer_emb; ca.ek = (const float4*)know_emb;
        ca.s16 = (uint4*)e16_s; ca.e16 = (uint4*)e16_e; ca.k16 = (uint4*)e16_k;
        ca.zero_base = (int*)A;
        csr_build_kernel<<<PNB, 256>>>(ca);
    }

    // 2) persistent SpMM
    {
        Spmm3Args sa;
        sa.rp[0] = rp_s;  sa.rp[1] = rp_e;  sa.rp[2] = rp_k;
        sa.pr[0] = pairs_s; sa.pr[1] = pairs_e; sa.pr[2] = pairs_k;
        sa.e16[0] = e16_s; sa.e16[1] = e16_e; sa.e16[2] = e16_k;
        sa.x1[0] = x1_s; sa.x1[1] = x1_e; sa.x1[2] = x1_k;
        sa.x2[0] = x2_s; sa.x2[1] = x2_e; sa.x2[2] = x2_k;
        sa.nrows[0] = S_N; sa.nrows[1] = E_N; sa.nrows[2] = K_N;
        sa.sid = student_id; sa.eid = exercise_id;
        sa.xg_s = xg_s; sa.xg_e = xg_e; sa.x3_k = x3_k;
        spmm3_kernel<<<PNB, 256>>>(sa);
    }

    // 3) output layout
    float* out   = (float*)d_out;
    float* O1    = out;
    float* O2    = O1 + (size_t)B_N * K_N;
    float* Odisc = O2 + (size_t)B_N * K_N;
    float* Okt   = Odisc + B_N;
    float* Oimp  = Okt + (size_t)K_N * FF;

    // 4) unified dense stage
    static bool attr_set = false;
    if (!attr_set) {
        cudaFuncSetAttribute(dense_all_kernel,
                             cudaFuncAttributeMaxDynamicSharedMemorySize, DM_SMEM_BYTES);
        cudaFuncSetAttribute(big_gemm_f16,
                             cudaFuncAttributeMaxDynamicSharedMemorySize, HGEMM_SMEM_BYTES);
        attr_set = true;
    }
    {
        DenseArgs da;
        da.x0s = stu_emb;  da.x1s = x1_s; da.x2s = x2_s; da.x3s = xg_s;
        da.x0e = exer_emb; da.x1e = x1_e; da.x2e = x2_e; da.x3e = xg_e;
        da.xk0 = know_emb; da.xk1 = x1_k; da.xk2 = x2_k; da.xk3 = x3_k;
        da.sid = student_id; da.eid = exercise_id;
        da.Ws = W_stu; da.bs = b_stu; da.We = W_exer; da.be = b_exer;
        da.Wk = W_know; da.bk = b_know; da.Wd = W_disc; da.bd = b_disc;
        da.imp = impact_emb;
        da.A1h = A1h; da.A2h = A2h; da.Bt16 = Bt16;
        da.Okt = Okt; da.Odisc = Odisc; da.Oimp = Oimp;
        dense_all_kernel<<<G_DENSE, 256, DM_SMEM_BYTES>>>(da);
    }

    // 5) fp16 big GEMM pair (one output matrix per block)
    dim3 grid(B_N / 128, 1024 / 128, 2);
    big_gemm_f16<<<grid, 256, HGEMM_SMEM_BYTES>>>(
        A1h, A2h, (const uint32_t*)Bt16, O1, O2);
}

// round 15
// speedup vs baseline: 1.7900x; 1.0108x over previous
#include <cuda_runtime.h>
#include <cuda_fp16.h>
#include <cstdint>
#include <cstddef>

#define S_N 100000
#define E_N 30000
#define K_N 1000
#define DD 64
#define FF 128
#define B_N 16384
#define NNZ_S 1600000
#define NNZ_E 480000
#define NNZ_K 32000
#define NNZ_TOT (NNZ_S + NNZ_E + NNZ_K)
#define MOM 0.9f
#define LEAK_F 0.1f

#define NB_S 98
#define NB_E 30
#define NB_K 1
#define NB_TOT (NB_S + NB_E + NB_K)

#define PNB 740

static constexpr size_t al256(size_t x) { return (x + 255) & ~(size_t)255; }

// ---------------- static scratch arena ----------------
static constexpr size_t O_RP_S = 0;
static constexpr size_t O_RP_E = O_RP_S + (size_t)(S_N + 1) * 4;
static constexpr size_t O_RP_K = O_RP_E + (size_t)(E_N + 1) * 4;
static constexpr size_t RP_END = O_RP_K + (size_t)(K_N + 1) * 4;
static constexpr size_t O_LK   = al256(RP_END);
static constexpr size_t LK_END = O_LK + (size_t)NB_TOT * 8;
static constexpr int    ZERO_INTS = (int)(LK_END / 4);

static constexpr size_t O_CUR_S = al256(LK_END);
static constexpr size_t O_CUR_E = al256(O_CUR_S + (size_t)S_N * 4);
static constexpr size_t O_CUR_K = al256(O_CUR_E + (size_t)E_N * 4);
static constexpr size_t O_LOC   = al256(O_CUR_K + (size_t)K_N * 4);
static constexpr size_t O_PAIRS_S = al256(O_LOC + (size_t)NNZ_TOT * 4);
static constexpr size_t O_PAIRS_E = al256(O_PAIRS_S + (size_t)NNZ_S * 8);
static constexpr size_t O_PAIRS_K = al256(O_PAIRS_E + (size_t)NNZ_E * 8);
static constexpr size_t O_E16_S = al256(O_PAIRS_K + (size_t)NNZ_K * 8);
static constexpr size_t O_E16_E = al256(O_E16_S + (size_t)S_N * DD * 2);
static constexpr size_t O_E16_K = al256(O_E16_E + (size_t)E_N * DD * 2);
static constexpr size_t O_X1_S  = al256(O_E16_K + (size_t)K_N * DD * 2);
static constexpr size_t O_X2_S  = al256(O_X1_S + (size_t)S_N * DD * 2);
static constexpr size_t O_X1_E  = al256(O_X2_S + (size_t)S_N * DD * 2);
static constexpr size_t O_X2_E  = al256(O_X1_E + (size_t)E_N * DD * 2);
static constexpr size_t O_X1_K  = al256(O_X2_E + (size_t)E_N * DD * 2);
static constexpr size_t O_X2_K  = al256(O_X1_K + (size_t)K_N * DD * 2);
static constexpr size_t O_X3_K  = al256(O_X2_K + (size_t)K_N * DD * 2);
static constexpr size_t O_XG_S  = al256(O_X3_K + (size_t)K_N * DD * 2);
static constexpr size_t O_XG_E  = al256(O_XG_S + (size_t)B_N * DD * 2);
static constexpr size_t O_A1    = al256(O_XG_E + (size_t)B_N * DD * 2);
static constexpr size_t O_A2    = al256(O_A1 + (size_t)B_N * FF * 2);
static constexpr size_t O_BT16  = al256(O_A2 + (size_t)B_N * FF * 2);
static constexpr size_t ARENA_BYTES = al256(O_BT16 + (size_t)1024 * FF * 2);

__device__ __align__(256) unsigned char g_arena[ARENA_BYTES];

__device__ int g_bar_csr[3];
__device__ int g_bar_spmm[2];

__device__ __forceinline__ void gbar(int* cnt, int nb) {
    __syncthreads();
    if (threadIdx.x == 0) {
        __threadfence();
        atomicAdd(cnt, 1);
        while (*(volatile int*)cnt < nb) { }
        __threadfence();
    }
    __syncthreads();
}

// ---------------- half<->float helpers ----------------
__device__ __forceinline__ float4 h4tof4(uint2 h) {
    __half2 a = *(__half2*)&h.x;
    __half2 b = *(__half2*)&h.y;
    float2 fa = __half22float2(a), fb = __half22float2(b);
    return make_float4(fa.x, fa.y, fb.x, fb.y);
}
__device__ __forceinline__ uint2 f4toh4(float4 f) {
    __half2 a = __floats2half2_rn(f.x, f.y);
    __half2 b = __floats2half2_rn(f.z, f.w);
    uint2 r;
    r.x = *(uint32_t*)&a;
    r.y = *(uint32_t*)&b;
    return r;
}
__device__ __forceinline__ uint32_t f2toh2(float a, float b) {
    __half2 h = __floats2half2_rn(a, b);
    return *(uint32_t*)&h;
}

#define BT16_PAD_WORDS (24 * 128 / 2)
#define N8_S (S_N * DD / 8)
#define N8_E (E_N * DD / 8)
#define N8_K (K_N * DD / 8)
#define N8_TOT (N8_S + N8_E + N8_K)
#define INIT_TOT (ZERO_INTS + BT16_PAD_WORDS + N8_TOT)

#define Q4_S (NNZ_S / 4)
#define Q4_E (NNZ_E / 4)
#define Q4_K (NNZ_K / 4)
#define Q4_TOT (Q4_S + Q4_E + Q4_K)

// ---------------- persistent CSR build ----------------
struct CsrArgs {
    const int4 *s_rows, *s_cols; const float4 *s_vals;
    const int4 *e_rows, *e_cols; const float4 *e_vals;
    const int4 *k_rows, *k_cols; const float4 *k_vals;
    int *rp_s, *rp_e, *rp_k;
    int *cur_s, *cur_e, *cur_k;
    int4 *loc;
    int2 *pairs_s, *pairs_e, *pairs_k;
    unsigned long long* lk;
    uint32_t* bt_pad;
    const float4 *es, *ee, *ek;
    uint4 *s16, *e16, *k16;
    int* zero_base;
};

__global__ void __launch_bounds__(256, 5) csr_build_kernel(CsrArgs a) {
    int tid = threadIdx.x;
    int gid0 = blockIdx.x * 256 + tid;

    for (int i = gid0; i < INIT_TOT; i += PNB * 256) {
        if (i < ZERO_INTS) { a.zero_base[i] = 0; continue; }
        if (i < ZERO_INTS + BT16_PAD_WORDS) { a.bt_pad[i - ZERO_INTS] = 0u; continue; }
        int c = i - ZERO_INTS - BT16_PAD_WORDS;
        const float4* src; uint4* dst; int j;
        if (c < N8_S)             { src = a.es; dst = a.s16; j = c; }
        else if (c < N8_S + N8_E) { src = a.ee; dst = a.e16; j = c - N8_S; }
        else                      { src = a.ek; dst = a.k16; j = c - N8_S - N8_E; }
        float4 x = __ldg(src + 2 * j);
        float4 y = __ldg(src + 2 * j + 1);
        uint2 hx = f4toh4(x), hy = f4toh4(y);
        dst[j] = make_uint4(hx.x, hx.y, hy.x, hy.y);
    }
    gbar(&g_bar_csr[0], PNB);

    for (int i = gid0; i < Q4_TOT; i += PNB * 256) {
        int4 r; int* rp; int4* lp = a.loc + i;
        if (i < Q4_S)             { r = __ldg(a.s_rows + i); rp = a.rp_s; }
        else if (i < Q4_S + Q4_E) { r = __ldg(a.e_rows + (i - Q4_S)); rp = a.rp_e; }
        else                      { r = __ldg(a.k_rows + (i - Q4_S - Q4_E)); rp = a.rp_k; }
        int4 l;
        l.x = atomicAdd(&rp[r.x + 1], 1);
        l.y = atomicAdd(&rp[r.y + 1], 1);
        l.z = atomicAdd(&rp[r.z + 1], 1);
        l.w = atomicAdd(&rp[r.w + 1], 1);
        *lp = l;
    }
    gbar(&g_bar_csr[1], PNB);
    if (blockIdx.x == 0 && tid == 0) g_bar_csr[0] = 0;

    if (blockIdx.x < NB_TOT) {
        __shared__ int wsum[8];
        __shared__ int s_excl;
        const unsigned FULL = 0xFFFFFFFFu;
        int b = blockIdx.x, lane = tid & 31, wid = tid >> 5;
        int *x, *c, n, lb;
        if (b < NB_S)             { x = a.rp_s; c = a.cur_s; n = S_N + 1; lb = b; }
        else if (b < NB_S + NB_E) { x = a.rp_e; c = a.cur_e; n = E_N + 1; lb = b - NB_S; }
        else                      { x = a.rp_k; c = a.cur_k; n = K_N + 1; lb = b - NB_S - NB_E; }
        int base = lb * 1024 + tid * 4;
        int v0 = (base     < n) ? x[base]     : 0;
        int v1 = (base + 1 < n) ? x[base + 1] : 0;
        int v2 = (base + 2 < n) ? x[base + 2] : 0;
        int v3 = (base + 3 < n) ? x[base + 3] : 0;
        v1 += v0; v2 += v1; v3 += v2;
        int tin = v3;
        int incl = tin;
        #pragma unroll
        for (int off = 1; off < 32; off <<= 1) {
            int o = __shfl_up_sync(FULL, incl, off);
            if (lane >= off) incl += o;
        }
        if (lane == 31) wsum[wid] = incl;
        __syncthreads();
        if (wid == 0) {
            int ws = (lane < 8) ? wsum[lane] : 0;
            #pragma unroll
            for (int off = 1; off < 8; off <<= 1) {
                int o = __shfl_up_sync(FULL, ws, off);
                if (lane >= off) ws += o;
            }
            if (lane < 8) wsum[lane] = ws;
        }
        __syncthreads();
        int agg = wsum[7];
        int warp_excl = wid ? wsum[wid - 1] : 0;
        int thread_excl = warp_excl + (incl - tin);

        if (wid == 0) {
            volatile unsigned long long* vlk = (volatile unsigned long long*)a.lk;
            if (lb == 0) {
                if (lane == 0) { vlk[b] = (2ULL << 32) | (unsigned)agg; s_excl = 0; }
            } else {
                if (lane == 0) vlk[b] = (1ULL << 32) | (unsigned)agg;
                int gbase = b - lb;
                int running = 0;
                int j = lb - 1;
                while (true) {
                    int idx = j - lane;
                    bool valid = idx >= 0;
                    unsigned long long w = 0; int st = 0;
                    while (true) {
                        if (valid) { w = vlk[gbase + idx]; st = (int)(w >> 32); }
                        if (__all_sync(FULL, !valid || st != 0)) break;
                    }
                    unsigned pm = __ballot_sync(FULL, valid && st == 2);
                    int lane_p = pm ? (__ffs(pm) - 1) : 32;
                    int val = (valid && lane <= lane_p) ? (int)(unsigned)w : 0;
                    #pragma unroll
                    for (int off = 16; off; off >>= 1) val += __shfl_xor_sync(FULL, val, off);
                    running += val;
                    if (lane_p < 32) break;
                    j -= 32;
                }
                if (lane == 0) {
                    vlk[b] = (2ULL << 32) | (unsigned)(running + agg);
                    s_excl = running;
                }
            }
        }
        __syncthreads();
        int off0 = s_excl + thread_excl;
        if (base < n)     { int v = v0 + off0; x[base]     = v; if (base     < n - 1) c[base]     = v; }
        if (base + 1 < n) { int v = v1 + off0; x[base + 1] = v; if (base + 1 < n - 1) c[base + 1] = v; }
        if (base + 2 < n) { int v = v2 + off0; x[base + 2] = v; if (base + 2 < n - 1) c[base + 2] = v; }
        if (base + 3 < n) { int v = v3 + off0; x[base + 3] = v; if (base + 3 < n - 1) c[base + 3] = v; }
    }
    gbar(&g_bar_csr[2], PNB);
    if (blockIdx.x == 0 && tid == 0) g_bar_csr[1] = 0;

    for (int i = gid0; i < Q4_TOT; i += PNB * 256) {
        int4 r, cidx; float4 v; const int* cur; int2* pairs;
        if (i < Q4_S) {
            r = __ldg(a.s_rows + i); cidx = __ldg(a.s_cols + i); v = __ldg(a.s_vals + i);
            cur = a.cur_s; pairs = a.pairs_s;
        } else if (i < Q4_S + Q4_E) {
            int j = i - Q4_S;
            r = __ldg(a.e_rows + j); cidx = __ldg(a.e_cols + j); v = __ldg(a.e_vals + j);
            cur = a.cur_e; pairs = a.pairs_e;
        } else {
            int j = i - Q4_S - Q4_E;
            r = __ldg(a.k_rows + j); cidx = __ldg(a.k_cols + j); v = __ldg(a.k_vals + j);
            cur = a.cur_k; pairs = a.pairs_k;
        }
        int4 l = __ldg(a.loc + i);
        pairs[__ldg(cur + r.x) + l.x] = make_int2(cidx.x, __float_as_int(v.x));
        pairs[__ldg(cur + r.y) + l.y] = make_int2(cidx.y, __float_as_int(v.y));
        pairs[__ldg(cur + r.z) + l.z] = make_int2(cidx.z, __float_as_int(v.z));
        pairs[__ldg(cur + r.w) + l.w] = make_int2(cidx.w, __float_as_int(v.w));
    }
}

// ---------------- SpMM core (fp16 x, fp32 accumulate) ----------------
__device__ __forceinline__ float4 spmm_row_h(const int* __restrict__ rowptr,
                                             const int2* __restrict__ pairs,
                                             const uint2* __restrict__ xin, int row, int d4) {
    int beg = __ldg(rowptr + row);
    int end = __ldg(rowptr + row + 1);
    float4 s = make_float4(0.f, 0.f, 0.f, 0.f);
    int j = beg;
    for (; j + 3 < end; j += 4) {
        int2 p0 = __ldg(pairs + j);
        int2 p1 = __ldg(pairs + j + 1);
        int2 p2 = __ldg(pairs + j + 2);
        int2 p3 = __ldg(pairs + j + 3);
        float4 v0 = h4tof4(__ldg(xin + ((size_t)p0.x << 4) + d4));
        float4 v1 = h4tof4(__ldg(xin + ((size_t)p1.x << 4) + d4));
        float4 v2 = h4tof4(__ldg(xin + ((size_t)p2.x << 4) + d4));
        float4 v3 = h4tof4(__ldg(xin + ((size_t)p3.x << 4) + d4));
        float w0 = __int_as_float(p0.y), w1 = __int_as_float(p1.y);
        float w2 = __int_as_float(p2.y), w3 = __int_as_float(p3.y);
        s.x = fmaf(w0, v0.x, s.x); s.y = fmaf(w0, v0.y, s.y); s.z = fmaf(w0, v0.z, s.z); s.w = fmaf(w0, v0.w, s.w);
        s.x = fmaf(w1, v1.x, s.x); s.y = fmaf(w1, v1.y, s.y); s.z = fmaf(w1, v1.z, s.z); s.w = fmaf(w1, v1.w, s.w);
        s.x = fmaf(w2, v2.x, s.x); s.y = fmaf(w2, v2.y, s.y); s.z = fmaf(w2, v2.z, s.z); s.w = fmaf(w2, v2.w, s.w);
        s.x = fmaf(w3, v3.x, s.x); s.y = fmaf(w3, v3.y, s.y); s.z = fmaf(w3, v3.z, s.z); s.w = fmaf(w3, v3.w, s.w);
    }
    for (; j < end; j++) {
        int2 p = __ldg(pairs + j);
        float w = __int_as_float(p.y);
        float4 v = h4tof4(__ldg(xin + ((size_t)p.x << 4) + d4));
        s.x = fmaf(w, v.x, s.x); s.y = fmaf(w, v.y, s.y); s.z = fmaf(w, v.z, s.z); s.w = fmaf(w, v.w, s.w);
    }
    return s;
}

#define GB_S 6250
#define GB_E 1875
#define GB_K 63
#define GB_TOT (GB_S + GB_E + GB_K)
#define GL_S 1024
#define GL_E 1024
#define GL_K 63
#define GL_TOT (GL_S + GL_E + GL_K)

struct Spmm3Args {
    const int* rp[3];
    const int2* pr[3];
    const uint2* e16[3];
    uint2* x1[3];
    uint2* x2[3];
    int nrows[3];
    const int *sid, *eid;
    uint2 *xg_s, *xg_e, *x3_k;
};

__device__ __forceinline__ void spmm_layer_v(const Spmm3Args& a, int v,
                                             const uint2* const* xin_arr, uint2* const* xout_arr) {
    int seg, lb;
    if (v < GB_S)             { seg = 0; lb = v; }
    else if (v < GB_S + GB_E) { seg = 1; lb = v - GB_S; }
    else                      { seg = 2; lb = v - GB_S - GB_E; }
    int row = lb * 16 + (threadIdx.x >> 4);
    int d4 = threadIdx.x & 15;
    if (row >= a.nrows[seg]) return;
    const uint2* xin = xin_arr[seg];
    float4 s = spmm_row_h(a.rp[seg], a.pr[seg], xin, row, d4);
    size_t o = ((size_t)row << 4) + d4;
    float4 m = h4tof4(xin[o]);
    s.x += MOM * m.x; s.y += MOM * m.y; s.z += MOM * m.z; s.w += MOM * m.w;
    xout_arr[seg][o] = f4toh4(s);
}

__global__ void __launch_bounds__(256, 5) spmm3_kernel(Spmm3Args a) {
    if (blockIdx.x == 0 && threadIdx.x == 0) g_bar_csr[2] = 0;
    for (int v = blockIdx.x; v < GB_TOT; v += PNB)
        spmm_layer_v(a, v, a.e16, a.x1);
    gbar(&g_bar_spmm[0], PNB);
    for (int v = blockIdx.x; v < GB_TOT; v += PNB)
        spmm_layer_v(a, v, (const uint2* const*)a.x1, a.x2);
    gbar(&g_bar_spmm[1], PNB);
    if (blockIdx.x == 0 && threadIdx.x == 0) g_bar_spmm[0] = 0;
    int d4 = threadIdx.x & 15;
    int lr = threadIdx.x >> 4;
    for (int v = blockIdx.x; v < GL_TOT; v += PNB) {
        if (v < GL_S) {
            int r = v * 16 + lr;
            int row = __ldg(a.sid + r);
            float4 s = spmm_row_h(a.rp[0], a.pr[0], a.x2[0], row, d4);
            float4 m = h4tof4(a.x2[0][((size_t)row << 4) + d4]);
            s.x += MOM * m.x; s.y += MOM * m.y; s.z += MOM * m.z; s.w += MOM * m.w;
            a.xg_s[((size_t)r << 4) + d4] = f4toh4(s);
        } else if (v < GL_S + GL_E) {
            int r = (v - GL_S) * 16 + lr;
            int row = __ldg(a.eid + r);
            float4 s = spmm_row_h(a.rp[1], a.pr[1], a.x2[1], row, d4);
            float4 m = h4tof4(a.x2[1][((size_t)row << 4) + d4]);
            s.x += MOM * m.x; s.y += MOM * m.y; s.z += MOM * m.z; s.w += MOM * m.w;
            a.xg_e[((size_t)r << 4) + d4] = f4toh4(s);
        } else {
            int row = (v - GL_S - GL_E) * 16 + lr;
            if (row >= K_N) continue;
            float4 s = spmm_row_h(a.rp[2], a.pr[2], a.x2[2], row, d4);
            float4 m = h4tof4(a.x2[2][((size_t)row << 4) + d4]);
            s.x += MOM * m.x; s.y += MOM * m.y; s.z += MOM * m.z; s.w += MOM * m.w;
            a.x3_k[((size_t)row << 4) + d4] = f4toh4(s);
        }
    }
}

// ---------------- tf32 helper / MMA macros ----------------
__device__ __forceinline__ uint32_t f2tf32(float f) {
    uint32_t u;
    asm("cvt.rna.tf32.f32 %0, %1;" : "=r"(u) : "f"(f));
    return u;
}

#define MMA_TF32(d, a, b)                                                     \
    asm volatile(                                                             \
        "mma.sync.aligned.m16n8k8.row.col.f32.tf32.tf32.f32 "                 \
        "{%0,%1,%2,%3}, {%4,%5,%6,%7}, {%8,%9}, {%0,%1,%2,%3};\n"             \
        : "+f"(d[0]), "+f"(d[1]), "+f"(d[2]), "+f"(d[3])                      \
        : "r"(a[0]), "r"(a[1]), "r"(a[2]), "r"(a[3]), "r"(b[0]), "r"(b[1]))

#define MMA_F16(d, a, b)                                                      \
    asm volatile(                                                             \
        "mma.sync.aligned.m16n8k16.row.col.f32.f16.f16.f32 "                  \
        "{%0,%1,%2,%3}, {%4,%5,%6,%7}, {%8,%9}, {%0,%1,%2,%3};\n"             \
        : "+f"(d[0]), "+f"(d[1]), "+f"(d[2]), "+f"(d[3])                      \
        : "r"(a[0]), "r"(a[1]), "r"(a[2]), "r"(a[3]), "r"(b[0]), "r"(b[1]))

// ---------------- unified dense stage ----------------
#define XS_STRIDE 68
#define WT_STRIDE 68
#define DM_XS_W   (64 * XS_STRIDE)
#define DM_WT_W   (128 * WT_STRIDE)
#define DM_SMEM_BYTES ((DM_XS_W + DM_WT_W + 128 + 64) * 4)
#define G_MMA 512
#define G_KNO 125
#define G_IMP 1024
#define G_DENSE (G_MMA + G_KNO + G_IMP)

struct DenseArgs {
    const float *x0s;  const uint2 *x1s, *x2s, *x3s;
    const float *x0e;  const uint2 *x1e, *x2e, *x3e;
    const float *xk0;  const uint2 *xk1, *xk2, *xk3;
    const int *sid, *eid;
    const float *Ws, *bs, *We, *be, *Wk, *bk, *Wd, *bd;
    const float *imp;
    uint32_t *A1h, *A2h;
    __half *Bt16;
    float *Okt, *Odisc, *Oimp;
};

__global__ void __launch_bounds__(256) dense_all_kernel(DenseArgs a) {
    extern __shared__ uint32_t dsm[];
    const unsigned FULL = 0xFFFFFFFFu;
    int b = blockIdx.x, tid = threadIdx.x;
    if (b == 0 && tid == 0) g_bar_spmm[1] = 0;

    if (b < G_MMA) {
        uint32_t* Xs = dsm;
        uint32_t* Wt = dsm + DM_XS_W;
        float* bsm = (float*)(dsm + DM_XS_W + DM_WT_W);
        float* wd  = bsm + 128;
        bool is_e = b >= 256;
        int r0 = (is_e ? b - 256 : b) * 64;
        const float* x0 = is_e ? a.x0e : a.x0s;
        const uint2* x1 = is_e ? a.x1e : a.x1s;
        const uint2* x2 = is_e ? a.x2e : a.x2s;
        const uint2* x3 = is_e ? a.x3e : a.x3s;
        const int* ids  = is_e ? a.eid : a.sid;
        const float* W  = is_e ? a.We : a.Ws;
        const float* bias = is_e ? a.be : a.bs;
        uint32_t* out = is_e ? a.A2h : a.A1h;

        for (int i = tid; i < 8192; i += 256) {
            int k = i >> 7, n = i & 127;
            Wt[n * WT_STRIDE + k] = f2tf32(__ldg(W + i));
        }
        if (tid < 128) bsm[tid] = __ldg(bias + tid);
        if (is_e && tid < 64) wd[tid] = __ldg(a.Wd + tid);

        for (int i = tid; i < 1024; i += 256) {
            int rr = i >> 4, c4 = i & 15;
            int r = r0 + rr;
            int rid = __ldg(ids + r);
            size_t o  = ((size_t)rid << 4) + c4;
            size_t o3 = ((size_t)r << 4) + c4;
            float4 a0 = __ldg((const float4*)x0 + o);
            float4 a1 = h4tof4(__ldg(x1 + o));
            float4 a2 = h4tof4(__ldg(x2 + o));
            float4 a3 = h4tof4(__ldg(x3 + o3));
            uint4 w;
            w.x = f2tf32(0.25f * (a0.x + a1.x + a2.x + a3.x));
            w.y = f2tf32(0.25f * (a0.y + a1.y + a2.y + a3.y));
            w.z = f2tf32(0.25f * (a0.z + a1.z + a2.z + a3.z));
            w.w = f2tf32(0.25f * (a0.w + a1.w + a2.w + a3.w));
            *(uint4*)&Xs[rr * XS_STRIDE + c4 * 4] = w;
        }
        __syncthreads();

        int warp = tid >> 5, lane = tid & 31, g = lane >> 2, tg = lane & 3;
        int wm = warp >> 1;
        int wn = warp & 1;
        float acc[8][4] = {};
        #pragma unroll
        for (int ks = 0; ks < 8; ks++) {
            int k0 = ks * 8;
            uint32_t A[4];
            const uint32_t* ap = &Xs[(wm * 16 + g) * XS_STRIDE + k0 + tg];
            A[0] = ap[0]; A[1] = ap[8 * XS_STRIDE]; A[2] = ap[4]; A[3] = ap[8 * XS_STRIDE + 4];
            #pragma unroll
            for (int nt = 0; nt < 8; nt++) {
                const uint32_t* bp = &Wt[(wn * 64 + nt * 8 + g) * WT_STRIDE + k0 + tg];
                uint32_t B[2] = {bp[0], bp[4]};
                MMA_TF32(acc[nt], A, B);
            }
        }

        #pragma unroll
        for (int nt = 0; nt < 8; nt++) {
            int col = wn * 64 + nt * 8 + tg * 2;
            float b0 = bsm[col], b1 = bsm[col + 1];
            size_t rA = (size_t)(r0 + wm * 16 + g);
            size_t rB = rA + 8;
            float v0 = acc[nt][0] + b0; v0 = (v0 > 0.f) ? v0 : LEAK_F * v0;
            float v1 = acc[nt][1] + b1; v1 = (v1 > 0.f) ? v1 : LEAK_F * v1;
            float v2 = acc[nt][2] + b0; v2 = (v2 > 0.f) ? v2 : LEAK_F * v2;
            float v3 = acc[nt][3] + b1; v3 = (v3 > 0.f) ? v3 : LEAK_F * v3;
            out[rA * 64 + (col >> 1)] = f2toh2(v0, v1);
            out[rB * 64 + (col >> 1)] = f2toh2(v2, v3);
        }

        if (is_e) {
            int row = tid >> 2, part = tid & 3;
            float s = 0.f;
            #pragma unroll
            for (int i = 0; i < 16; i++)
                s += __uint_as_float(Xs[row * XS_STRIDE + part * 16 + i]) * wd[part * 16 + i];
            s += __shfl_xor_sync(FULL, s, 1);
            s += __shfl_xor_sync(FULL, s, 2);
            if (part == 0) a.Odisc[r0 + row] = 1.f / (1.f + __expf(-(s + __ldg(a.bd))));
        }
    } else if (b < G_MMA + G_KNO) {
        float* Ws = (float*)dsm;
        float* Xs = Ws + 8192;
        int r0 = (b - G_MMA) * 8;
        const float4* W4 = (const float4*)a.Wk;
        float4* Ws4 = (float4*)Ws;
        #pragma unroll
        for (int i = 0; i < 8; i++) Ws4[tid + i * 256] = W4[tid + i * 256];
        if (tid < 128) {
            int rr = tid >> 4;
            int c4 = tid & 15;
            int r = r0 + rr;
            float4 v = make_float4(0.f, 0.f, 0.f, 0.f);
            if (r < K_N) {
                size_t o = ((size_t)r << 4) + c4;
                float4 a0 = __ldg((const float4*)a.xk0 + o);
                float4 a1 = h4tof4(__ldg(a.xk1 + o));
                float4 a2 = h4tof4(__ldg(a.xk2 + o));
                float4 a3 = h4tof4(__ldg(a.xk3 + o));
                v.x = 0.25f * (a0.x + a1.x + a2.x + a3.x);
                v.y = 0.25f * (a0.y + a1.y + a2.y + a3.y);
                v.z = 0.25f * (a0.z + a1.z + a2.z + a3.z);
                v.w = 0.25f * (a0.w + a1.w + a2.w + a3.w);
            }
            ((float4*)&Xs[rr * 64])[c4] = v;
        }
        __syncthreads();
        int col = tid & 127;
        int rbase = tid >> 7;
        float bv = __ldg(a.bk + col);
        #pragma unroll
        for (int rr = 0; rr < 4; rr++) {
            int lrow = rr * 2 + rbase;
            int r = r0 + lrow;
            if (r >= K_N) continue;
            float acc = bv;
            #pragma unroll
            for (int i = 0; i < 64; i++) acc = fmaf(Xs[lrow * 64 + i], Ws[i * 128 + col], acc);
            float rv = (acc > 0.f) ? acc : LEAK_F * acc;
            a.Okt[(size_t)r * 128 + col] = rv;
            a.Bt16[(size_t)r * 128 + col] = __float2half_rn(rv);
        }
    } else {
        int t = (b - G_MMA - G_KNO) * 256 + tid;
        int bi = t >> 4, q = t & 15;
        ((float4*)a.Oimp)[((size_t)bi << 4) + q] =
            __ldg((const float4*)a.imp + ((size_t)__ldg(a.eid + bi) << 4) + q);
    }
}

// ---------------- fp16 big GEMM: 128x64 tile, 4 blocks/SM ----------------
#define SMH 68
#define HGA_W (128 * SMH)
#define HGB_W (64 * SMH)
#define HGEMM_SMEM_BYTES ((HGA_W + HGB_W) * 4)   // 52224

__device__ __forceinline__ void cp16(uint32_t dst, const void* src) {
    asm volatile("cp.async.cg.shared.global [%0], [%1], 16;" :: "r"(dst), "l"(src));
}

__global__ void __launch_bounds__(256, 4) big_gemm_f16(
    const uint32_t* __restrict__ A1h, const uint32_t* __restrict__ A2h,
    const uint32_t* __restrict__ Bh, float* __restrict__ O1, float* __restrict__ O2) {
    extern __shared__ uint32_t sm[];
    uint32_t sbase = (uint32_t)__cvta_generic_to_shared(sm);
    const uint32_t* As = sm;
    const uint32_t* Bs = sm + HGA_W;

    int tid = threadIdx.x;
    int warp = tid >> 5;
    int lane = tid & 31;
    int g = lane >> 2;
    int tg = lane & 3;
    int wm = warp >> 1;     // 4 m-groups of 32 rows
    int wn = warp & 1;      // 2 n-halves of 32 cols
    int m0 = blockIdx.x * 128;
    int n0 = blockIdx.y * 64;
    bool second = blockIdx.z != 0;
    const uint32_t* Ah = second ? A2h : A1h;
    float* O = second ? O2 : O1;

    // load A tile (128 rows x 64 words) + B tile (64 rows x 64 words)
    #pragma unroll
    for (int i = 0; i < 8; i++) {
        int idx = tid + i * 256;          // 0..2047
        int row = idx >> 4, q = idx & 15;
        cp16(sbase + (uint32_t)(row * SMH + q * 4) * 4,
             Ah + (size_t)(m0 + row) * 64 + q * 4);
    }
    #pragma unroll
    for (int i = 0; i < 4; i++) {
        int idx = tid + i * 256;          // 0..1023
        int row = idx >> 4, q = idx & 15;
        cp16(sbase + HGA_W * 4 + (uint32_t)(row * SMH + q * 4) * 4,
             Bh + (size_t)(n0 + row) * 64 + q * 4);
    }
    asm volatile("cp.async.commit_group;");
    asm volatile("cp.async.wait_group 0;");
    __syncthreads();

    float acc[2][4][4] = {};

    #pragma unroll
    for (int ks = 0; ks < 8; ks++) {
        int w0 = ks * 8;
        uint32_t b[4][2];
        #pragma unroll
        for (int nt = 0; nt < 4; nt++) {
            const uint32_t* bp = &Bs[(wn * 32 + nt * 8 + g) * SMH + w0 + tg];
            b[nt][0] = bp[0];
            b[nt][1] = bp[4];
        }
        #pragma unroll
        for (int mt = 0; mt < 2; mt++) {
            uint32_t a[4];
            const uint32_t* ap = &As[(wm * 32 + mt * 16 + g) * SMH + w0 + tg];
            a[0] = ap[0]; a[1] = ap[8 * SMH]; a[2] = ap[4]; a[3] = ap[8 * SMH + 4];
            #pragma unroll
            for (int nt = 0; nt < 4; nt++) MMA_F16(acc[mt][nt], a, b[nt]);
        }
    }

    #pragma unroll
    for (int mt = 0; mt < 2; mt++) {
        #pragma unroll
        for (int nt = 0; nt < 4; nt++) {
            int col = n0 + wn * 32 + nt * 8 + tg * 2;
            if (col >= K_N) continue;
            size_t r0 = (size_t)(m0 + wm * 32 + mt * 16 + g);
            size_t r1 = r0 + 8;
            *(float2*)(O + r0 * K_N + col) = make_float2(acc[mt][nt][0], acc[mt][nt][1]);
            *(float2*)(O + r1 * K_N + col) = make_float2(acc[mt][nt][2], acc[mt][nt][3]);
        }
    }
}

// ---------------- host orchestration ----------------
extern "C" void kernel_launch(void* const* d_in, const int* in_sizes, int n_in,
                              void* d_out, int out_size) {
    (void)in_sizes; (void)n_in; (void)out_size;
    const int*   student_id  = (const int*)d_in[0];
    const int*   exercise_id = (const int*)d_in[1];
    const float* stu_emb     = (const float*)d_in[3];
    const float* exer_emb    = (const float*)d_in[4];
    const float* know_emb    = (const float*)d_in[5];
    const float* impact_emb  = (const float*)d_in[6];
    const int*   s_rows = (const int*)d_in[7];
    const int*   s_cols = (const int*)d_in[8];
    const float* s_vals = (const float*)d_in[9];
    const int*   e_rows = (const int*)d_in[10];
    const int*   e_cols = (const int*)d_in[11];
    const float* e_vals = (const float*)d_in[12];
    const int*   k_rows = (const int*)d_in[13];
    const int*   k_cols = (const int*)d_in[14];
    const float* k_vals = (const float*)d_in[15];
    const float* W_stu  = (const float*)d_in[16];
    const float* b_stu  = (const float*)d_in[17];
    const float* W_exer = (const float*)d_in[18];
    const float* b_exer = (const float*)d_in[19];
    const float* W_know = (const float*)d_in[20];
    const float* b_know = (const float*)d_in[21];
    const float* W_disc = (const float*)d_in[22];
    const float* b_disc = (const float*)d_in[23];

    unsigned char* A = nullptr;
    cudaGetSymbolAddress((void**)&A, g_arena);

    int*  rp_s  = (int*)(A + O_RP_S);
    int*  rp_e  = (int*)(A + O_RP_E);
    int*  rp_k  = (int*)(A + O_RP_K);
    unsigned long long* lk = (unsigned long long*)(A + O_LK);
    int*  cur_s = (int*)(A + O_CUR_S);
    int*  cur_e = (int*)(A + O_CUR_E);
    int*  cur_k = (int*)(A + O_CUR_K);
    int*  loc   = (int*)(A + O_LOC);
    int2* pairs_s = (int2*)(A + O_PAIRS_S);
    int2* pairs_e = (int2*)(A + O_PAIRS_E);
    int2* pairs_k = (int2*)(A + O_PAIRS_K);
    uint2* e16_s = (uint2*)(A + O_E16_S);
    uint2* e16_e = (uint2*)(A + O_E16_E);
    uint2* e16_k = (uint2*)(A + O_E16_K);
    uint2* x1_s = (uint2*)(A + O_X1_S);
    uint2* x2_s = (uint2*)(A + O_X2_S);
    uint2* x1_e = (uint2*)(A + O_X1_E);
    uint2* x2_e = (uint2*)(A + O_X2_E);
    uint2* x1_k = (uint2*)(A + O_X1_K);
    uint2* x2_k = (uint2*)(A + O_X2_K);
    uint2* x3_k = (uint2*)(A + O_X3_K);
    uint2* xg_s = (uint2*)(A + O_XG_S);
    uint2* xg_e = (uint2*)(A + O_XG_E);
    uint32_t* A1h = (uint32_t*)(A + O_A1);
    uint32_t* A2h = (uint32_t*)(A + O_A2);
    __half* Bt16 = (__half*)(A + O_BT16);

    // 1) persistent CSR build
    {
        CsrArgs ca;
        ca.s_rows = (const int4*)s_rows; ca.s_cols = (const int4*)s_cols; ca.s_vals = (const float4*)s_vals;
        ca.e_rows = (const int4*)e_rows; ca.e_cols = (const int4*)e_cols; ca.e_vals = (const float4*)e_vals;
        ca.k_rows = (const int4*)k_rows; ca.k_cols = (const int4*)k_cols; ca.k_vals = (const float4*)k_vals;
        ca.rp_s = rp_s; ca.rp_e = rp_e; ca.rp_k = rp_k;
        ca.cur_s = cur_s; ca.cur_e = cur_e; ca.cur_k = cur_k;
        ca.loc = (int4*)loc;
        ca.pairs_s = pairs_s; ca.pairs_e = pairs_e; ca.pairs_k = pairs_k;
        ca.lk = lk;
        ca.bt_pad = (uint32_t*)(Bt16 + (size_t)K_N * 128);
        ca.es = (const float4*)stu_emb; ca.ee = (const float4*)exer_emb; ca.ek = (const float4*)know_emb;
        ca.s16 = (uint4*)e16_s; ca.e16 = (uint4*)e16_e; ca.k16 = (uint4*)e16_k;
        ca.zero_base = (int*)A;
        csr_build_kernel<<<PNB, 256>>>(ca);
    }

    // 2) persistent SpMM
    {
        Spmm3Args sa;
        sa.rp[0] = rp_s;  sa.rp[1] = rp_e;  sa.rp[2] = rp_k;
        sa.pr[0] = pairs_s; sa.pr[1] = pairs_e; sa.pr[2] = pairs_k;
        sa.e16[0] = e16_s; sa.e16[1] = e16_e; sa.e16[2] = e16_k;
        sa.x1[0] = x1_s; sa.x1[1] = x1_e; sa.x1[2] = x1_k;
        sa.x2[0] = x2_s; sa.x2[1] = x2_e; sa.x2[2] = x2_k;
        sa.nrows[0] = S_N; sa.nrows[1] = E_N; sa.nrows[2] = K_N;
        sa.sid = student_id; sa.eid = exercise_id;
        sa.xg_s = xg_s; sa.xg_e = xg_e; sa.x3_k = x3_k;
        spmm3_kernel<<<PNB, 256>>>(sa);
    }

    // 3) output layout
    float* out   = (float*)d_out;
    float* O1    = out;
    float* O2    = O1 + (size_t)B_N * K_N;
    float* Odisc = O2 + (size_t)B_N * K_N;
    float* Okt   = Odisc + B_N;
    float* Oimp  = Okt + (size_t)K_N * FF;

    // 4) unified dense stage
    static bool attr_set = false;
    if (!attr_set) {
        cudaFuncSetAttribute(dense_all_kernel,
                             cudaFuncAttributeMaxDynamicSharedMemorySize, DM_SMEM_BYTES);
        cudaFuncSetAttribute(big_gemm_f16,
                             cudaFuncAttributeMaxDynamicSharedMemorySize, HGEMM_SMEM_BYTES);
        attr_set = true;
    }
    {
        DenseArgs da;
        da.x0s = stu_emb;  da.x1s = x1_s; da.x2s = x2_s; da.x3s = xg_s;
        da.x0e = exer_emb; da.x1e = x1_e; da.x2e = x2_e; da.x3e = xg_e;
        da.xk0 = know_emb; da.xk1 = x1_k; da.xk2 = x2_k; da.xk3 = x3_k;
        da.sid = student_id; da.eid = exercise_id;
        da.Ws = W_stu; da.bs = b_stu; da.We = W_exer; da.be = b_exer;
        da.Wk = W_know; da.bk = b_know; da.Wd = W_disc; da.bd = b_disc;
        da.imp = impact_emb;
        da.A1h = A1h; da.A2h = A2h; da.Bt16 = Bt16;
        da.Okt = Okt; da.Odisc = Odisc; da.Oimp = Oimp;
        dense_all_kernel<<<G_DENSE, 256, DM_SMEM_BYTES>>>(da);
    }

    // 5) fp16 big GEMM pair (128x64 tiles, 4 blocks/SM)
    dim3 grid(B_N / 128, 1024 / 64, 2);
    big_gemm_f16<<<grid, 256, HGEMM_SMEM_BYTES>>>(
        A1h, A2h, (const uint32_t*)Bt16, O1, O2);
}